// round 1
// baseline (speedup 1.0000x reference)
#include <cuda_runtime.h>
#include <cstdint>

typedef unsigned long long u64;

// ---------------------------------------------------------------------------
// Problem dimensions (fixed)
// ---------------------------------------------------------------------------
// x: (16, 2, 128, 128, 64)
// conv1: 2->8,  5x5 s4 p1 -> (16,8,32,32,64)
// conv2: 8->32             -> (16,32,8,8,64)
// conv3: 32->64            -> (16,64,2,2,64)
// dense1: 256->2056
// dense2: 2056->11         -> out (16,11,64)

#define B_ 16
#define T_ 64

// ---------------------------------------------------------------------------
// Device scratch (no allocations allowed): one float pool + one u64 pool
// ---------------------------------------------------------------------------
// float pool offsets
#define W1_OFF 0              // 8*50    = 400
#define W2_OFF 400            // 32*200  = 6400
#define W3_OFF 6800           // 64*800  = 51200
#define W4_OFF 58000          // 2056*256= 526336
#define W5_OFF 584336         // 11*2056 = 22616
#define Z5_OFF 606952         // 16*11*64= 11264
#define FBUF_TOTAL 618216

// u64 pool offsets
#define XP_OFF 0              // 16*2*128*128 = 524288
#define S1_OFF 524288         // 16*8*32*32   = 131072
#define S2_OFF 655360         // 16*32*8*8    = 32768
#define S3_OFF 688128         // 16*256       = 4096
#define S4_OFF 692224         // 16*2056      = 32896
#define UBUF_TOTAL 725120

__device__ float g_fbuf[FBUF_TOTAL];
__device__ u64   g_ubuf[UBUF_TOTAL];

// ---------------------------------------------------------------------------
// weight_norm: w = g * v / ||v||  (norm over all non-output dims)
// one block per output row
// ---------------------------------------------------------------------------
__global__ void wnorm_kernel(const float* __restrict__ v,
                             const float* __restrict__ g,
                             float* __restrict__ w, int cols)
{
    int r = blockIdx.x;
    int tid = threadIdx.x;
    __shared__ float red[256];
    float s = 0.0f;
    for (int i = tid; i < cols; i += 256) {
        float a = v[(size_t)r * cols + i];
        s += a * a;
    }
    red[tid] = s;
    __syncthreads();
    for (int off = 128; off > 0; off >>= 1) {
        if (tid < off) red[tid] += red[tid + off];
        __syncthreads();
    }
    float n = sqrtf(red[0]);
    float gr = g[r];
    for (int i = tid; i < cols; i += 256) {
        w[(size_t)r * cols + i] = gr * v[(size_t)r * cols + i] / n;
    }
}

// ---------------------------------------------------------------------------
// pack input spikes: (B,2,128,128,T) float -> u64 bitmask per pixel (bit t)
// one thread per pixel, 16x float4 loads (256B contiguous per thread)
// ---------------------------------------------------------------------------
__global__ void pack_kernel(const float* __restrict__ x, u64* __restrict__ xp)
{
    int p = blockIdx.x * 256 + threadIdx.x;   // 524288 pixels
    const float4* xv = (const float4*)(x + (size_t)p * 64);
    u64 m = 0;
    #pragma unroll
    for (int q = 0; q < 16; ++q) {
        float4 f = xv[q];
        int base = q * 4;
        if (f.x > 0.5f) m |= (1ULL << (base + 0));
        if (f.y > 0.5f) m |= (1ULL << (base + 1));
        if (f.z > 0.5f) m |= (1ULL << (base + 2));
        if (f.w > 0.5f) m |= (1ULL << (base + 3));
    }
    xp[p] = m;
}

// ---------------------------------------------------------------------------
// Fused conv (5x5, stride 4, pad 1) + CUBA LIF, spike-bit in/out.
//
// Block = (b, spatial-tile st, o-group og). Threads 256 = 64 t-lanes x 4 pq.
// Phase 1: each thread computes z for PPT positions x OBLK outputs at its t,
//          input words are warp-uniform u64 broadcasts, weights hoisted to regs.
// Phase 2 (after barrier): 1 thread per neuron runs the 64-step CUBA recurrence
//          from smem and writes one packed u64 spike word.
// ---------------------------------------------------------------------------
template<int CI, int HI, int WI, int OTOT, int OBLK, int HO, int WO, int NPOS>
__global__ void __launch_bounds__(256)
conv_cuba_kernel(const u64* __restrict__ xp,
                 const float* __restrict__ wn,
                 u64* __restrict__ sp)
{
    extern __shared__ float smem[];
    float* wsm = smem;                        // OBLK * CI*25
    float* zsm = smem + OBLK * CI * 25;       // (OBLK*NPOS) * 65 (padded)

    const int b  = blockIdx.x;
    const int st = blockIdx.y;
    const int og = blockIdx.z;
    const int tid = threadIdx.x;

    // load this o-group's normalized weights to smem
    for (int idx = tid; idx < OBLK * CI * 25; idx += 256)
        wsm[idx] = wn[og * OBLK * CI * 25 + idx];
    __syncthreads();

    const int t  = tid & 63;
    const int pq = tid >> 6;
    constexpr int PPT = NPOS / 4;

    int ys[PPT], xs[PPT];
    #pragma unroll
    for (int i = 0; i < PPT; ++i) {
        int P = st * NPOS + (pq + 4 * i);
        ys[i] = P / WO;
        xs[i] = P % WO;
    }

    float acc[PPT][OBLK];
    #pragma unroll
    for (int i = 0; i < PPT; ++i)
        #pragma unroll
        for (int o = 0; o < OBLK; ++o) acc[i][o] = 0.0f;

    #pragma unroll 1
    for (int c = 0; c < CI; ++c) {
        const u64* xc = xp + ((size_t)(b * CI + c)) * HI * WI;
        #pragma unroll 1
        for (int ky = 0; ky < 5; ++ky) {
            #pragma unroll
            for (int kx = 0; kx < 5; ++kx) {
                float wreg[OBLK];
                #pragma unroll
                for (int o = 0; o < OBLK; ++o)
                    wreg[o] = wsm[o * (CI * 25) + (c * 5 + ky) * 5 + kx];
                #pragma unroll
                for (int i = 0; i < PPT; ++i) {
                    int iy = ys[i] * 4 - 1 + ky;   // pad=1; iy<HI guaranteed
                    int ix = xs[i] * 4 - 1 + kx;
                    u64 w64 = 0;
                    if (iy >= 0 && ix >= 0) w64 = xc[iy * WI + ix];
                    float sv = ((w64 >> t) & 1ULL) ? 1.0f : 0.0f;
                    #pragma unroll
                    for (int o = 0; o < OBLK; ++o)
                        acc[i][o] = fmaf(wreg[o], sv, acc[i][o]);
                }
            }
        }
    }

    // stage z into padded smem [neuron][t]
    #pragma unroll
    for (int i = 0; i < PPT; ++i) {
        int p = pq + 4 * i;
        #pragma unroll
        for (int o = 0; o < OBLK; ++o)
            zsm[(o * NPOS + p) * 65 + t] = acc[i][o];
    }
    __syncthreads();

    // CUBA recurrence, one thread per neuron
    if (tid < OBLK * NPOS) {
        int o = tid / NPOS;
        int p = tid % NPOS;
        float cc = 0.0f, vv = 0.0f;
        u64 m = 0;
        #pragma unroll 1
        for (int tt = 0; tt < 64; ++tt) {
            float z = zsm[tid * 65 + tt];
            cc = 0.7f * cc + z;       // (1 - 0.3)  exact in fp32
            vv = 0.75f * vv + cc;     // (1 - 0.25) exact in fp32
            if (vv >= 1.0f) { m |= (1ULL << tt); vv = 0.0f; }
        }
        int P = st * NPOS + p;
        int y = P / WO, x = P % WO;
        sp[(((size_t)b * OTOT + og * OBLK + o) * HO + y) * WO + x] = m;
    }
}

// ---------------------------------------------------------------------------
// dense1 (256 -> 2056) fused with CUBA. Register-tiled GEMM-ish:
// block = (b, og of 128 outputs), threads 256 = 16 t-lanes x 16 oq.
// thread tile: 8 outputs x 4 timesteps -> 32 FFMA per (12 smem ops).
// ---------------------------------------------------------------------------
__global__ void __launch_bounds__(256)
dense1_cuba_kernel(const u64* __restrict__ s3,
                   const float* __restrict__ w4,
                   u64* __restrict__ s4)
{
    extern __shared__ float sm[];
    u64*   words = (u64*)sm;                  // 256 u64 (512 floats)
    float* wsm   = sm + 512;                  // [i=256][129] padded, [i][o_local]
    float* zsm   = wsm + 256 * 129;           // [128][65] padded

    const int b  = blockIdx.x;
    const int og = blockIdx.y;
    const int tid = threadIdx.x;

    // stage spike words for this batch element
    words[tid] = s3[b * 256 + tid];

    // stage weights transposed [i][o_local]; guard rows beyond 2056
    for (int idx = tid; idx < 128 * 256; idx += 256) {
        int o_local = idx >> 8;       // 0..127
        int i       = idx & 255;      // 0..255  (consecutive tid -> consecutive i)
        int o_g = og * 128 + o_local;
        wsm[i * 129 + o_local] = (o_g < 2056) ? w4[(size_t)o_g * 256 + i] : 0.0f;
    }
    __syncthreads();

    const int tq = tid & 15;    // time lane: handles t = tq + 16k, k<4
    const int oq = tid >> 4;    // 0..15:     handles o_local = oq + 16j, j<8

    float acc[8][4];
    #pragma unroll
    for (int j = 0; j < 8; ++j)
        #pragma unroll
        for (int k = 0; k < 4; ++k) acc[j][k] = 0.0f;

    #pragma unroll 2
    for (int i = 0; i < 256; ++i) {
        u64 w64 = words[i];
        float sv[4];
        #pragma unroll
        for (int k = 0; k < 4; ++k)
            sv[k] = ((w64 >> (tq + 16 * k)) & 1ULL) ? 1.0f : 0.0f;
        float wr[8];
        #pragma unroll
        for (int j = 0; j < 8; ++j)
            wr[j] = wsm[i * 129 + oq + 16 * j];
        #pragma unroll
        for (int j = 0; j < 8; ++j)
            #pragma unroll
            for (int k = 0; k < 4; ++k)
                acc[j][k] = fmaf(wr[j], sv[k], acc[j][k]);
    }

    #pragma unroll
    for (int j = 0; j < 8; ++j)
        #pragma unroll
        for (int k = 0; k < 4; ++k)
            zsm[(oq + 16 * j) * 65 + (tq + 16 * k)] = acc[j][k];
    __syncthreads();

    if (tid < 128) {
        int o_g = og * 128 + tid;
        float cc = 0.0f, vv = 0.0f;
        u64 m = 0;
        #pragma unroll 1
        for (int tt = 0; tt < 64; ++tt) {
            float z = zsm[tid * 65 + tt];
            cc = 0.7f * cc + z;
            vv = 0.75f * vv + cc;
            if (vv >= 1.0f) { m |= (1ULL << tt); vv = 0.0f; }
        }
        if (o_g < 2056) s4[b * 2056 + o_g] = m;
    }
}

// ---------------------------------------------------------------------------
// dense2 (2056 -> 11) pre-activation: one warp per output element (b,o,t)
// ---------------------------------------------------------------------------
__global__ void dense2_z_kernel(const u64* __restrict__ s4,
                                const float* __restrict__ w5,
                                float* __restrict__ z5)
{
    int warp = (blockIdx.x * blockDim.x + threadIdx.x) >> 5;   // 11264 warps
    int lane = threadIdx.x & 31;
    int b = warp / (11 * 64);
    int r = warp % (11 * 64);
    int o = r / 64;
    int t = r % 64;
    float s = 0.0f;
    for (int k = lane; k < 2056; k += 32) {
        float wv = w5[(size_t)o * 2056 + k];
        if ((s4[b * 2056 + k] >> t) & 1ULL) s += wv;
    }
    #pragma unroll
    for (int off = 16; off > 0; off >>= 1)
        s += __shfl_down_sync(0xffffffffu, s, off);
    if (lane == 0) z5[warp] = s;
}

// ---------------------------------------------------------------------------
// final CUBA over z5, writes (B,11,T) float spikes to output
// ---------------------------------------------------------------------------
__global__ void cuba_out_kernel(const float* __restrict__ z5,
                                float* __restrict__ out)
{
    int n = threadIdx.x;
    if (n >= 16 * 11) return;
    float cc = 0.0f, vv = 0.0f;
    #pragma unroll 1
    for (int tt = 0; tt < 64; ++tt) {
        float z = z5[n * 64 + tt];
        cc = 0.7f * cc + z;
        vv = 0.75f * vv + cc;
        float s = (vv >= 1.0f) ? 1.0f : 0.0f;
        if (s != 0.0f) vv = 0.0f;
        out[n * 64 + tt] = s;
    }
}

// ---------------------------------------------------------------------------
// launch
// ---------------------------------------------------------------------------
extern "C" void kernel_launch(void* const* d_in, const int* in_sizes, int n_in,
                              void* d_out, int out_size)
{
    const float* x   = (const float*)d_in[0];
    const float* c1v = (const float*)d_in[1];
    const float* c1g = (const float*)d_in[2];
    const float* c2v = (const float*)d_in[3];
    const float* c2g = (const float*)d_in[4];
    const float* c3v = (const float*)d_in[5];
    const float* c3g = (const float*)d_in[6];
    const float* d1v = (const float*)d_in[7];
    const float* d1g = (const float*)d_in[8];
    const float* d2v = (const float*)d_in[9];
    const float* d2g = (const float*)d_in[10];
    float* out = (float*)d_out;

    void* fp = nullptr; void* up = nullptr;
    cudaGetSymbolAddress(&fp, g_fbuf);
    cudaGetSymbolAddress(&up, g_ubuf);
    float* F = (float*)fp;
    u64*   U = (u64*)up;

    float* W1 = F + W1_OFF;  float* W2 = F + W2_OFF;  float* W3 = F + W3_OFF;
    float* W4 = F + W4_OFF;  float* W5 = F + W5_OFF;  float* Z5 = F + Z5_OFF;
    u64* XP = U + XP_OFF;  u64* S1 = U + S1_OFF;  u64* S2 = U + S2_OFF;
    u64* S3 = U + S3_OFF;  u64* S4 = U + S4_OFF;

    // dynamic smem sizes
    const int SM1 = (8 * 50   + 8 * 32 * 65) * 4;              // 68160
    const int SM2 = (32 * 200 + 32 * 8 * 65) * 4;              // 92160
    const int SM3 = (8 * 800  + 8 * 4 * 65) * 4;               // 33920
    const int SMD = (512 + 256 * 129 + 128 * 65) * 4;          // 167424

    cudaFuncSetAttribute(conv_cuba_kernel<2, 128, 128, 8, 8, 32, 32, 32>,
                         cudaFuncAttributeMaxDynamicSharedMemorySize, SM1);
    cudaFuncSetAttribute(conv_cuba_kernel<8, 32, 32, 32, 32, 8, 8, 8>,
                         cudaFuncAttributeMaxDynamicSharedMemorySize, SM2);
    cudaFuncSetAttribute(conv_cuba_kernel<32, 8, 8, 64, 8, 2, 2, 4>,
                         cudaFuncAttributeMaxDynamicSharedMemorySize, SM3);
    cudaFuncSetAttribute(dense1_cuba_kernel,
                         cudaFuncAttributeMaxDynamicSharedMemorySize, SMD);

    // weight_norm for all 5 layers
    wnorm_kernel<<<8,    256>>>(c1v, c1g, W1, 50);
    wnorm_kernel<<<32,   256>>>(c2v, c2g, W2, 200);
    wnorm_kernel<<<64,   256>>>(c3v, c3g, W3, 800);
    wnorm_kernel<<<2056, 256>>>(d1v, d1g, W4, 256);
    wnorm_kernel<<<11,   256>>>(d2v, d2g, W5, 2056);

    // pack input spikes into bit-words
    pack_kernel<<<2048, 256>>>(x, XP);

    // conv+CUBA stack
    conv_cuba_kernel<2, 128, 128, 8, 8, 32, 32, 32>
        <<<dim3(16, 32, 1), 256, SM1>>>(XP, W1, S1);
    conv_cuba_kernel<8, 32, 32, 32, 32, 8, 8, 8>
        <<<dim3(16, 8, 1), 256, SM2>>>(S1, W2, S2);
    conv_cuba_kernel<32, 8, 8, 64, 8, 2, 2, 4>
        <<<dim3(16, 1, 8), 256, SM3>>>(S2, W3, S3);

    // dense1 + CUBA (2056 = 17 groups of 128, last partially masked)
    dense1_cuba_kernel<<<dim3(16, 17), 256, SMD>>>(S3, W4, S4);

    // dense2 pre-activation + final CUBA to output
    dense2_z_kernel<<<1408, 256>>>(S4, W5, Z5);
    cuba_out_kernel<<<1, 192>>>(Z5, out);
}

// round 2
// speedup vs baseline: 1.3394x; 1.3394x over previous
#include <cuda_runtime.h>
#include <cstdint>

typedef unsigned long long u64;

// ---------------------------------------------------------------------------
// Dimensions
// x: (16,2,128,128,64) -> conv1 (8,2,5,5) s4 p1 -> (16,8,32,32,T)
// -> conv2 (32,8,5,5) -> (16,32,8,8,T) -> conv3 (64,32,5,5) -> (16,64,2,2,T)
// -> dense1 256->2056 -> dense2 2056->11 -> out (16,11,64)
// ---------------------------------------------------------------------------

// float pool offsets
#define W1_OFF   0              // 8*50
#define W2_OFF   400            // 32*200
#define W3_OFF   6800           // 64*800
#define W4T_OFF  58000          // 256 * 2304 (transposed, padded rows)
#define W5_OFF   647824         // 11*2056
#define FBUF_TOTAL 670440

#define W4T_STRIDE 2304

// u64 pool offsets
#define XP_OFF 0                // 16*2*128*128
#define S1_OFF 524288           // 16*8*32*32
#define S2_OFF 655360           // 16*32*8*8
#define S3_OFF 688128           // 16*256
#define S4_OFF 692224           // 16*2056
#define UBUF_TOTAL 725120

__device__ float g_fbuf[FBUF_TOTAL];
__device__ u64   g_ubuf[UBUF_TOTAL];

// ---------------------------------------------------------------------------
// Fused weight_norm for all 5 layers. Layer 3 (dense1) is written TRANSPOSED
// with padded row stride so dense1 can stage weights with coalesced float4s.
// ---------------------------------------------------------------------------
__global__ void wnorm_all_kernel(const float* __restrict__ c1v, const float* __restrict__ c1g,
                                 const float* __restrict__ c2v, const float* __restrict__ c2g,
                                 const float* __restrict__ c3v, const float* __restrict__ c3g,
                                 const float* __restrict__ d1v, const float* __restrict__ d1g,
                                 const float* __restrict__ d2v, const float* __restrict__ d2g)
{
    int blk = blockIdx.x;
    int tid = threadIdx.x;
    const float* v; const float* g; float* w; int cols; int r; int trans = 0;
    if (blk < 8)          { v = c1v; g = c1g; w = g_fbuf + W1_OFF;  cols = 50;   r = blk; }
    else if (blk < 40)    { v = c2v; g = c2g; w = g_fbuf + W2_OFF;  cols = 200;  r = blk - 8; }
    else if (blk < 104)   { v = c3v; g = c3g; w = g_fbuf + W3_OFF;  cols = 800;  r = blk - 104 + 64; }
    else if (blk < 2160)  { v = d1v; g = d1g; w = g_fbuf + W4T_OFF; cols = 256;  r = blk - 104; trans = 1; }
    else                  { v = d2v; g = d2g; w = g_fbuf + W5_OFF;  cols = 2056; r = blk - 2160; }
    if (blk >= 40 && blk < 104) r = blk - 40;

    __shared__ float red[256];
    float s = 0.0f;
    for (int i = tid; i < cols; i += 256) {
        float a = v[(size_t)r * cols + i];
        s += a * a;
    }
    red[tid] = s;
    __syncthreads();
    for (int off = 128; off > 0; off >>= 1) {
        if (tid < off) red[tid] += red[tid + off];
        __syncthreads();
    }
    float n = sqrtf(red[0]);
    float gr = g[r];
    if (!trans) {
        for (int i = tid; i < cols; i += 256)
            w[(size_t)r * cols + i] = gr * v[(size_t)r * cols + i] / n;
    } else {
        for (int i = tid; i < cols; i += 256)
            w[(size_t)i * W4T_STRIDE + r] = gr * v[(size_t)r * cols + i] / n;
    }
}

// ---------------------------------------------------------------------------
// Pack input spikes, coalesced. Block = 256 pixels (64KB of input).
// Phase 1: coalesced float4 loads -> 4-bit nibbles into padded smem.
// Phase 2: each thread assembles one pixel's u64 from 16 nibbles.
// ---------------------------------------------------------------------------
__global__ void __launch_bounds__(256)
pack_kernel(const float* __restrict__ x, u64* __restrict__ xp)
{
    __shared__ unsigned int nsm[256 * 17];
    int tid = threadIdx.x;
    const float4* xg = (const float4*)x + (size_t)blockIdx.x * 4096;
    #pragma unroll
    for (int j = 0; j < 16; ++j) {
        float4 f = xg[j * 256 + tid];
        unsigned int v = (f.x > 0.5f ? 1u : 0u) | (f.y > 0.5f ? 2u : 0u)
                       | (f.z > 0.5f ? 4u : 0u) | (f.w > 0.5f ? 8u : 0u);
        int pl  = j * 16 + (tid >> 4);
        int nib = tid & 15;
        nsm[pl * 17 + nib] = v;
    }
    __syncthreads();
    u64 m = 0;
    #pragma unroll
    for (int k = 0; k < 16; ++k)
        m |= (u64)nsm[tid * 17 + k] << (4 * k);
    xp[(size_t)blockIdx.x * 256 + tid] = m;
}

// bit -> float helpers (t-quad extraction from a u64 word held as uint2)
__device__ __forceinline__ void extract4(uint2 w, int tq, float f[4])
{
    f[0] = (float)((w.x >> tq) & 1u);
    f[1] = (float)((w.x >> (tq + 16)) & 1u);
    f[2] = (float)((w.y >> tq) & 1u);
    f[3] = (float)((w.y >> (tq + 16)) & 1u);
}

// ---------------------------------------------------------------------------
// conv1: 2->8, in 128x128, out 32x32. Block = (b, output row y).
// 256 thr = 16 t-quad lanes x 16 x-positions; each thread: x and x+16,
// 8 outputs, 4 timesteps -> 64 FFMA per input word pair.
// ---------------------------------------------------------------------------
__global__ void __launch_bounds__(256, 2)
conv1_kernel(const u64* __restrict__ xp, const float* __restrict__ wn,
             u64* __restrict__ sp)
{
    extern __shared__ float sm1[];
    float* wsm = sm1;            // [50 taps][8 o]
    float* zsm = sm1 + 400;      // [256 neurons][65]

    const int b = blockIdx.x, y = blockIdx.y;
    const int tid = threadIdx.x;
    const int tq = tid & 15, pq = tid >> 4;

    for (int idx = tid; idx < 400; idx += 256)
        wsm[idx] = wn[(idx & 7) * 50 + (idx >> 3)];
    __syncthreads();

    float acc[2][4][8];
    #pragma unroll
    for (int i = 0; i < 2; ++i)
        #pragma unroll
        for (int k = 0; k < 4; ++k)
            #pragma unroll
            for (int o = 0; o < 8; ++o) acc[i][k][o] = 0.0f;

    #pragma unroll 1
    for (int c = 0; c < 2; ++c) {
        const u64* plane = xp + ((size_t)(b * 2 + c) << 14);
        #pragma unroll 1
        for (int ky = 0; ky < 5; ++ky) {
            int iy = y * 4 - 1 + ky;
            if (iy < 0) continue;
            const uint2* row = (const uint2*)(plane + ((size_t)iy << 7));
            #pragma unroll
            for (int kx = 0; kx < 5; ++kx) {
                const float* wp = wsm + (c * 25 + ky * 5 + kx) * 8;
                float4 wa = *(const float4*)wp;
                float4 wb = *(const float4*)(wp + 4);
                float wv[8] = {wa.x, wa.y, wa.z, wa.w, wb.x, wb.y, wb.z, wb.w};
                #pragma unroll
                for (int i = 0; i < 2; ++i) {
                    int ix = (pq + 16 * i) * 4 - 1 + kx;
                    uint2 w = make_uint2(0u, 0u);
                    if (ix >= 0) w = row[ix];
                    float f[4]; extract4(w, tq, f);
                    #pragma unroll
                    for (int k = 0; k < 4; ++k)
                        #pragma unroll
                        for (int o = 0; o < 8; ++o)
                            acc[i][k][o] = fmaf(wv[o], f[k], acc[i][k][o]);
                }
            }
        }
    }

    #pragma unroll
    for (int i = 0; i < 2; ++i)
        #pragma unroll
        for (int k = 0; k < 4; ++k)
            #pragma unroll
            for (int o = 0; o < 8; ++o)
                zsm[(o * 32 + pq + 16 * i) * 65 + tq + 16 * k] = acc[i][k][o];
    __syncthreads();

    {   // CUBA: one thread per neuron (o,p)
        int o = tid >> 5, p = tid & 31;
        float cc = 0.0f, vv = 0.0f;
        u64 m = 0;
        #pragma unroll 1
        for (int tt = 0; tt < 64; ++tt) {
            float z = zsm[tid * 65 + tt];
            cc = 0.7f * cc + z;
            vv = 0.75f * vv + cc;
            if (vv >= 1.0f) { m |= (1ULL << tt); vv = 0.0f; }
        }
        sp[(((size_t)b * 8 + o) * 32 + y) * 32 + p] = m;
    }
}

// ---------------------------------------------------------------------------
// conv2: 8->32, in 32x32, out 8x8. Grid (16 b, 16 st, 2 og); 512 blocks.
// 256 thr = 16 tq x 4 pos x 4 osub; thread: 1 pos, 4 o, 4 t -> 16 FFMA/word.
// ---------------------------------------------------------------------------
__global__ void __launch_bounds__(256)
conv2_kernel(const u64* __restrict__ s1, const float* __restrict__ wn,
             u64* __restrict__ sp)
{
    __shared__ float wsm[200 * 16];   // [tap][16 o]
    __shared__ float zsm[64 * 65];    // [16o x 4pos][65]

    const int b = blockIdx.x, st = blockIdx.y, og = blockIdx.z;
    const int tid = threadIdx.x;
    const int tq = tid & 15;
    const int pq = (tid >> 4) & 3;
    const int osub = tid >> 6;        // 0..3 -> o-base osub*4

    for (int idx = tid; idx < 3200; idx += 256)
        wsm[idx] = wn[(og * 16 + (idx & 15)) * 200 + (idx >> 4)];
    __syncthreads();

    const int P = st * 4 + pq;
    const int y = P >> 3, x = P & 7;

    float acc[4][4];                  // [k][j]
    #pragma unroll
    for (int k = 0; k < 4; ++k)
        #pragma unroll
        for (int j = 0; j < 4; ++j) acc[k][j] = 0.0f;

    #pragma unroll 1
    for (int c = 0; c < 8; ++c) {
        const u64* plane = s1 + ((size_t)(b * 8 + c) << 10);
        #pragma unroll 1
        for (int ky = 0; ky < 5; ++ky) {
            int iy = y * 4 - 1 + ky;
            if (iy < 0) continue;
            const uint2* row = (const uint2*)(plane + (size_t)iy * 32);
            #pragma unroll
            for (int kx = 0; kx < 5; ++kx) {
                float4 wv = *(const float4*)(wsm + (c * 25 + ky * 5 + kx) * 16 + osub * 4);
                int ix = x * 4 - 1 + kx;
                uint2 w = make_uint2(0u, 0u);
                if (ix >= 0) w = row[ix];
                float f[4]; extract4(w, tq, f);
                #pragma unroll
                for (int k = 0; k < 4; ++k) {
                    acc[k][0] = fmaf(wv.x, f[k], acc[k][0]);
                    acc[k][1] = fmaf(wv.y, f[k], acc[k][1]);
                    acc[k][2] = fmaf(wv.z, f[k], acc[k][2]);
                    acc[k][3] = fmaf(wv.w, f[k], acc[k][3]);
                }
            }
        }
    }

    #pragma unroll
    for (int k = 0; k < 4; ++k)
        #pragma unroll
        for (int j = 0; j < 4; ++j)
            zsm[((osub * 4 + j) * 4 + pq) * 65 + tq + 16 * k] = acc[k][j];
    __syncthreads();

    if (tid < 64) {
        int o_loc = tid >> 2, p = tid & 3;
        float cc = 0.0f, vv = 0.0f;
        u64 m = 0;
        #pragma unroll 1
        for (int tt = 0; tt < 64; ++tt) {
            float z = zsm[tid * 65 + tt];
            cc = 0.7f * cc + z;
            vv = 0.75f * vv + cc;
            if (vv >= 1.0f) { m |= (1ULL << tt); vv = 0.0f; }
        }
        int Pp = st * 4 + p;
        int yy = Pp >> 3, xx = Pp & 7;
        sp[(((size_t)b * 32 + og * 16 + o_loc) * 8 + yy) * 8 + xx] = m;
    }
}

// ---------------------------------------------------------------------------
// conv3: 32->64, in 8x8, out 2x2. Grid (16 b, 8 og); 128 blocks.
// 256 thr = 64 t-lanes x 4 positions, 8 outputs per block.
// ---------------------------------------------------------------------------
__global__ void __launch_bounds__(256)
conv3_kernel(const u64* __restrict__ s2, const float* __restrict__ wn,
             u64* __restrict__ sp)
{
    __shared__ float wsm[800 * 8];   // [tap][8 o]
    __shared__ float zsm[32 * 65];

    const int b = blockIdx.x, og = blockIdx.y;
    const int tid = threadIdx.x;
    const int t = tid & 63, pq = tid >> 6;
    const int y = pq >> 1, x = pq & 1;
    const unsigned int mbit = 1u << (t & 31);
    const bool hi = t >= 32;

    for (int idx = tid; idx < 6400; idx += 256)
        wsm[idx] = wn[(og * 8 + (idx & 7)) * 800 + (idx >> 3)];
    __syncthreads();

    float acc[8];
    #pragma unroll
    for (int o = 0; o < 8; ++o) acc[o] = 0.0f;

    #pragma unroll 1
    for (int c = 0; c < 32; ++c) {
        const u64* plane = s2 + ((size_t)(b * 32 + c) << 6);
        #pragma unroll 1
        for (int ky = 0; ky < 5; ++ky) {
            int iy = y * 4 - 1 + ky;
            if (iy < 0) continue;
            const uint2* row = (const uint2*)(plane + (size_t)iy * 8);
            #pragma unroll
            for (int kx = 0; kx < 5; ++kx) {
                const float* wp = wsm + (c * 25 + ky * 5 + kx) * 8;
                float4 wa = *(const float4*)wp;
                float4 wb = *(const float4*)(wp + 4);
                int ix = x * 4 - 1 + kx;
                uint2 w = make_uint2(0u, 0u);
                if (ix >= 0) w = row[ix];
                unsigned int ui = hi ? w.y : w.x;
                float f = (ui & mbit) ? 1.0f : 0.0f;
                acc[0] = fmaf(wa.x, f, acc[0]);
                acc[1] = fmaf(wa.y, f, acc[1]);
                acc[2] = fmaf(wa.z, f, acc[2]);
                acc[3] = fmaf(wa.w, f, acc[3]);
                acc[4] = fmaf(wb.x, f, acc[4]);
                acc[5] = fmaf(wb.y, f, acc[5]);
                acc[6] = fmaf(wb.z, f, acc[6]);
                acc[7] = fmaf(wb.w, f, acc[7]);
            }
        }
    }

    #pragma unroll
    for (int o = 0; o < 8; ++o)
        zsm[(o * 4 + pq) * 65 + t] = acc[o];
    __syncthreads();

    if (tid < 32) {
        int o = tid >> 2, p = tid & 3;
        float cc = 0.0f, vv = 0.0f;
        u64 m = 0;
        #pragma unroll 1
        for (int tt = 0; tt < 64; ++tt) {
            float z = zsm[tid * 65 + tt];
            cc = 0.7f * cc + z;
            vv = 0.75f * vv + cc;
            if (vv >= 1.0f) { m |= (1ULL << tt); vv = 0.0f; }
        }
        sp[(size_t)b * 256 + (og * 8 + o) * 4 + p] = m;
    }
}

// ---------------------------------------------------------------------------
// dense1: 256 -> 2056 fused with CUBA. Grid (16 b, 9 og of 256 outputs).
// 256 thr = 16 tq x 16 oq; thread: 16 o x 4 t. Weights from pre-transposed
// W4T, staged to smem in quarters of the i dimension (coalesced float4).
// ---------------------------------------------------------------------------
__global__ void __launch_bounds__(256)
dense1_cuba_kernel(const u64* __restrict__ s3,
                   const float* __restrict__ w4t,
                   u64* __restrict__ s4)
{
    extern __shared__ float smd[];
    u64*   words = (u64*)smd;                 // 256 u64
    float* wsm   = smd + 512;                 // [64 i][256 o]
    float* zsm   = wsm + 64 * 256;            // [256][65]

    const int b = blockIdx.x, og = blockIdx.y;
    const int tid = threadIdx.x;
    const int tq = tid & 15, oq = tid >> 4;

    words[tid] = s3[b * 256 + tid];

    float acc[4][16];
    #pragma unroll
    for (int k = 0; k < 4; ++k)
        #pragma unroll
        for (int j = 0; j < 16; ++j) acc[k][j] = 0.0f;

    #pragma unroll 1
    for (int q = 0; q < 4; ++q) {
        __syncthreads();
        // stage 64 i-rows x 256 o (coalesced float4 loads)
        #pragma unroll
        for (int r = 0; r < 16; ++r) {
            int f4 = r * 256 + tid;
            int ii = f4 >> 6;
            int o4 = (f4 & 63) * 4;
            *(float4*)(wsm + ii * 256 + o4) =
                *(const float4*)(w4t + (size_t)(q * 64 + ii) * W4T_STRIDE + og * 256 + o4);
        }
        __syncthreads();

        #pragma unroll 2
        for (int ii = 0; ii < 64; ++ii) {
            u64 wd = words[q * 64 + ii];
            uint2 w = make_uint2((unsigned int)wd, (unsigned int)(wd >> 32));
            float f[4]; extract4(w, tq, f);
            const float* wp = wsm + ii * 256 + oq * 16;
            float4 w0 = *(const float4*)(wp);
            float4 w1 = *(const float4*)(wp + 4);
            float4 w2 = *(const float4*)(wp + 8);
            float4 w3 = *(const float4*)(wp + 12);
            float wr[16] = {w0.x, w0.y, w0.z, w0.w, w1.x, w1.y, w1.z, w1.w,
                            w2.x, w2.y, w2.z, w2.w, w3.x, w3.y, w3.z, w3.w};
            #pragma unroll
            for (int k = 0; k < 4; ++k)
                #pragma unroll
                for (int j = 0; j < 16; ++j)
                    acc[k][j] = fmaf(wr[j], f[k], acc[k][j]);
        }
    }

    #pragma unroll
    for (int k = 0; k < 4; ++k)
        #pragma unroll
        for (int j = 0; j < 16; ++j)
            zsm[(oq * 16 + j) * 65 + tq + 16 * k] = acc[k][j];
    __syncthreads();

    {
        int o_g = og * 256 + tid;
        float cc = 0.0f, vv = 0.0f;
        u64 m = 0;
        #pragma unroll 1
        for (int tt = 0; tt < 64; ++tt) {
            float z = zsm[tid * 65 + tt];
            cc = 0.7f * cc + z;
            vv = 0.75f * vv + cc;
            if (vv >= 1.0f) { m |= (1ULL << tt); vv = 0.0f; }
        }
        if (o_g < 2056) s4[b * 2056 + o_g] = m;
    }
}

// ---------------------------------------------------------------------------
// dense2 (2056->11) + final CUBA + float output, fused. Grid (16 b, 11 o).
// 256 thr = 64 t-lanes x 4 i-chunks of 514.
// ---------------------------------------------------------------------------
__global__ void __launch_bounds__(256)
dense2_out_kernel(const u64* __restrict__ s4, const float* __restrict__ w5,
                  float* __restrict__ out)
{
    __shared__ float part[4][64];
    __shared__ float zrow[64];
    __shared__ u64 spk;

    const int b = blockIdx.x, o = blockIdx.y;
    const int tid = threadIdx.x;
    const int t = tid & 63, q = tid >> 6;

    float s = 0.0f;
    const u64*   wp = s4 + b * 2056;
    const float* vp = w5 + (size_t)o * 2056;
    for (int i = q * 514; i < q * 514 + 514; ++i) {
        float wt = vp[i];
        if ((wp[i] >> t) & 1ULL) s += wt;
    }
    part[q][t] = s;
    __syncthreads();
    if (tid < 64)
        zrow[tid] = part[0][tid] + part[1][tid] + part[2][tid] + part[3][tid];
    __syncthreads();
    if (tid == 0) {
        float cc = 0.0f, vv = 0.0f;
        u64 m = 0;
        #pragma unroll 1
        for (int tt = 0; tt < 64; ++tt) {
            cc = 0.7f * cc + zrow[tt];
            vv = 0.75f * vv + cc;
            if (vv >= 1.0f) { m |= (1ULL << tt); vv = 0.0f; }
        }
        spk = m;
    }
    __syncthreads();
    if (tid < 64)
        out[((size_t)b * 11 + o) * 64 + tid] = (float)((spk >> tid) & 1ULL);
}

// ---------------------------------------------------------------------------
// launch
// ---------------------------------------------------------------------------
extern "C" void kernel_launch(void* const* d_in, const int* in_sizes, int n_in,
                              void* d_out, int out_size)
{
    const float* x   = (const float*)d_in[0];
    const float* c1v = (const float*)d_in[1];
    const float* c1g = (const float*)d_in[2];
    const float* c2v = (const float*)d_in[3];
    const float* c2g = (const float*)d_in[4];
    const float* c3v = (const float*)d_in[5];
    const float* c3g = (const float*)d_in[6];
    const float* d1v = (const float*)d_in[7];
    const float* d1g = (const float*)d_in[8];
    const float* d2v = (const float*)d_in[9];
    const float* d2g = (const float*)d_in[10];
    float* out = (float*)d_out;

    void* fp = nullptr; void* up = nullptr;
    cudaGetSymbolAddress(&fp, g_fbuf);
    cudaGetSymbolAddress(&up, g_ubuf);
    float* F = (float*)fp;
    u64*   U = (u64*)up;

    float* W1  = F + W1_OFF;
    float* W2  = F + W2_OFF;
    float* W3  = F + W3_OFF;
    float* W4T = F + W4T_OFF;
    float* W5  = F + W5_OFF;
    u64* XP = U + XP_OFF;  u64* S1 = U + S1_OFF;  u64* S2 = U + S2_OFF;
    u64* S3 = U + S3_OFF;  u64* S4 = U + S4_OFF;

    const int SM1 = (400 + 256 * 65) * 4;                 // 68160
    const int SMD = (512 + 64 * 256 + 256 * 65) * 4;      // 134144

    cudaFuncSetAttribute(conv1_kernel,
                         cudaFuncAttributeMaxDynamicSharedMemorySize, SM1);
    cudaFuncSetAttribute(dense1_cuba_kernel,
                         cudaFuncAttributeMaxDynamicSharedMemorySize, SMD);

    wnorm_all_kernel<<<2171, 256>>>(c1v, c1g, c2v, c2g, c3v, c3g,
                                    d1v, d1g, d2v, d2g);
    pack_kernel<<<2048, 256>>>(x, XP);

    conv1_kernel<<<dim3(16, 32), 256, SM1>>>(XP, W1, S1);
    conv2_kernel<<<dim3(16, 16, 2), 256>>>(S1, W2, S2);
    conv3_kernel<<<dim3(16, 8), 256>>>(S2, W3, S3);

    dense1_cuba_kernel<<<dim3(16, 9), 256, SMD>>>(S3, W4T, S4);
    dense2_out_kernel<<<dim3(16, 11), 256>>>(S4, W5, out);
}

// round 3
// speedup vs baseline: 1.3958x; 1.0422x over previous
#include <cuda_runtime.h>
#include <cstdint>

typedef unsigned long long u64;

// ---------------------------------------------------------------------------
// Dimensions
// x: (16,2,128,128,64) -> conv1 (8,2,5,5) s4 p1 -> (16,8,32,32,T)
// -> conv2 (32,8,5,5) -> (16,32,8,8,T) -> conv3 (64,32,5,5) -> (16,64,2,2,T)
// -> dense1 256->2056 -> dense2 2056->11 -> out (16,11,64)
// ---------------------------------------------------------------------------

// float pool offsets
#define W1_OFF   0              // 8*50
#define W2_OFF   400            // 32*200
#define W3_OFF   6800           // 64*800
#define W4T_OFF  58000          // 256 * 2304 (transposed, padded rows)
#define W5_OFF   647824         // 11*2056
#define FBUF_TOTAL 670440

#define W4T_STRIDE 2304

// u64 pool offsets
#define XP_OFF 0                // 16*2*128*128
#define S1_OFF 524288           // 16*8*32*32
#define S2_OFF 655360           // 16*32*8*8
#define S3_OFF 688128           // 16*256
#define S4_OFF 692224           // 16*2056
#define UBUF_TOTAL 725120

__device__ float g_fbuf[FBUF_TOTAL];
__device__ u64   g_ubuf[UBUF_TOTAL];

// ---------------------------------------------------------------------------
// Fused weight_norm for all 5 layers. dense1 written TRANSPOSED (padded rows).
// ---------------------------------------------------------------------------
__global__ void wnorm_all_kernel(const float* __restrict__ c1v, const float* __restrict__ c1g,
                                 const float* __restrict__ c2v, const float* __restrict__ c2g,
                                 const float* __restrict__ c3v, const float* __restrict__ c3g,
                                 const float* __restrict__ d1v, const float* __restrict__ d1g,
                                 const float* __restrict__ d2v, const float* __restrict__ d2g)
{
    int blk = blockIdx.x;
    int tid = threadIdx.x;
    const float* v; const float* g; float* w; int cols; int r; int trans = 0;
    if (blk < 8)          { v = c1v; g = c1g; w = g_fbuf + W1_OFF;  cols = 50;   r = blk; }
    else if (blk < 40)    { v = c2v; g = c2g; w = g_fbuf + W2_OFF;  cols = 200;  r = blk - 8; }
    else if (blk < 104)   { v = c3v; g = c3g; w = g_fbuf + W3_OFF;  cols = 800;  r = blk - 40; }
    else if (blk < 2160)  { v = d1v; g = d1g; w = g_fbuf + W4T_OFF; cols = 256;  r = blk - 104; trans = 1; }
    else                  { v = d2v; g = d2g; w = g_fbuf + W5_OFF;  cols = 2056; r = blk - 2160; }

    __shared__ float red[256];
    float s = 0.0f;
    for (int i = tid; i < cols; i += 256) {
        float a = v[(size_t)r * cols + i];
        s += a * a;
    }
    red[tid] = s;
    __syncthreads();
    for (int off = 128; off > 0; off >>= 1) {
        if (tid < off) red[tid] += red[tid + off];
        __syncthreads();
    }
    float n = sqrtf(red[0]);
    float gr = g[r];
    if (!trans) {
        for (int i = tid; i < cols; i += 256)
            w[(size_t)r * cols + i] = gr * v[(size_t)r * cols + i] / n;
    } else {
        for (int i = tid; i < cols; i += 256)
            w[(size_t)i * W4T_STRIDE + r] = gr * v[(size_t)r * cols + i] / n;
    }
}

// ---------------------------------------------------------------------------
// Pack input spikes, coalesced (smem nibble transpose).
// ---------------------------------------------------------------------------
__global__ void __launch_bounds__(256)
pack_kernel(const float* __restrict__ x, u64* __restrict__ xp)
{
    __shared__ unsigned int nsm[256 * 17];
    int tid = threadIdx.x;
    const float4* xg = (const float4*)x + (size_t)blockIdx.x * 4096;
    #pragma unroll
    for (int j = 0; j < 16; ++j) {
        float4 f = xg[j * 256 + tid];
        unsigned int v = (f.x > 0.5f ? 1u : 0u) | (f.y > 0.5f ? 2u : 0u)
                       | (f.z > 0.5f ? 4u : 0u) | (f.w > 0.5f ? 8u : 0u);
        int pl  = j * 16 + (tid >> 4);
        int nib = tid & 15;
        nsm[pl * 17 + nib] = v;
    }
    __syncthreads();
    u64 m = 0;
    #pragma unroll
    for (int k = 0; k < 16; ++k)
        m |= (u64)nsm[tid * 17 + k] << (4 * k);
    xp[(size_t)blockIdx.x * 256 + tid] = m;
}

__device__ __forceinline__ void extract4(uint2 w, int tq, float f[4])
{
    f[0] = (float)((w.x >> tq) & 1u);
    f[1] = (float)((w.x >> (tq + 16)) & 1u);
    f[2] = (float)((w.y >> tq) & 1u);
    f[3] = (float)((w.y >> (tq + 16)) & 1u);
}

// ---------------------------------------------------------------------------
// conv1: 2->8, in 128x128, out 32x32. Block=(b,y), 512 blocks.
// 256 thr = 8 t-lanes (bits tq+8k) x 32 x-positions; thread tile 8o x 8t.
// One u64 load + 8 bit-extracts feed 64 FFMA.
// ---------------------------------------------------------------------------
__global__ void __launch_bounds__(256, 2)
conv1_kernel(const u64* __restrict__ xp, const float* __restrict__ wn,
             u64* __restrict__ sp)
{
    extern __shared__ float sm1[];
    float* wsm = sm1;            // [50 taps][8 o]
    float* zsm = sm1 + 400;      // [256 neurons][65]

    const int b = blockIdx.x, y = blockIdx.y;
    const int tid = threadIdx.x;
    const int tq = tid & 7, px = tid >> 3;

    for (int idx = tid; idx < 400; idx += 256)
        wsm[idx] = wn[(idx & 7) * 50 + (idx >> 3)];
    __syncthreads();

    float acc[8][8];   // [k(t)][o]
    #pragma unroll
    for (int k = 0; k < 8; ++k)
        #pragma unroll
        for (int o = 0; o < 8; ++o) acc[k][o] = 0.0f;

    #pragma unroll 1
    for (int c = 0; c < 2; ++c) {
        const u64* plane = xp + ((size_t)(b * 2 + c) << 14);
        #pragma unroll 1
        for (int ky = 0; ky < 5; ++ky) {
            int iy = y * 4 - 1 + ky;
            if (iy < 0) continue;
            const uint2* row = (const uint2*)(plane + ((size_t)iy << 7));
            #pragma unroll
            for (int kx = 0; kx < 5; ++kx) {
                const float* wp = wsm + (c * 25 + ky * 5 + kx) * 8;
                float4 wa = *(const float4*)wp;
                float4 wb = *(const float4*)(wp + 4);
                float wv[8] = {wa.x, wa.y, wa.z, wa.w, wb.x, wb.y, wb.z, wb.w};
                int ix = px * 4 - 1 + kx;
                uint2 w = make_uint2(0u, 0u);
                if (ix >= 0) w = row[ix];
                float f[8];
                #pragma unroll
                for (int k = 0; k < 4; ++k) {
                    f[k]     = (float)((w.x >> (tq + 8 * k)) & 1u);
                    f[k + 4] = (float)((w.y >> (tq + 8 * k)) & 1u);
                }
                #pragma unroll
                for (int k = 0; k < 8; ++k)
                    #pragma unroll
                    for (int o = 0; o < 8; ++o)
                        acc[k][o] = fmaf(wv[o], f[k], acc[k][o]);
            }
        }
    }

    #pragma unroll
    for (int k = 0; k < 8; ++k)
        #pragma unroll
        for (int o = 0; o < 8; ++o)
            zsm[(o * 32 + px) * 65 + tq + 8 * k] = acc[k][o];
    __syncthreads();

    {   // CUBA: one thread per neuron (o,p)
        int o = tid >> 5, p = tid & 31;
        float cc = 0.0f, vv = 0.0f;
        u64 m = 0;
        #pragma unroll 1
        for (int tt = 0; tt < 64; ++tt) {
            float z = zsm[tid * 65 + tt];
            cc = 0.7f * cc + z;
            vv = 0.75f * vv + cc;
            if (vv >= 1.0f) { m |= (1ULL << tt); vv = 0.0f; }
        }
        sp[(((size_t)b * 8 + o) * 32 + y) * 32 + p] = m;
    }
}

// ---------------------------------------------------------------------------
// conv2: 8->32, in 32x32, out 8x8. Grid (16 b, 4 st, 2 og) = 128 blocks.
// 256 thr = 16 tq x 16 pos; thread tile 16 o x 4 t -> 64 FFMA per word.
// Zero-word skip (exact: fma(w,0,acc)==acc).
// ---------------------------------------------------------------------------
__global__ void __launch_bounds__(256)
conv2_kernel(const u64* __restrict__ s1, const float* __restrict__ wn,
             u64* __restrict__ sp)
{
    extern __shared__ float sm2[];
    float* wsm = sm2;            // [200 taps][16 o]
    float* zsm = sm2 + 3200;     // [256 neurons][65]

    const int b = blockIdx.x, st = blockIdx.y, og = blockIdx.z;
    const int tid = threadIdx.x;
    const int tq = tid & 15, pp = tid >> 4;
    const int P = st * 16 + pp;
    const int y = P >> 3, x = P & 7;

    for (int idx = tid; idx < 3200; idx += 256)
        wsm[idx] = wn[(og * 16 + (idx & 15)) * 200 + (idx >> 4)];
    __syncthreads();

    float acc[4][16];
    #pragma unroll
    for (int k = 0; k < 4; ++k)
        #pragma unroll
        for (int j = 0; j < 16; ++j) acc[k][j] = 0.0f;

    #pragma unroll 1
    for (int c = 0; c < 8; ++c) {
        const u64* plane = s1 + ((size_t)(b * 8 + c) << 10);
        #pragma unroll 1
        for (int ky = 0; ky < 5; ++ky) {
            int iy = y * 4 - 1 + ky;
            if (iy < 0) continue;
            const uint2* row = (const uint2*)(plane + (size_t)iy * 32);
            #pragma unroll
            for (int kx = 0; kx < 5; ++kx) {
                int ix = x * 4 - 1 + kx;
                uint2 w = make_uint2(0u, 0u);
                if (ix >= 0) w = row[ix];
                if (w.x | w.y) {
                    float f[4]; extract4(w, tq, f);
                    const float* wp = wsm + (c * 25 + ky * 5 + kx) * 16;
                    float4 w0 = *(const float4*)(wp);
                    float4 w1 = *(const float4*)(wp + 4);
                    float4 w2 = *(const float4*)(wp + 8);
                    float4 w3 = *(const float4*)(wp + 12);
                    float wv[16] = {w0.x, w0.y, w0.z, w0.w, w1.x, w1.y, w1.z, w1.w,
                                    w2.x, w2.y, w2.z, w2.w, w3.x, w3.y, w3.z, w3.w};
                    #pragma unroll
                    for (int k = 0; k < 4; ++k)
                        #pragma unroll
                        for (int j = 0; j < 16; ++j)
                            acc[k][j] = fmaf(wv[j], f[k], acc[k][j]);
                }
            }
        }
    }

    #pragma unroll
    for (int k = 0; k < 4; ++k)
        #pragma unroll
        for (int j = 0; j < 16; ++j)
            zsm[(j * 16 + pp) * 65 + tq + 16 * k] = acc[k][j];
    __syncthreads();

    {   // CUBA: 256 neurons, one per thread
        int j = tid >> 4, p = tid & 15;
        float cc = 0.0f, vv = 0.0f;
        u64 m = 0;
        #pragma unroll 1
        for (int tt = 0; tt < 64; ++tt) {
            float z = zsm[tid * 65 + tt];
            cc = 0.7f * cc + z;
            vv = 0.75f * vv + cc;
            if (vv >= 1.0f) { m |= (1ULL << tt); vv = 0.0f; }
        }
        int Pp = st * 16 + p;
        int yy = Pp >> 3, xx = Pp & 7;
        sp[(((size_t)b * 32 + og * 16 + j) * 8 + yy) * 8 + xx] = m;
    }
}

// ---------------------------------------------------------------------------
// conv3: 32->64, in 8x8, out 2x2. Grid (16 b, 8 og); warp-uniform zero skip.
// ---------------------------------------------------------------------------
__global__ void __launch_bounds__(256)
conv3_kernel(const u64* __restrict__ s2, const float* __restrict__ wn,
             u64* __restrict__ sp)
{
    __shared__ float wsm[800 * 8];   // [tap][8 o]
    __shared__ float zsm[32 * 65];

    const int b = blockIdx.x, og = blockIdx.y;
    const int tid = threadIdx.x;
    const int t = tid & 63, pq = tid >> 6;
    const int y = pq >> 1, x = pq & 1;
    const unsigned int mbit = 1u << (t & 31);
    const bool hi = t >= 32;

    for (int idx = tid; idx < 6400; idx += 256)
        wsm[idx] = wn[(og * 8 + (idx & 7)) * 800 + (idx >> 3)];
    __syncthreads();

    float acc[8];
    #pragma unroll
    for (int o = 0; o < 8; ++o) acc[o] = 0.0f;

    #pragma unroll 1
    for (int c = 0; c < 32; ++c) {
        const u64* plane = s2 + ((size_t)(b * 32 + c) << 6);
        #pragma unroll 1
        for (int ky = 0; ky < 5; ++ky) {
            int iy = y * 4 - 1 + ky;
            if (iy < 0) continue;
            const uint2* row = (const uint2*)(plane + (size_t)iy * 8);
            #pragma unroll
            for (int kx = 0; kx < 5; ++kx) {
                int ix = x * 4 - 1 + kx;
                uint2 w = make_uint2(0u, 0u);
                if (ix >= 0) w = row[ix];
                if (w.x | w.y) {   // warp-uniform: all lanes share this word
                    const float* wp = wsm + (c * 25 + ky * 5 + kx) * 8;
                    float4 wa = *(const float4*)wp;
                    float4 wb = *(const float4*)(wp + 4);
                    unsigned int ui = hi ? w.y : w.x;
                    float f = (ui & mbit) ? 1.0f : 0.0f;
                    acc[0] = fmaf(wa.x, f, acc[0]);
                    acc[1] = fmaf(wa.y, f, acc[1]);
                    acc[2] = fmaf(wa.z, f, acc[2]);
                    acc[3] = fmaf(wa.w, f, acc[3]);
                    acc[4] = fmaf(wb.x, f, acc[4]);
                    acc[5] = fmaf(wb.y, f, acc[5]);
                    acc[6] = fmaf(wb.z, f, acc[6]);
                    acc[7] = fmaf(wb.w, f, acc[7]);
                }
            }
        }
    }

    #pragma unroll
    for (int o = 0; o < 8; ++o)
        zsm[(o * 4 + pq) * 65 + t] = acc[o];
    __syncthreads();

    if (tid < 32) {
        int o = tid >> 2, p = tid & 3;
        float cc = 0.0f, vv = 0.0f;
        u64 m = 0;
        #pragma unroll 1
        for (int tt = 0; tt < 64; ++tt) {
            float z = zsm[tid * 65 + tt];
            cc = 0.7f * cc + z;
            vv = 0.75f * vv + cc;
            if (vv >= 1.0f) { m |= (1ULL << tt); vv = 0.0f; }
        }
        sp[(size_t)b * 256 + (og * 8 + o) * 4 + p] = m;
    }
}

// ---------------------------------------------------------------------------
// dense1: 256->2056 + CUBA. Grid (16 b, 9 og of 256 o). Block-uniform
// zero-word skip in the i loop.
// ---------------------------------------------------------------------------
__global__ void __launch_bounds__(256)
dense1_cuba_kernel(const u64* __restrict__ s3,
                   const float* __restrict__ w4t,
                   u64* __restrict__ s4)
{
    extern __shared__ float smd[];
    u64*   words = (u64*)smd;                 // 256 u64
    float* wsm   = smd + 512;                 // [64 i][256 o]
    float* zsm   = wsm + 64 * 256;            // [256][65]

    const int b = blockIdx.x, og = blockIdx.y;
    const int tid = threadIdx.x;
    const int tq = tid & 15, oq = tid >> 4;

    words[tid] = s3[b * 256 + tid];

    float acc[4][16];
    #pragma unroll
    for (int k = 0; k < 4; ++k)
        #pragma unroll
        for (int j = 0; j < 16; ++j) acc[k][j] = 0.0f;

    #pragma unroll 1
    for (int q = 0; q < 4; ++q) {
        __syncthreads();
        #pragma unroll
        for (int r = 0; r < 16; ++r) {
            int f4 = r * 256 + tid;
            int ii = f4 >> 6;
            int o4 = (f4 & 63) * 4;
            *(float4*)(wsm + ii * 256 + o4) =
                *(const float4*)(w4t + (size_t)(q * 64 + ii) * W4T_STRIDE + og * 256 + o4);
        }
        __syncthreads();

        #pragma unroll 2
        for (int ii = 0; ii < 64; ++ii) {
            u64 wd = words[q * 64 + ii];
            if (wd == 0ULL) continue;          // block-uniform, exact skip
            uint2 w = make_uint2((unsigned int)wd, (unsigned int)(wd >> 32));
            float f[4]; extract4(w, tq, f);
            const float* wp = wsm + ii * 256 + oq * 16;
            float4 w0 = *(const float4*)(wp);
            float4 w1 = *(const float4*)(wp + 4);
            float4 w2 = *(const float4*)(wp + 8);
            float4 w3 = *(const float4*)(wp + 12);
            float wr[16] = {w0.x, w0.y, w0.z, w0.w, w1.x, w1.y, w1.z, w1.w,
                            w2.x, w2.y, w2.z, w2.w, w3.x, w3.y, w3.z, w3.w};
            #pragma unroll
            for (int k = 0; k < 4; ++k)
                #pragma unroll
                for (int j = 0; j < 16; ++j)
                    acc[k][j] = fmaf(wr[j], f[k], acc[k][j]);
        }
    }

    #pragma unroll
    for (int k = 0; k < 4; ++k)
        #pragma unroll
        for (int j = 0; j < 16; ++j)
            zsm[(oq * 16 + j) * 65 + tq + 16 * k] = acc[k][j];
    __syncthreads();

    {
        int o_g = og * 256 + tid;
        float cc = 0.0f, vv = 0.0f;
        u64 m = 0;
        #pragma unroll 1
        for (int tt = 0; tt < 64; ++tt) {
            float z = zsm[tid * 65 + tt];
            cc = 0.7f * cc + z;
            vv = 0.75f * vv + cc;
            if (vv >= 1.0f) { m |= (1ULL << tt); vv = 0.0f; }
        }
        if (o_g < 2056) s4[b * 2056 + o_g] = m;
    }
}

// ---------------------------------------------------------------------------
// dense2 (2056->11) + final CUBA + float output. Grid (16 b, 11 o).
// ---------------------------------------------------------------------------
__global__ void __launch_bounds__(256)
dense2_out_kernel(const u64* __restrict__ s4, const float* __restrict__ w5,
                  float* __restrict__ out)
{
    __shared__ float part[4][64];
    __shared__ float zrow[64];
    __shared__ u64 spk;

    const int b = blockIdx.x, o = blockIdx.y;
    const int tid = threadIdx.x;
    const int t = tid & 63, q = tid >> 6;

    float s = 0.0f;
    const u64*   wp = s4 + b * 2056;
    const float* vp = w5 + (size_t)o * 2056;
    for (int i = q * 514; i < q * 514 + 514; ++i) {
        float wt = vp[i];
        if ((wp[i] >> t) & 1ULL) s += wt;
    }
    part[q][t] = s;
    __syncthreads();
    if (tid < 64)
        zrow[tid] = part[0][tid] + part[1][tid] + part[2][tid] + part[3][tid];
    __syncthreads();
    if (tid == 0) {
        float cc = 0.0f, vv = 0.0f;
        u64 m = 0;
        #pragma unroll 1
        for (int tt = 0; tt < 64; ++tt) {
            cc = 0.7f * cc + zrow[tt];
            vv = 0.75f * vv + cc;
            if (vv >= 1.0f) { m |= (1ULL << tt); vv = 0.0f; }
        }
        spk = m;
    }
    __syncthreads();
    if (tid < 64)
        out[((size_t)b * 11 + o) * 64 + tid] = (float)((spk >> tid) & 1ULL);
}

// ---------------------------------------------------------------------------
// launch
// ---------------------------------------------------------------------------
extern "C" void kernel_launch(void* const* d_in, const int* in_sizes, int n_in,
                              void* d_out, int out_size)
{
    const float* x   = (const float*)d_in[0];
    const float* c1v = (const float*)d_in[1];
    const float* c1g = (const float*)d_in[2];
    const float* c2v = (const float*)d_in[3];
    const float* c2g = (const float*)d_in[4];
    const float* c3v = (const float*)d_in[5];
    const float* c3g = (const float*)d_in[6];
    const float* d1v = (const float*)d_in[7];
    const float* d1g = (const float*)d_in[8];
    const float* d2v = (const float*)d_in[9];
    const float* d2g = (const float*)d_in[10];
    float* out = (float*)d_out;

    void* fp = nullptr; void* up = nullptr;
    cudaGetSymbolAddress(&fp, g_fbuf);
    cudaGetSymbolAddress(&up, g_ubuf);
    float* F = (float*)fp;
    u64*   U = (u64*)up;

    float* W1  = F + W1_OFF;
    float* W2  = F + W2_OFF;
    float* W3  = F + W3_OFF;
    float* W4T = F + W4T_OFF;
    float* W5  = F + W5_OFF;
    u64* XP = U + XP_OFF;  u64* S1 = U + S1_OFF;  u64* S2 = U + S2_OFF;
    u64* S3 = U + S3_OFF;  u64* S4 = U + S4_OFF;

    const int SM1 = (400 + 256 * 65) * 4;                 // 68160
    const int SM2 = (3200 + 256 * 65) * 4;                // 79360
    const int SMD = (512 + 64 * 256 + 256 * 65) * 4;      // 134144

    cudaFuncSetAttribute(conv1_kernel,
                         cudaFuncAttributeMaxDynamicSharedMemorySize, SM1);
    cudaFuncSetAttribute(conv2_kernel,
                         cudaFuncAttributeMaxDynamicSharedMemorySize, SM2);
    cudaFuncSetAttribute(dense1_cuba_kernel,
                         cudaFuncAttributeMaxDynamicSharedMemorySize, SMD);

    wnorm_all_kernel<<<2171, 256>>>(c1v, c1g, c2v, c2g, c3v, c3g,
                                    d1v, d1g, d2v, d2g);
    pack_kernel<<<2048, 256>>>(x, XP);

    conv1_kernel<<<dim3(16, 32), 256, SM1>>>(XP, W1, S1);
    conv2_kernel<<<dim3(16, 4, 2), 256, SM2>>>(S1, W2, S2);
    conv3_kernel<<<dim3(16, 8), 256>>>(S2, W3, S3);

    dense1_cuba_kernel<<<dim3(16, 9), 256, SMD>>>(S3, W4T, S4);
    dense2_out_kernel<<<dim3(16, 11), 256>>>(S4, W5, out);
}

// round 4
// speedup vs baseline: 1.4086x; 1.0091x over previous
#include <cuda_runtime.h>
#include <cstdint>

typedef unsigned long long u64;

// ---------------------------------------------------------------------------
// Dimensions
// x: (16,2,128,128,64) -> conv1 (8,2,5,5) s4 p1 -> (16,8,32,32,T)
// -> conv2 (32,8,5,5) -> (16,32,8,8,T) -> conv3 (64,32,5,5) -> (16,64,2,2,T)
// -> dense1 256->2056 -> dense2 2056->11 -> out (16,11,64)
// ---------------------------------------------------------------------------

// float pool offsets
#define W1_OFF   0              // 8*50
#define W2_OFF   400            // 32*200
#define W3_OFF   6800           // 64*800
#define W4T_OFF  58000          // 256 * 2304 (transposed, padded rows)
#define W5_OFF   647824         // 11*2056
#define FBUF_TOTAL 670440

#define W4T_STRIDE 2304

// u64 pool offsets
#define XP_OFF 0                // 16*2*128*128
#define S1_OFF 524288           // 16*8*32*32
#define S2_OFF 655360           // 16*32*8*8
#define S3_OFF 688128           // 16*256
#define S4_OFF 692224           // 16*2056
#define UBUF_TOTAL 725120

__device__ float g_fbuf[FBUF_TOTAL];
__device__ u64   g_ubuf[UBUF_TOTAL];

// ---------------------------------------------------------------------------
// f32x2 packed-FMA helpers. Each 64-bit reg holds two fp32 lanes; every lane
// op is an exact IEEE fp32 FMA, so results match scalar fmaf bit-for-bit.
// ---------------------------------------------------------------------------
__device__ __forceinline__ void ffma2(u64& d, u64 a, u64 b)
{
    asm("fma.rn.f32x2 %0, %1, %2, %0;" : "+l"(d) : "l"(a), "l"(b));
}
// broadcast a spike bit to both fp32 lanes: {1.0f,1.0f} or {0,0}
__device__ __forceinline__ u64 bit2f2(unsigned int word, int t)
{
    return ((word >> t) & 1u) ? 0x3F8000003F800000ULL : 0ULL;
}
__device__ __forceinline__ void unpack2(u64 p, float& lo, float& hi)
{
    unsigned int l_, h_;
    asm("mov.b64 {%0,%1}, %2;" : "=r"(l_), "=r"(h_) : "l"(p));
    lo = __uint_as_float(l_);
    hi = __uint_as_float(h_);
}

// ---------------------------------------------------------------------------
// Fused weight_norm for all 5 layers. dense1 written TRANSPOSED (padded rows).
// ---------------------------------------------------------------------------
__global__ void wnorm_all_kernel(const float* __restrict__ c1v, const float* __restrict__ c1g,
                                 const float* __restrict__ c2v, const float* __restrict__ c2g,
                                 const float* __restrict__ c3v, const float* __restrict__ c3g,
                                 const float* __restrict__ d1v, const float* __restrict__ d1g,
                                 const float* __restrict__ d2v, const float* __restrict__ d2g)
{
    int blk = blockIdx.x;
    int tid = threadIdx.x;
    const float* v; const float* g; float* w; int cols; int r; int trans = 0;
    if (blk < 8)          { v = c1v; g = c1g; w = g_fbuf + W1_OFF;  cols = 50;   r = blk; }
    else if (blk < 40)    { v = c2v; g = c2g; w = g_fbuf + W2_OFF;  cols = 200;  r = blk - 8; }
    else if (blk < 104)   { v = c3v; g = c3g; w = g_fbuf + W3_OFF;  cols = 800;  r = blk - 40; }
    else if (blk < 2160)  { v = d1v; g = d1g; w = g_fbuf + W4T_OFF; cols = 256;  r = blk - 104; trans = 1; }
    else                  { v = d2v; g = d2g; w = g_fbuf + W5_OFF;  cols = 2056; r = blk - 2160; }

    __shared__ float red[256];
    float s = 0.0f;
    for (int i = tid; i < cols; i += 256) {
        float a = v[(size_t)r * cols + i];
        s += a * a;
    }
    red[tid] = s;
    __syncthreads();
    for (int off = 128; off > 0; off >>= 1) {
        if (tid < off) red[tid] += red[tid + off];
        __syncthreads();
    }
    float n = sqrtf(red[0]);
    float gr = g[r];
    if (!trans) {
        for (int i = tid; i < cols; i += 256)
            w[(size_t)r * cols + i] = gr * v[(size_t)r * cols + i] / n;
    } else {
        for (int i = tid; i < cols; i += 256)
            w[(size_t)i * W4T_STRIDE + r] = gr * v[(size_t)r * cols + i] / n;
    }
}

// ---------------------------------------------------------------------------
// Pack input spikes, coalesced (smem nibble transpose).
// ---------------------------------------------------------------------------
__global__ void __launch_bounds__(256)
pack_kernel(const float* __restrict__ x, u64* __restrict__ xp)
{
    __shared__ unsigned int nsm[256 * 17];
    int tid = threadIdx.x;
    const float4* xg = (const float4*)x + (size_t)blockIdx.x * 4096;
    #pragma unroll
    for (int j = 0; j < 16; ++j) {
        float4 f = xg[j * 256 + tid];
        unsigned int v = (f.x > 0.5f ? 1u : 0u) | (f.y > 0.5f ? 2u : 0u)
                       | (f.z > 0.5f ? 4u : 0u) | (f.w > 0.5f ? 8u : 0u);
        int pl  = j * 16 + (tid >> 4);
        int nib = tid & 15;
        nsm[pl * 17 + nib] = v;
    }
    __syncthreads();
    u64 m = 0;
    #pragma unroll
    for (int k = 0; k < 16; ++k)
        m |= (u64)nsm[tid * 17 + k] << (4 * k);
    xp[(size_t)blockIdx.x * 256 + tid] = m;
}

// ---------------------------------------------------------------------------
// conv1: 2->8, in 128x128, out 32x32. Grid (16 b, 32 y, 2 xh) = 1024 blocks.
// 256 thr = 16 tq x 16 px; thread tile 8o(4 f32x2 pairs) x 4t.
// ---------------------------------------------------------------------------
__global__ void __launch_bounds__(256)
conv1_kernel(const u64* __restrict__ xp, const float* __restrict__ wn,
             u64* __restrict__ sp)
{
    __shared__ __align__(16) float wsm[400];       // [50 taps][8 o]
    __shared__ float zsm[128 * 65];                // 128 neurons

    const int b = blockIdx.x, y = blockIdx.y, xh = blockIdx.z;
    const int tid = threadIdx.x;
    const int tq = tid & 15, pxl = tid >> 4;
    const int px = xh * 16 + pxl;

    for (int idx = tid; idx < 400; idx += 256)
        wsm[idx] = wn[(idx & 7) * 50 + (idx >> 3)];
    __syncthreads();

    u64 acc[4][4];   // [opair][k(t)]
    #pragma unroll
    for (int j = 0; j < 4; ++j)
        #pragma unroll
        for (int k = 0; k < 4; ++k) acc[j][k] = 0ULL;

    #pragma unroll 1
    for (int c = 0; c < 2; ++c) {
        const u64* plane = xp + ((size_t)(b * 2 + c) << 14);
        #pragma unroll 1
        for (int ky = 0; ky < 5; ++ky) {
            int iy = y * 4 - 1 + ky;
            if (iy < 0) continue;
            const u64* row = plane + ((size_t)iy << 7);
            #pragma unroll
            for (int kx = 0; kx < 5; ++kx) {
                int ix = px * 4 - 1 + kx;
                u64 word = 0ULL;
                if (ix >= 0) word = row[ix];
                unsigned int lo = (unsigned int)word;
                unsigned int hi = (unsigned int)(word >> 32);
                u64 fd[4];
                fd[0] = bit2f2(lo, tq);
                fd[1] = bit2f2(lo, tq + 16);
                fd[2] = bit2f2(hi, tq);
                fd[3] = bit2f2(hi, tq + 16);
                const ulonglong2* wp =
                    (const ulonglong2*)(wsm + (c * 25 + ky * 5 + kx) * 8);
                ulonglong2 wA = wp[0];   // pairs (o0,o1),(o2,o3)
                ulonglong2 wB = wp[1];   // pairs (o4,o5),(o6,o7)
                u64 wpair[4] = {wA.x, wA.y, wB.x, wB.y};
                #pragma unroll
                for (int k = 0; k < 4; ++k)
                    #pragma unroll
                    for (int j = 0; j < 4; ++j)
                        ffma2(acc[j][k], wpair[j], fd[k]);
            }
        }
    }

    #pragma unroll
    for (int j = 0; j < 4; ++j)
        #pragma unroll
        for (int k = 0; k < 4; ++k) {
            float lo, hi;
            unpack2(acc[j][k], lo, hi);
            zsm[((2 * j)     * 16 + pxl) * 65 + tq + 16 * k] = lo;
            zsm[((2 * j + 1) * 16 + pxl) * 65 + tq + 16 * k] = hi;
        }
    __syncthreads();

    if (tid < 128) {   // CUBA: neuron = (o, pxl)
        int o = tid >> 4, p = tid & 15;
        float cc = 0.0f, vv = 0.0f;
        u64 m = 0;
        #pragma unroll 1
        for (int tt = 0; tt < 64; ++tt) {
            float z = zsm[tid * 65 + tt];
            cc = 0.7f * cc + z;
            vv = 0.75f * vv + cc;
            if (vv >= 1.0f) { m |= (1ULL << tt); vv = 0.0f; }
        }
        sp[(((size_t)b * 8 + o) * 32 + y) * 32 + xh * 16 + p] = m;
    }
}

// ---------------------------------------------------------------------------
// conv2: 8->32, in 32x32, out 8x8. Grid (16 b, 16 st, 2 og) = 512 blocks.
// 256 thr = 64 t x 4 pos; thread tile 16o (8 f32x2 pairs) x 1t.
// Word is warp-uniform -> zero-skip has no divergence.
// ---------------------------------------------------------------------------
__global__ void __launch_bounds__(256)
conv2_kernel(const u64* __restrict__ s1, const float* __restrict__ wn,
             u64* __restrict__ sp)
{
    __shared__ __align__(16) float wsm[200 * 16];  // [tap][16 o]
    __shared__ float zsm[64 * 65];                 // 64 neurons

    const int b = blockIdx.x, st = blockIdx.y, og = blockIdx.z;
    const int tid = threadIdx.x;
    const int t = tid & 63, pq = tid >> 6;
    const int P = st * 4 + pq;
    const int y = P >> 3, x = P & 7;
    const unsigned int mbit_t = t & 31;
    const bool hi_t = t >= 32;

    for (int idx = tid; idx < 3200; idx += 256)
        wsm[idx] = wn[(og * 16 + (idx & 15)) * 200 + (idx >> 4)];
    __syncthreads();

    u64 acc[8];
    #pragma unroll
    for (int j = 0; j < 8; ++j) acc[j] = 0ULL;

    #pragma unroll 1
    for (int c = 0; c < 8; ++c) {
        const u64* plane = s1 + ((size_t)(b * 8 + c) << 10);
        #pragma unroll 1
        for (int ky = 0; ky < 5; ++ky) {
            int iy = y * 4 - 1 + ky;
            if (iy < 0) continue;
            const u64* row = plane + (size_t)iy * 32;
            #pragma unroll
            for (int kx = 0; kx < 5; ++kx) {
                int ix = x * 4 - 1 + kx;
                u64 word = 0ULL;
                if (ix >= 0) word = row[ix];
                if (word) {   // warp-uniform skip
                    unsigned int half = hi_t ? (unsigned int)(word >> 32)
                                             : (unsigned int)word;
                    u64 f = bit2f2(half, mbit_t);
                    const ulonglong2* wp =
                        (const ulonglong2*)(wsm + (c * 25 + ky * 5 + kx) * 16);
                    ulonglong2 w0 = wp[0], w1 = wp[1], w2 = wp[2], w3 = wp[3];
                    ffma2(acc[0], w0.x, f);
                    ffma2(acc[1], w0.y, f);
                    ffma2(acc[2], w1.x, f);
                    ffma2(acc[3], w1.y, f);
                    ffma2(acc[4], w2.x, f);
                    ffma2(acc[5], w2.y, f);
                    ffma2(acc[6], w3.x, f);
                    ffma2(acc[7], w3.y, f);
                }
            }
        }
    }

    #pragma unroll
    for (int j = 0; j < 8; ++j) {
        float lo, hi;
        unpack2(acc[j], lo, hi);
        zsm[((2 * j)     * 4 + pq) * 65 + t] = lo;
        zsm[((2 * j + 1) * 4 + pq) * 65 + t] = hi;
    }
    __syncthreads();

    if (tid < 64) {   // CUBA
        int o_loc = tid >> 2, p = tid & 3;
        float cc = 0.0f, vv = 0.0f;
        u64 m = 0;
        #pragma unroll 1
        for (int tt = 0; tt < 64; ++tt) {
            float z = zsm[tid * 65 + tt];
            cc = 0.7f * cc + z;
            vv = 0.75f * vv + cc;
            if (vv >= 1.0f) { m |= (1ULL << tt); vv = 0.0f; }
        }
        int Pp = st * 4 + p;
        int yy = Pp >> 3, xx = Pp & 7;
        sp[(((size_t)b * 32 + og * 16 + o_loc) * 8 + yy) * 8 + xx] = m;
    }
}

// ---------------------------------------------------------------------------
// conv3: 32->64, in 8x8, out 2x2. Grid (16 b, 16 og of 4 o) = 256 blocks.
// 256 thr = 64 t x 4 pos; tile 4o (2 pairs) x 1t; warp-uniform zero skip.
// ---------------------------------------------------------------------------
__global__ void __launch_bounds__(256)
conv3_kernel(const u64* __restrict__ s2, const float* __restrict__ wn,
             u64* __restrict__ sp)
{
    __shared__ __align__(16) float wsm[800 * 4];   // [tap][4 o]
    __shared__ float zsm[16 * 65];

    const int b = blockIdx.x, og = blockIdx.y;
    const int tid = threadIdx.x;
    const int t = tid & 63, pq = tid >> 6;
    const int y = pq >> 1, x = pq & 1;
    const unsigned int mbit_t = t & 31;
    const bool hi_t = t >= 32;

    for (int idx = tid; idx < 3200; idx += 256)
        wsm[idx] = wn[(og * 4 + (idx & 3)) * 800 + (idx >> 2)];
    __syncthreads();

    u64 acc[2] = {0ULL, 0ULL};

    #pragma unroll 1
    for (int c = 0; c < 32; ++c) {
        const u64* plane = s2 + ((size_t)(b * 32 + c) << 6);
        #pragma unroll 1
        for (int ky = 0; ky < 5; ++ky) {
            int iy = y * 4 - 1 + ky;
            if (iy < 0) continue;
            const u64* row = plane + (size_t)iy * 8;
            #pragma unroll
            for (int kx = 0; kx < 5; ++kx) {
                int ix = x * 4 - 1 + kx;
                u64 word = 0ULL;
                if (ix >= 0) word = row[ix];
                if (word) {
                    unsigned int half = hi_t ? (unsigned int)(word >> 32)
                                             : (unsigned int)word;
                    u64 f = bit2f2(half, mbit_t);
                    ulonglong2 w01 =
                        *(const ulonglong2*)(wsm + (c * 25 + ky * 5 + kx) * 4);
                    ffma2(acc[0], w01.x, f);
                    ffma2(acc[1], w01.y, f);
                }
            }
        }
    }

    #pragma unroll
    for (int j = 0; j < 2; ++j) {
        float lo, hi;
        unpack2(acc[j], lo, hi);
        zsm[((2 * j)     * 4 + pq) * 65 + t] = lo;
        zsm[((2 * j + 1) * 4 + pq) * 65 + t] = hi;
    }
    __syncthreads();

    if (tid < 16) {
        int o = tid >> 2, p = tid & 3;
        float cc = 0.0f, vv = 0.0f;
        u64 m = 0;
        #pragma unroll 1
        for (int tt = 0; tt < 64; ++tt) {
            float z = zsm[tid * 65 + tt];
            cc = 0.7f * cc + z;
            vv = 0.75f * vv + cc;
            if (vv >= 1.0f) { m |= (1ULL << tt); vv = 0.0f; }
        }
        sp[(size_t)b * 256 + (og * 4 + o) * 4 + p] = m;
    }
}

// ---------------------------------------------------------------------------
// dense1: 256->2056 + CUBA. Grid (16 b, 17 og of 128 o) = 272 blocks.
// 256 thr = 32 tq x 8 oq; tile 16o (8 pairs) x 2t (tq, tq+32).
// Block-uniform zero-word skip.
// ---------------------------------------------------------------------------
__global__ void __launch_bounds__(256)
dense1_cuba_kernel(const u64* __restrict__ s3,
                   const float* __restrict__ w4t,
                   u64* __restrict__ s4)
{
    extern __shared__ __align__(16) float smd[];
    u64*   words = (u64*)smd;                 // 256 u64 (512 f)
    float* wsm   = smd + 512;                 // [64 i][128 o]
    float* zsm   = wsm + 64 * 128;            // [128][65]

    const int b = blockIdx.x, og = blockIdx.y;
    const int tid = threadIdx.x;
    const int tq = tid & 31, oq = tid >> 5;

    words[tid] = s3[b * 256 + tid];

    u64 acc[8][2];
    #pragma unroll
    for (int j = 0; j < 8; ++j) { acc[j][0] = 0ULL; acc[j][1] = 0ULL; }

    #pragma unroll 1
    for (int q = 0; q < 4; ++q) {
        __syncthreads();
        // stage 64 i-rows x 128 o (coalesced float4)
        #pragma unroll
        for (int r = 0; r < 8; ++r) {
            int f4 = r * 256 + tid;           // 0..2047
            int ii = f4 >> 5;                 // 0..63
            int o4 = (f4 & 31) * 4;           // 0..124
            *(float4*)(wsm + ii * 128 + o4) =
                *(const float4*)(w4t + (size_t)(q * 64 + ii) * W4T_STRIDE + og * 128 + o4);
        }
        __syncthreads();

        #pragma unroll 2
        for (int ii = 0; ii < 64; ++ii) {
            u64 wd = words[q * 64 + ii];
            if (wd == 0ULL) continue;          // block-uniform, exact skip
            u64 f0 = bit2f2((unsigned int)wd, tq);
            u64 f1 = bit2f2((unsigned int)(wd >> 32), tq);
            const ulonglong2* wp = (const ulonglong2*)(wsm + ii * 128 + oq * 16);
            ulonglong2 w0 = wp[0], w1 = wp[1], w2 = wp[2], w3 = wp[3];
            u64 wpair[8] = {w0.x, w0.y, w1.x, w1.y, w2.x, w2.y, w3.x, w3.y};
            #pragma unroll
            for (int j = 0; j < 8; ++j) {
                ffma2(acc[j][0], wpair[j], f0);
                ffma2(acc[j][1], wpair[j], f1);
            }
        }
    }

    #pragma unroll
    for (int j = 0; j < 8; ++j)
        #pragma unroll
        for (int k = 0; k < 2; ++k) {
            float lo, hi;
            unpack2(acc[j][k], lo, hi);
            zsm[(oq * 16 + 2 * j)     * 65 + tq + 32 * k] = lo;
            zsm[(oq * 16 + 2 * j + 1) * 65 + tq + 32 * k] = hi;
        }
    __syncthreads();

    if (tid < 128) {
        int o_g = og * 128 + tid;
        float cc = 0.0f, vv = 0.0f;
        u64 m = 0;
        #pragma unroll 1
        for (int tt = 0; tt < 64; ++tt) {
            float z = zsm[tid * 65 + tt];
            cc = 0.7f * cc + z;
            vv = 0.75f * vv + cc;
            if (vv >= 1.0f) { m |= (1ULL << tt); vv = 0.0f; }
        }
        if (o_g < 2056) s4[b * 2056 + o_g] = m;
    }
}

// ---------------------------------------------------------------------------
// dense2 (2056->11) + final CUBA + float output. Grid (16 b, 11 o).
// ---------------------------------------------------------------------------
__global__ void __launch_bounds__(256)
dense2_out_kernel(const u64* __restrict__ s4, const float* __restrict__ w5,
                  float* __restrict__ out)
{
    __shared__ float part[4][64];
    __shared__ float zrow[64];
    __shared__ u64 spk;

    const int b = blockIdx.x, o = blockIdx.y;
    const int tid = threadIdx.x;
    const int t = tid & 63, q = tid >> 6;

    float s = 0.0f;
    const u64*   wp = s4 + b * 2056;
    const float* vp = w5 + (size_t)o * 2056;
    for (int i = q * 514; i < q * 514 + 514; ++i) {
        float wt = vp[i];
        if ((wp[i] >> t) & 1ULL) s += wt;
    }
    part[q][t] = s;
    __syncthreads();
    if (tid < 64)
        zrow[tid] = part[0][tid] + part[1][tid] + part[2][tid] + part[3][tid];
    __syncthreads();
    if (tid == 0) {
        float cc = 0.0f, vv = 0.0f;
        u64 m = 0;
        #pragma unroll 1
        for (int tt = 0; tt < 64; ++tt) {
            cc = 0.7f * cc + zrow[tt];
            vv = 0.75f * vv + cc;
            if (vv >= 1.0f) { m |= (1ULL << tt); vv = 0.0f; }
        }
        spk = m;
    }
    __syncthreads();
    if (tid < 64)
        out[((size_t)b * 11 + o) * 64 + tid] = (float)((spk >> tid) & 1ULL);
}

// ---------------------------------------------------------------------------
// launch
// ---------------------------------------------------------------------------
extern "C" void kernel_launch(void* const* d_in, const int* in_sizes, int n_in,
                              void* d_out, int out_size)
{
    const float* x   = (const float*)d_in[0];
    const float* c1v = (const float*)d_in[1];
    const float* c1g = (const float*)d_in[2];
    const float* c2v = (const float*)d_in[3];
    const float* c2g = (const float*)d_in[4];
    const float* c3v = (const float*)d_in[5];
    const float* c3g = (const float*)d_in[6];
    const float* d1v = (const float*)d_in[7];
    const float* d1g = (const float*)d_in[8];
    const float* d2v = (const float*)d_in[9];
    const float* d2g = (const float*)d_in[10];
    float* out = (float*)d_out;

    void* fp = nullptr; void* up = nullptr;
    cudaGetSymbolAddress(&fp, g_fbuf);
    cudaGetSymbolAddress(&up, g_ubuf);
    float* F = (float*)fp;
    u64*   U = (u64*)up;

    float* W1  = F + W1_OFF;
    float* W2  = F + W2_OFF;
    float* W3  = F + W3_OFF;
    float* W4T = F + W4T_OFF;
    float* W5  = F + W5_OFF;
    u64* XP = U + XP_OFF;  u64* S1 = U + S1_OFF;  u64* S2 = U + S2_OFF;
    u64* S3 = U + S3_OFF;  u64* S4 = U + S4_OFF;

    const int SMD = (512 + 64 * 128 + 128 * 65) * 4;   // 68096 bytes

    cudaFuncSetAttribute(dense1_cuba_kernel,
                         cudaFuncAttributeMaxDynamicSharedMemorySize, SMD);

    wnorm_all_kernel<<<2171, 256>>>(c1v, c1g, c2v, c2g, c3v, c3g,
                                    d1v, d1g, d2v, d2g);
    pack_kernel<<<2048, 256>>>(x, XP);

    conv1_kernel<<<dim3(16, 32, 2), 256>>>(XP, W1, S1);
    conv2_kernel<<<dim3(16, 16, 2), 256>>>(S1, W2, S2);
    conv3_kernel<<<dim3(16, 16), 256>>>(S2, W3, S3);

    dense1_cuba_kernel<<<dim3(16, 17), 256, SMD>>>(S3, W4T, S4);
    dense2_out_kernel<<<dim3(16, 11), 256>>>(S4, W5, out);
}

// round 5
// speedup vs baseline: 1.4523x; 1.0310x over previous
#include <cuda_runtime.h>
#include <cstdint>

typedef unsigned long long u64;

// ---------------------------------------------------------------------------
// Dimensions
// x: (16,2,128,128,64) -> conv1 (8,2,5,5) s4 p1 -> (16,8,32,32,T)
// -> conv2 (32,8,5,5) -> (16,32,8,8,T) -> conv3 (64,32,5,5) -> (16,64,2,2,T)
// -> dense1 256->2056 -> dense2 2056->11 -> out (16,11,64)
// ---------------------------------------------------------------------------

// float pool offsets
#define W1_OFF   0              // 8*50
#define W2_OFF   400            // 32*200
#define W3_OFF   6800           // 64*800
#define W4T_OFF  58000          // 256 * 2304 (transposed, padded rows)
#define W5_OFF   647824         // 11*2056
#define FBUF_TOTAL 670440

#define W4T_STRIDE 2304

// u64 pool offsets
#define XP_OFF 0                // 16*2*128*128
#define S1_OFF 524288           // 16*8*32*32
#define S2_OFF 655360           // 16*32*8*8
#define S3_OFF 688128           // 16*256
#define S4_OFF 692224           // 16*2056
#define UBUF_TOTAL 725120

__device__ float g_fbuf[FBUF_TOTAL];
__device__ u64   g_ubuf[UBUF_TOTAL];

// ---------------------------------------------------------------------------
// f32x2 packed-FMA helpers (two exact IEEE fp32 lanes -> bit-identical z)
// ---------------------------------------------------------------------------
__device__ __forceinline__ void ffma2(u64& d, u64 a, u64 b)
{
    asm("fma.rn.f32x2 %0, %1, %2, %0;" : "+l"(d) : "l"(a), "l"(b));
}
#define ONE2 0x3F8000003F800000ULL
__device__ __forceinline__ u64 bit2f2(unsigned int word, int t)
{
    return ((word >> t) & 1u) ? ONE2 : 0ULL;
}
__device__ __forceinline__ void unpack2(u64 p, float& lo, float& hi)
{
    unsigned int l_, h_;
    asm("mov.b64 {%0,%1}, %2;" : "=r"(l_), "=r"(h_) : "l"(p));
    lo = __uint_as_float(l_);
    hi = __uint_as_float(h_);
}

// ---------------------------------------------------------------------------
// Fused weight_norm for all 5 layers. dense1 written TRANSPOSED (padded rows).
// ---------------------------------------------------------------------------
__global__ void wnorm_all_kernel(const float* __restrict__ c1v, const float* __restrict__ c1g,
                                 const float* __restrict__ c2v, const float* __restrict__ c2g,
                                 const float* __restrict__ c3v, const float* __restrict__ c3g,
                                 const float* __restrict__ d1v, const float* __restrict__ d1g,
                                 const float* __restrict__ d2v, const float* __restrict__ d2g)
{
    int blk = blockIdx.x;
    int tid = threadIdx.x;
    const float* v; const float* g; float* w; int cols; int r; int trans = 0;
    if (blk < 8)          { v = c1v; g = c1g; w = g_fbuf + W1_OFF;  cols = 50;   r = blk; }
    else if (blk < 40)    { v = c2v; g = c2g; w = g_fbuf + W2_OFF;  cols = 200;  r = blk - 8; }
    else if (blk < 104)   { v = c3v; g = c3g; w = g_fbuf + W3_OFF;  cols = 800;  r = blk - 40; }
    else if (blk < 2160)  { v = d1v; g = d1g; w = g_fbuf + W4T_OFF; cols = 256;  r = blk - 104; trans = 1; }
    else                  { v = d2v; g = d2g; w = g_fbuf + W5_OFF;  cols = 2056; r = blk - 2160; }

    __shared__ float red[256];
    float s = 0.0f;
    for (int i = tid; i < cols; i += 256) {
        float a = v[(size_t)r * cols + i];
        s += a * a;
    }
    red[tid] = s;
    __syncthreads();
    for (int off = 128; off > 0; off >>= 1) {
        if (tid < off) red[tid] += red[tid + off];
        __syncthreads();
    }
    float n = sqrtf(red[0]);
    float gr = g[r];
    if (!trans) {
        for (int i = tid; i < cols; i += 256)
            w[(size_t)r * cols + i] = gr * v[(size_t)r * cols + i] / n;
    } else {
        for (int i = tid; i < cols; i += 256)
            w[(size_t)i * W4T_STRIDE + r] = gr * v[(size_t)r * cols + i] / n;
    }
}

// ---------------------------------------------------------------------------
// Pack input spikes, coalesced (smem nibble transpose).
// ---------------------------------------------------------------------------
__global__ void __launch_bounds__(256)
pack_kernel(const float* __restrict__ x, u64* __restrict__ xp)
{
    __shared__ unsigned int nsm[256 * 17];
    int tid = threadIdx.x;
    const float4* xg = (const float4*)x + (size_t)blockIdx.x * 4096;
    #pragma unroll
    for (int j = 0; j < 16; ++j) {
        float4 f = xg[j * 256 + tid];
        unsigned int v = (f.x > 0.5f ? 1u : 0u) | (f.y > 0.5f ? 2u : 0u)
                       | (f.z > 0.5f ? 4u : 0u) | (f.w > 0.5f ? 8u : 0u);
        int pl  = j * 16 + (tid >> 4);
        int nib = tid & 15;
        nsm[pl * 17 + nib] = v;
    }
    __syncthreads();
    u64 m = 0;
    #pragma unroll
    for (int k = 0; k < 16; ++k)
        m |= (u64)nsm[tid * 17 + k] << (4 * k);
    xp[(size_t)blockIdx.x * 256 + tid] = m;
}

// ---------------------------------------------------------------------------
// conv1: 2->8, in 128x128, out 32x32. Grid (16 b, 32 y, 2 xh) = 1024 blocks.
// Input halo tile staged to smem (zero-padded) -> inner loop is LDS-only.
// 256 thr = 16 tq x 16 px; thread tile 8o x 4t = 32 FMA per word.
// ---------------------------------------------------------------------------
__global__ void __launch_bounds__(256, 4)
conv1_kernel(const u64* __restrict__ xp, const float* __restrict__ wn,
             u64* __restrict__ sp)
{
    __shared__ u64 tile[2][5][65];                 // 5200 B, zero-padded halo
    __shared__ __align__(16) float wsm[400];       // [50 taps][8 o]
    __shared__ float zsm[128 * 65];                // 128 neurons

    const int b = blockIdx.x, y = blockIdx.y, xh = blockIdx.z;
    const int tid = threadIdx.x;
    const int tq = tid & 15, pxl = tid >> 4;

    for (int idx = tid; idx < 400; idx += 256)
        wsm[idx] = wn[(idx & 7) * 50 + (idx >> 3)];
    for (int idx = tid; idx < 650; idx += 256) {
        int c = idx / 325, rem = idx % 325;
        int r = rem / 65, col = rem % 65;
        int gy = 4 * y - 1 + r;
        int gx = xh * 64 - 1 + col;
        u64 v = 0ULL;
        if (gy >= 0 && gx >= 0)
            v = xp[(((size_t)b * 2 + c) << 14) + ((size_t)gy << 7) + gx];
        tile[c][r][col] = v;
    }
    __syncthreads();

    u64 acc[4][4];   // [opair][k(t)]
    #pragma unroll
    for (int j = 0; j < 4; ++j)
        #pragma unroll
        for (int k = 0; k < 4; ++k) acc[j][k] = 0ULL;

    #pragma unroll
    for (int c = 0; c < 2; ++c) {
        #pragma unroll 1
        for (int ky = 0; ky < 5; ++ky) {
            #pragma unroll
            for (int kx = 0; kx < 5; ++kx) {
                u64 word = tile[c][ky][pxl * 4 + kx];
                unsigned int lo = (unsigned int)word;
                unsigned int hi = (unsigned int)(word >> 32);
                u64 fd[4];
                fd[0] = bit2f2(lo, tq);
                fd[1] = bit2f2(lo, tq + 16);
                fd[2] = bit2f2(hi, tq);
                fd[3] = bit2f2(hi, tq + 16);
                const ulonglong2* wp =
                    (const ulonglong2*)(wsm + (c * 25 + ky * 5 + kx) * 8);
                ulonglong2 wA = wp[0];
                ulonglong2 wB = wp[1];
                u64 wpair[4] = {wA.x, wA.y, wB.x, wB.y};
                #pragma unroll
                for (int k = 0; k < 4; ++k)
                    #pragma unroll
                    for (int j = 0; j < 4; ++j)
                        ffma2(acc[j][k], wpair[j], fd[k]);
            }
        }
    }

    #pragma unroll
    for (int j = 0; j < 4; ++j)
        #pragma unroll
        for (int k = 0; k < 4; ++k) {
            float lo, hi;
            unpack2(acc[j][k], lo, hi);
            zsm[((2 * j)     * 16 + pxl) * 65 + tq + 16 * k] = lo;
            zsm[((2 * j + 1) * 16 + pxl) * 65 + tq + 16 * k] = hi;
        }
    __syncthreads();

    if (tid < 128) {   // CUBA: neuron = (o, pxl)
        int o = tid >> 4, p = tid & 15;
        float cc = 0.0f, vv = 0.0f;
        u64 m = 0;
        #pragma unroll 1
        for (int tt = 0; tt < 64; ++tt) {
            float z = zsm[tid * 65 + tt];
            cc = 0.7f * cc + z;
            vv = 0.75f * vv + cc;
            if (vv >= 1.0f) { m |= (1ULL << tt); vv = 0.0f; }
        }
        sp[(((size_t)b * 8 + o) * 32 + y) * 32 + xh * 16 + p] = m;
    }
}

// ---------------------------------------------------------------------------
// conv2: 8->32, in 32x32, out 8x8. Grid (16 b, 16 st, 2 og) = 512 blocks,
// 512 threads (occ ~75%). Input halo staged to smem; warp-uniform zero skip.
// thr = 64t x 4 pos x 2 osub; tile 8o x 1t.
// ---------------------------------------------------------------------------
__global__ void __launch_bounds__(512, 3)
conv2_kernel(const u64* __restrict__ s1, const float* __restrict__ wn,
             u64* __restrict__ sp)
{
    __shared__ u64 tile[8][5][17];                 // 5440 B, zero-padded
    __shared__ __align__(16) float wsm[200 * 16];  // [tap][16 o]
    __shared__ float zsm[64 * 65];                 // 64 neurons

    const int b = blockIdx.x, st = blockIdx.y, og = blockIdx.z;
    const int tid = threadIdx.x;
    const int t = tid & 63;
    const int pq = (tid >> 6) & 3;
    const int osub = tid >> 8;
    const int y = st >> 1, x0 = (st & 1) * 4;
    const int shift = t & 32, tb = t & 31;

    for (int idx = tid; idx < 3200; idx += 512)
        wsm[idx] = wn[(og * 16 + (idx & 15)) * 200 + (idx >> 4)];
    for (int idx = tid; idx < 680; idx += 512) {
        int c = idx / 85, rem = idx % 85;
        int r = rem / 17, col = rem % 17;
        int gy = 4 * y - 1 + r;
        int gx = x0 * 4 - 1 + col;
        u64 v = 0ULL;
        if (gy >= 0 && gx >= 0)
            v = s1[(((size_t)b * 8 + c) << 10) + ((size_t)gy << 5) + gx];
        tile[c][r][col] = v;
    }
    __syncthreads();

    u64 acc[4];
    #pragma unroll
    for (int j = 0; j < 4; ++j) acc[j] = 0ULL;

    #pragma unroll 1
    for (int c = 0; c < 8; ++c) {
        #pragma unroll 1
        for (int ky = 0; ky < 5; ++ky) {
            #pragma unroll
            for (int kx = 0; kx < 5; ++kx) {
                u64 word = tile[c][ky][pq * 4 + kx];
                if (word) {   // warp-uniform skip
                    unsigned int half = (unsigned int)(word >> shift);
                    u64 f = bit2f2(half, tb);
                    const ulonglong2* wp =
                        (const ulonglong2*)(wsm + (c * 25 + ky * 5 + kx) * 16 + osub * 8);
                    ulonglong2 w0 = wp[0], w1 = wp[1];
                    ffma2(acc[0], w0.x, f);
                    ffma2(acc[1], w0.y, f);
                    ffma2(acc[2], w1.x, f);
                    ffma2(acc[3], w1.y, f);
                }
            }
        }
    }

    #pragma unroll
    for (int j = 0; j < 4; ++j) {
        float lo, hi;
        unpack2(acc[j], lo, hi);
        zsm[((osub * 8 + 2 * j)     * 4 + pq) * 65 + t] = lo;
        zsm[((osub * 8 + 2 * j + 1) * 4 + pq) * 65 + t] = hi;
    }
    __syncthreads();

    if (tid < 64) {   // CUBA
        int o_loc = tid >> 2, p = tid & 3;
        float cc = 0.0f, vv = 0.0f;
        u64 m = 0;
        #pragma unroll 1
        for (int tt = 0; tt < 64; ++tt) {
            float z = zsm[tid * 65 + tt];
            cc = 0.7f * cc + z;
            vv = 0.75f * vv + cc;
            if (vv >= 1.0f) { m |= (1ULL << tt); vv = 0.0f; }
        }
        int Pp = st * 4 + p;
        int yy = Pp >> 3, xx = Pp & 7;
        sp[(((size_t)b * 32 + og * 16 + o_loc) * 8 + yy) * 8 + xx] = m;
    }
}

// ---------------------------------------------------------------------------
// conv3: 32->64, in 8x8, out 2x2. Grid (16 b, 16 og of 4 o) = 256 blocks.
// Whole input image (16 KB) staged to smem; warp-uniform zero skip.
// ---------------------------------------------------------------------------
__global__ void __launch_bounds__(256, 4)
conv3_kernel(const u64* __restrict__ s2, const float* __restrict__ wn,
             u64* __restrict__ sp)
{
    __shared__ u64 tile[2048];                     // 16 KB: 32c x 8 x 8
    __shared__ __align__(16) float wsm[800 * 4];   // [tap][4 o]
    __shared__ float zsm[16 * 65];

    const int b = blockIdx.x, og = blockIdx.y;
    const int tid = threadIdx.x;
    const int t = tid & 63, pq = tid >> 6;
    const int y = pq >> 1, x = pq & 1;
    const int shift = t & 32, tb = t & 31;

    for (int idx = tid; idx < 3200; idx += 256)
        wsm[idx] = wn[(og * 4 + (idx & 3)) * 800 + (idx >> 2)];
    for (int idx = tid; idx < 2048; idx += 256)
        tile[idx] = s2[(size_t)b * 2048 + idx];
    __syncthreads();

    u64 acc[2] = {0ULL, 0ULL};

    #pragma unroll 1
    for (int c = 0; c < 32; ++c) {
        #pragma unroll 1
        for (int ky = 0; ky < 5; ++ky) {
            int iy = 4 * y - 1 + ky;
            if (iy < 0) continue;
            #pragma unroll
            for (int kx = 0; kx < 5; ++kx) {
                int ix = 4 * x - 1 + kx;
                u64 word = 0ULL;
                if (ix >= 0) word = tile[c * 64 + iy * 8 + ix];
                if (word) {
                    unsigned int half = (unsigned int)(word >> shift);
                    u64 f = bit2f2(half, tb);
                    ulonglong2 w01 =
                        *(const ulonglong2*)(wsm + (c * 25 + ky * 5 + kx) * 4);
                    ffma2(acc[0], w01.x, f);
                    ffma2(acc[1], w01.y, f);
                }
            }
        }
    }

    #pragma unroll
    for (int j = 0; j < 2; ++j) {
        float lo, hi;
        unpack2(acc[j], lo, hi);
        zsm[((2 * j)     * 4 + pq) * 65 + t] = lo;
        zsm[((2 * j + 1) * 4 + pq) * 65 + t] = hi;
    }
    __syncthreads();

    if (tid < 16) {
        int o = tid >> 2, p = tid & 3;
        float cc = 0.0f, vv = 0.0f;
        u64 m = 0;
        #pragma unroll 1
        for (int tt = 0; tt < 64; ++tt) {
            float z = zsm[tid * 65 + tt];
            cc = 0.7f * cc + z;
            vv = 0.75f * vv + cc;
            if (vv >= 1.0f) { m |= (1ULL << tt); vv = 0.0f; }
        }
        sp[(size_t)b * 256 + (og * 4 + o) * 4 + p] = m;
    }
}

// ---------------------------------------------------------------------------
// dense1: 256->2056 + CUBA. Grid (16 b, 33 og of 64 o) = 528 blocks.
// 256 thr = 32 tq x 8 oq; tile 8o (4 pairs) x 2t. Block-uniform zero skip.
// ---------------------------------------------------------------------------
__global__ void __launch_bounds__(256, 4)
dense1_cuba_kernel(const u64* __restrict__ s3,
                   const float* __restrict__ w4t,
                   u64* __restrict__ s4)
{
    __shared__ u64 words[256];                     // 2 KB
    __shared__ __align__(16) float wsm[64 * 64];   // 16 KB: [i][64 o]
    __shared__ float zsm[64 * 65];                 // 16.6 KB

    const int b = blockIdx.x, og = blockIdx.y;
    const int tid = threadIdx.x;
    const int tq = tid & 31, oq = tid >> 5;

    words[tid] = s3[b * 256 + tid];

    u64 acc[4][2];
    #pragma unroll
    for (int j = 0; j < 4; ++j) { acc[j][0] = 0ULL; acc[j][1] = 0ULL; }

    #pragma unroll 1
    for (int q = 0; q < 4; ++q) {
        __syncthreads();
        #pragma unroll
        for (int r = 0; r < 4; ++r) {
            int f4 = r * 256 + tid;           // 0..1023
            int ii = f4 >> 4;                 // 0..63
            int o4 = (f4 & 15) * 4;           // 0..60
            *(float4*)(wsm + ii * 64 + o4) =
                *(const float4*)(w4t + (size_t)(q * 64 + ii) * W4T_STRIDE + og * 64 + o4);
        }
        __syncthreads();

        #pragma unroll 2
        for (int ii = 0; ii < 64; ++ii) {
            u64 wd = words[q * 64 + ii];
            if (wd == 0ULL) continue;          // block-uniform, exact skip
            u64 f0 = bit2f2((unsigned int)wd, tq);
            u64 f1 = bit2f2((unsigned int)(wd >> 32), tq);
            const ulonglong2* wp = (const ulonglong2*)(wsm + ii * 64 + oq * 8);
            ulonglong2 w0 = wp[0], w1 = wp[1];
            u64 wpair[4] = {w0.x, w0.y, w1.x, w1.y};
            #pragma unroll
            for (int j = 0; j < 4; ++j) {
                ffma2(acc[j][0], wpair[j], f0);
                ffma2(acc[j][1], wpair[j], f1);
            }
        }
    }

    #pragma unroll
    for (int j = 0; j < 4; ++j)
        #pragma unroll
        for (int k = 0; k < 2; ++k) {
            float lo, hi;
            unpack2(acc[j][k], lo, hi);
            zsm[(oq * 8 + 2 * j)     * 65 + tq + 32 * k] = lo;
            zsm[(oq * 8 + 2 * j + 1) * 65 + tq + 32 * k] = hi;
        }
    __syncthreads();

    if (tid < 64) {
        int o_g = og * 64 + tid;
        float cc = 0.0f, vv = 0.0f;
        u64 m = 0;
        #pragma unroll 1
        for (int tt = 0; tt < 64; ++tt) {
            float z = zsm[tid * 65 + tt];
            cc = 0.7f * cc + z;
            vv = 0.75f * vv + cc;
            if (vv >= 1.0f) { m |= (1ULL << tt); vv = 0.0f; }
        }
        if (o_g < 2056) s4[b * 2056 + o_g] = m;
    }
}

// ---------------------------------------------------------------------------
// dense2 (2056->11) + final CUBA + float output. Grid (16 b, 11 o).
// ---------------------------------------------------------------------------
__global__ void __launch_bounds__(256)
dense2_out_kernel(const u64* __restrict__ s4, const float* __restrict__ w5,
                  float* __restrict__ out)
{
    __shared__ float part[4][64];
    __shared__ float zrow[64];
    __shared__ u64 spk;

    const int b = blockIdx.x, o = blockIdx.y;
    const int tid = threadIdx.x;
    const int t = tid & 63, q = tid >> 6;

    float s = 0.0f;
    const u64*   wp = s4 + b * 2056;
    const float* vp = w5 + (size_t)o * 2056;
    for (int i = q * 514; i < q * 514 + 514; ++i) {
        float wt = vp[i];
        if ((wp[i] >> t) & 1ULL) s += wt;
    }
    part[q][t] = s;
    __syncthreads();
    if (tid < 64)
        zrow[tid] = part[0][tid] + part[1][tid] + part[2][tid] + part[3][tid];
    __syncthreads();
    if (tid == 0) {
        float cc = 0.0f, vv = 0.0f;
        u64 m = 0;
        #pragma unroll 1
        for (int tt = 0; tt < 64; ++tt) {
            cc = 0.7f * cc + zrow[tt];
            vv = 0.75f * vv + cc;
            if (vv >= 1.0f) { m |= (1ULL << tt); vv = 0.0f; }
        }
        spk = m;
    }
    __syncthreads();
    if (tid < 64)
        out[((size_t)b * 11 + o) * 64 + tid] = (float)((spk >> tid) & 1ULL);
}

// ---------------------------------------------------------------------------
// launch
// ---------------------------------------------------------------------------
extern "C" void kernel_launch(void* const* d_in, const int* in_sizes, int n_in,
                              void* d_out, int out_size)
{
    const float* x   = (const float*)d_in[0];
    const float* c1v = (const float*)d_in[1];
    const float* c1g = (const float*)d_in[2];
    const float* c2v = (const float*)d_in[3];
    const float* c2g = (const float*)d_in[4];
    const float* c3v = (const float*)d_in[5];
    const float* c3g = (const float*)d_in[6];
    const float* d1v = (const float*)d_in[7];
    const float* d1g = (const float*)d_in[8];
    const float* d2v = (const float*)d_in[9];
    const float* d2g = (const float*)d_in[10];
    float* out = (float*)d_out;

    void* fp = nullptr; void* up = nullptr;
    cudaGetSymbolAddress(&fp, g_fbuf);
    cudaGetSymbolAddress(&up, g_ubuf);
    float* F = (float*)fp;
    u64*   U = (u64*)up;

    float* W1  = F + W1_OFF;
    float* W2  = F + W2_OFF;
    float* W3  = F + W3_OFF;
    float* W4T = F + W4T_OFF;
    float* W5  = F + W5_OFF;
    u64* XP = U + XP_OFF;  u64* S1 = U + S1_OFF;  u64* S2 = U + S2_OFF;
    u64* S3 = U + S3_OFF;  u64* S4 = U + S4_OFF;

    wnorm_all_kernel<<<2171, 256>>>(c1v, c1g, c2v, c2g, c3v, c3g,
                                    d1v, d1g, d2v, d2g);
    pack_kernel<<<2048, 256>>>(x, XP);

    conv1_kernel<<<dim3(16, 32, 2), 256>>>(XP, W1, S1);
    conv2_kernel<<<dim3(16, 16, 2), 512>>>(S1, W2, S2);
    conv3_kernel<<<dim3(16, 16), 256>>>(S2, W3, S3);

    dense1_cuba_kernel<<<dim3(16, 33), 256>>>(S3, W4T, S4);
    dense2_out_kernel<<<dim3(16, 11), 256>>>(S4, W5, out);
}

// round 6
// speedup vs baseline: 1.6091x; 1.1079x over previous
#include <cuda_runtime.h>
#include <cstdint>

typedef unsigned long long u64;

// ---------------------------------------------------------------------------
// Dimensions
// x: (16,2,128,128,64) -> conv1 (8,2,5,5) s4 p1 -> (16,8,32,32,T)
// -> conv2 (32,8,5,5) -> (16,32,8,8,T) -> conv3 (64,32,5,5) -> (16,64,2,2,T)
// -> dense1 256->2056 -> dense2 2056->11 -> out (16,11,64)
// ---------------------------------------------------------------------------

// float pool offsets
#define W1_OFF   0              // 8*50
#define W2_OFF   400            // 32*200
#define W3_OFF   6800           // 64*800
#define W4T_OFF  58000          // 256 * 2304 (transposed, padded rows)
#define W5_OFF   647824         // 11*2056
#define FBUF_TOTAL 670440

#define W4T_STRIDE 2304

// u64 pool offsets
#define XP_OFF 0                // 16*2*128*128
#define S1_OFF 524288           // 16*8*32*32
#define S2_OFF 655360           // 16*32*8*8
#define S3_OFF 688128           // 16*256
#define S4_OFF 692224           // 16*2056
#define UBUF_TOTAL 725120

__device__ float g_fbuf[FBUF_TOTAL];
__device__ u64   g_ubuf[UBUF_TOTAL];

// ---------------------------------------------------------------------------
// f32x2 packed-FMA helpers (two exact IEEE fp32 lanes -> bit-identical z)
// ---------------------------------------------------------------------------
__device__ __forceinline__ void ffma2(u64& d, u64 a, u64 b)
{
    asm("fma.rn.f32x2 %0, %1, %2, %0;" : "+l"(d) : "l"(a), "l"(b));
}
#define ONE2 0x3F8000003F800000ULL
__device__ __forceinline__ u64 bit2f2(unsigned int word, int t)
{
    return ((word >> t) & 1u) ? ONE2 : 0ULL;
}
__device__ __forceinline__ void unpack2(u64 p, float& lo, float& hi)
{
    unsigned int l_, h_;
    asm("mov.b64 {%0,%1}, %2;" : "=r"(l_), "=r"(h_) : "l"(p));
    lo = __uint_as_float(l_);
    hi = __uint_as_float(h_);
}

// ---------------------------------------------------------------------------
// Fused weight_norm for all 5 layers. dense1 written TRANSPOSED (padded rows).
// ---------------------------------------------------------------------------
__global__ void wnorm_all_kernel(const float* __restrict__ c1v, const float* __restrict__ c1g,
                                 const float* __restrict__ c2v, const float* __restrict__ c2g,
                                 const float* __restrict__ c3v, const float* __restrict__ c3g,
                                 const float* __restrict__ d1v, const float* __restrict__ d1g,
                                 const float* __restrict__ d2v, const float* __restrict__ d2g)
{
    int blk = blockIdx.x;
    int tid = threadIdx.x;
    const float* v; const float* g; float* w; int cols; int r; int trans = 0;
    if (blk < 8)          { v = c1v; g = c1g; w = g_fbuf + W1_OFF;  cols = 50;   r = blk; }
    else if (blk < 40)    { v = c2v; g = c2g; w = g_fbuf + W2_OFF;  cols = 200;  r = blk - 8; }
    else if (blk < 104)   { v = c3v; g = c3g; w = g_fbuf + W3_OFF;  cols = 800;  r = blk - 40; }
    else if (blk < 2160)  { v = d1v; g = d1g; w = g_fbuf + W4T_OFF; cols = 256;  r = blk - 104; trans = 1; }
    else                  { v = d2v; g = d2g; w = g_fbuf + W5_OFF;  cols = 2056; r = blk - 2160; }

    __shared__ float red[256];
    float s = 0.0f;
    for (int i = tid; i < cols; i += 256) {
        float a = v[(size_t)r * cols + i];
        s += a * a;
    }
    red[tid] = s;
    __syncthreads();
    for (int off = 128; off > 0; off >>= 1) {
        if (tid < off) red[tid] += red[tid + off];
        __syncthreads();
    }
    float n = sqrtf(red[0]);
    float gr = g[r];
    if (!trans) {
        for (int i = tid; i < cols; i += 256)
            w[(size_t)r * cols + i] = gr * v[(size_t)r * cols + i] / n;
    } else {
        for (int i = tid; i < cols; i += 256)
            w[(size_t)i * W4T_STRIDE + r] = gr * v[(size_t)r * cols + i] / n;
    }
}

// ---------------------------------------------------------------------------
// Pack input spikes, coalesced (smem nibble transpose).
// ---------------------------------------------------------------------------
__global__ void __launch_bounds__(256)
pack_kernel(const float* __restrict__ x, u64* __restrict__ xp)
{
    __shared__ unsigned int nsm[256 * 17];
    int tid = threadIdx.x;
    const float4* xg = (const float4*)x + (size_t)blockIdx.x * 4096;
    #pragma unroll
    for (int j = 0; j < 16; ++j) {
        float4 f = xg[j * 256 + tid];
        unsigned int v = (f.x > 0.5f ? 1u : 0u) | (f.y > 0.5f ? 2u : 0u)
                       | (f.z > 0.5f ? 4u : 0u) | (f.w > 0.5f ? 8u : 0u);
        int pl  = j * 16 + (tid >> 4);
        int nib = tid & 15;
        nsm[pl * 17 + nib] = v;
    }
    __syncthreads();
    u64 m = 0;
    #pragma unroll
    for (int k = 0; k < 16; ++k)
        m |= (u64)nsm[tid * 17 + k] << (4 * k);
    xp[(size_t)blockIdx.x * 256 + tid] = m;
}

// ---------------------------------------------------------------------------
// conv1: 2->8, in 128x128, out 32x32. Grid (16 b, 32 y, 2 xh) = 1024 blocks.
// Input halo tile staged to smem (zero-padded) -> inner loop is LDS-only.
// 256 thr = 16 tq x 16 px; thread tile 8o x 4t = 16 FFMA2 per word.
// ---------------------------------------------------------------------------
__global__ void __launch_bounds__(256, 4)
conv1_kernel(const u64* __restrict__ xp, const float* __restrict__ wn,
             u64* __restrict__ sp)
{
    __shared__ u64 tile[2][5][65];                 // 5200 B, zero-padded halo
    __shared__ __align__(16) float wsm[400];       // [50 taps][8 o]
    __shared__ float zsm[128 * 65];                // 128 neurons

    const int b = blockIdx.x, y = blockIdx.y, xh = blockIdx.z;
    const int tid = threadIdx.x;
    const int tq = tid & 15, pxl = tid >> 4;

    for (int idx = tid; idx < 400; idx += 256)
        wsm[idx] = wn[(idx & 7) * 50 + (idx >> 3)];
    for (int idx = tid; idx < 650; idx += 256) {
        int c = idx / 325, rem = idx % 325;
        int r = rem / 65, col = rem % 65;
        int gy = 4 * y - 1 + r;
        int gx = xh * 64 - 1 + col;
        u64 v = 0ULL;
        if (gy >= 0 && gx >= 0)
            v = xp[(((size_t)b * 2 + c) << 14) + ((size_t)gy << 7) + gx];
        tile[c][r][col] = v;
    }
    __syncthreads();

    u64 acc[4][4];   // [opair][k(t)]
    #pragma unroll
    for (int j = 0; j < 4; ++j)
        #pragma unroll
        for (int k = 0; k < 4; ++k) acc[j][k] = 0ULL;

    #pragma unroll
    for (int c = 0; c < 2; ++c) {
        #pragma unroll 1
        for (int ky = 0; ky < 5; ++ky) {
            #pragma unroll
            for (int kx = 0; kx < 5; ++kx) {
                u64 word = tile[c][ky][pxl * 4 + kx];
                unsigned int lo = (unsigned int)word;
                unsigned int hi = (unsigned int)(word >> 32);
                u64 fd[4];
                fd[0] = bit2f2(lo, tq);
                fd[1] = bit2f2(lo, tq + 16);
                fd[2] = bit2f2(hi, tq);
                fd[3] = bit2f2(hi, tq + 16);
                const ulonglong2* wp =
                    (const ulonglong2*)(wsm + (c * 25 + ky * 5 + kx) * 8);
                ulonglong2 wA = wp[0];
                ulonglong2 wB = wp[1];
                u64 wpair[4] = {wA.x, wA.y, wB.x, wB.y};
                #pragma unroll
                for (int k = 0; k < 4; ++k)
                    #pragma unroll
                    for (int j = 0; j < 4; ++j)
                        ffma2(acc[j][k], wpair[j], fd[k]);
            }
        }
    }

    #pragma unroll
    for (int j = 0; j < 4; ++j)
        #pragma unroll
        for (int k = 0; k < 4; ++k) {
            float lo, hi;
            unpack2(acc[j][k], lo, hi);
            zsm[((2 * j)     * 16 + pxl) * 65 + tq + 16 * k] = lo;
            zsm[((2 * j + 1) * 16 + pxl) * 65 + tq + 16 * k] = hi;
        }
    __syncthreads();

    if (tid < 128) {   // CUBA: neuron = (o, pxl)
        int o = tid >> 4, p = tid & 15;
        float cc = 0.0f, vv = 0.0f;
        u64 m = 0;
        #pragma unroll 1
        for (int tt = 0; tt < 64; ++tt) {
            float z = zsm[tid * 65 + tt];
            cc = 0.7f * cc + z;
            vv = 0.75f * vv + cc;
            if (vv >= 1.0f) { m |= (1ULL << tt); vv = 0.0f; }
        }
        sp[(((size_t)b * 8 + o) * 32 + y) * 32 + xh * 16 + p] = m;
    }
}

// ---------------------------------------------------------------------------
// conv2: 8->32, in 32x32, out 8x8. Grid (16 b, 8 yrow, 4 og of 8o) = 512
// blocks x 128 thr. Input halo (one output row) staged to smem.
// 128 thr = 16 tq x 8 x-positions; thread tile 8o x 4t = 16 FFMA2 per word.
// No zero-branch (words are dense in time).
// ---------------------------------------------------------------------------
__global__ void __launch_bounds__(128, 6)
conv2_kernel(const u64* __restrict__ s1, const float* __restrict__ wn,
             u64* __restrict__ sp)
{
    __shared__ u64 tile[8][5][33];                 // 10560 B, zero-padded halo
    __shared__ __align__(16) float wsm[1600];      // [200 taps][8 o]
    __shared__ float zsm[64 * 65];                 // 64 neurons

    const int b = blockIdx.x, yq = blockIdx.y, og = blockIdx.z;
    const int tid = threadIdx.x;
    const int tq = tid & 15, px = tid >> 4;        // px = output x, 0..7

    for (int idx = tid; idx < 1600; idx += 128)
        wsm[idx] = wn[(og * 8 + (idx & 7)) * 200 + (idx >> 3)];
    for (int idx = tid; idx < 1320; idx += 128) {
        int c = idx / 165, rem = idx % 165;
        int r = rem / 33, col = rem % 33;
        int gy = 4 * yq - 1 + r;
        int gx = col - 1;
        u64 v = 0ULL;
        if (gy >= 0 && gx >= 0)
            v = s1[(((size_t)b * 8 + c) << 10) + ((size_t)gy << 5) + gx];
        tile[c][r][col] = v;
    }
    __syncthreads();

    u64 acc[4][4];   // [opair][k(t)]
    #pragma unroll
    for (int j = 0; j < 4; ++j)
        #pragma unroll
        for (int k = 0; k < 4; ++k) acc[j][k] = 0ULL;

    #pragma unroll 1
    for (int c = 0; c < 8; ++c) {
        #pragma unroll 1
        for (int ky = 0; ky < 5; ++ky) {
            #pragma unroll
            for (int kx = 0; kx < 5; ++kx) {
                u64 word = tile[c][ky][px * 4 + kx];
                unsigned int lo = (unsigned int)word;
                unsigned int hi = (unsigned int)(word >> 32);
                u64 fd[4];
                fd[0] = bit2f2(lo, tq);
                fd[1] = bit2f2(lo, tq + 16);
                fd[2] = bit2f2(hi, tq);
                fd[3] = bit2f2(hi, tq + 16);
                const ulonglong2* wp =
                    (const ulonglong2*)(wsm + (c * 25 + ky * 5 + kx) * 8);
                ulonglong2 wA = wp[0];
                ulonglong2 wB = wp[1];
                u64 wpair[4] = {wA.x, wA.y, wB.x, wB.y};
                #pragma unroll
                for (int k = 0; k < 4; ++k)
                    #pragma unroll
                    for (int j = 0; j < 4; ++j)
                        ffma2(acc[j][k], wpair[j], fd[k]);
            }
        }
    }

    #pragma unroll
    for (int j = 0; j < 4; ++j)
        #pragma unroll
        for (int k = 0; k < 4; ++k) {
            float lo, hi;
            unpack2(acc[j][k], lo, hi);
            zsm[((2 * j)     * 8 + px) * 65 + tq + 16 * k] = lo;
            zsm[((2 * j + 1) * 8 + px) * 65 + tq + 16 * k] = hi;
        }
    __syncthreads();

    if (tid < 64) {   // CUBA: neuron = (o_local, px)
        int o_loc = tid >> 3, p = tid & 7;
        float cc = 0.0f, vv = 0.0f;
        u64 m = 0;
        #pragma unroll 1
        for (int tt = 0; tt < 64; ++tt) {
            float z = zsm[tid * 65 + tt];
            cc = 0.7f * cc + z;
            vv = 0.75f * vv + cc;
            if (vv >= 1.0f) { m |= (1ULL << tt); vv = 0.0f; }
        }
        sp[(((size_t)b * 32 + og * 8 + o_loc) * 8 + yq) * 8 + p] = m;
    }
}

// ---------------------------------------------------------------------------
// conv3: 32->64, in 8x8, out 2x2. Grid (16 b, 16 og of 4 o) = 256 blocks.
// Whole input image (16 KB) staged to smem; warp-uniform zero skip.
// ---------------------------------------------------------------------------
__global__ void __launch_bounds__(256, 4)
conv3_kernel(const u64* __restrict__ s2, const float* __restrict__ wn,
             u64* __restrict__ sp)
{
    __shared__ u64 tile[2048];                     // 16 KB: 32c x 8 x 8
    __shared__ __align__(16) float wsm[800 * 4];   // [tap][4 o]
    __shared__ float zsm[16 * 65];

    const int b = blockIdx.x, og = blockIdx.y;
    const int tid = threadIdx.x;
    const int t = tid & 63, pq = tid >> 6;
    const int y = pq >> 1, x = pq & 1;
    const int shift = t & 32, tb = t & 31;

    for (int idx = tid; idx < 3200; idx += 256)
        wsm[idx] = wn[(og * 4 + (idx & 3)) * 800 + (idx >> 2)];
    for (int idx = tid; idx < 2048; idx += 256)
        tile[idx] = s2[(size_t)b * 2048 + idx];
    __syncthreads();

    u64 acc[2] = {0ULL, 0ULL};

    #pragma unroll 1
    for (int c = 0; c < 32; ++c) {
        #pragma unroll 1
        for (int ky = 0; ky < 5; ++ky) {
            int iy = 4 * y - 1 + ky;
            if (iy < 0) continue;
            #pragma unroll
            for (int kx = 0; kx < 5; ++kx) {
                int ix = 4 * x - 1 + kx;
                u64 word = 0ULL;
                if (ix >= 0) word = tile[c * 64 + iy * 8 + ix];
                if (word) {
                    unsigned int half = (unsigned int)(word >> shift);
                    u64 f = bit2f2(half, tb);
                    ulonglong2 w01 =
                        *(const ulonglong2*)(wsm + (c * 25 + ky * 5 + kx) * 4);
                    ffma2(acc[0], w01.x, f);
                    ffma2(acc[1], w01.y, f);
                }
            }
        }
    }

    #pragma unroll
    for (int j = 0; j < 2; ++j) {
        float lo, hi;
        unpack2(acc[j], lo, hi);
        zsm[((2 * j)     * 4 + pq) * 65 + t] = lo;
        zsm[((2 * j + 1) * 4 + pq) * 65 + t] = hi;
    }
    __syncthreads();

    if (tid < 16) {
        int o = tid >> 2, p = tid & 3;
        float cc = 0.0f, vv = 0.0f;
        u64 m = 0;
        #pragma unroll 1
        for (int tt = 0; tt < 64; ++tt) {
            float z = zsm[tid * 65 + tt];
            cc = 0.7f * cc + z;
            vv = 0.75f * vv + cc;
            if (vv >= 1.0f) { m |= (1ULL << tt); vv = 0.0f; }
        }
        sp[(size_t)b * 256 + (og * 4 + o) * 4 + p] = m;
    }
}

// ---------------------------------------------------------------------------
// dense1: 256->2056 + CUBA. Grid (16 b, 33 og of 64 o) = 528 blocks x 128 thr.
// 128 thr = 32 tq x 4 oq; thread tile 16o (8 pairs) x 2t = 16 FFMA2 per word.
// Block-uniform zero-word skip.
// ---------------------------------------------------------------------------
__global__ void __launch_bounds__(128, 6)
dense1_cuba_kernel(const u64* __restrict__ s3,
                   const float* __restrict__ w4t,
                   u64* __restrict__ s4)
{
    __shared__ u64 words[256];                     // 2 KB
    __shared__ __align__(16) float wsm[64 * 64];   // 16 KB: [i][64 o]
    __shared__ float zsm[64 * 65];                 // 16.6 KB

    const int b = blockIdx.x, og = blockIdx.y;
    const int tid = threadIdx.x;
    const int tq = tid & 31, oq = tid >> 5;        // oq 0..3, 16 o each

    words[tid]       = s3[b * 256 + tid];
    words[tid + 128] = s3[b * 256 + tid + 128];

    u64 acc[8][2];
    #pragma unroll
    for (int j = 0; j < 8; ++j) { acc[j][0] = 0ULL; acc[j][1] = 0ULL; }

    #pragma unroll 1
    for (int q = 0; q < 4; ++q) {
        __syncthreads();
        #pragma unroll
        for (int r = 0; r < 8; ++r) {
            int f4 = r * 128 + tid;           // 0..1023
            int ii = f4 >> 4;                 // 0..63
            int o4 = (f4 & 15) * 4;           // 0..60
            *(float4*)(wsm + ii * 64 + o4) =
                *(const float4*)(w4t + (size_t)(q * 64 + ii) * W4T_STRIDE + og * 64 + o4);
        }
        __syncthreads();

        #pragma unroll 2
        for (int ii = 0; ii < 64; ++ii) {
            u64 wd = words[q * 64 + ii];
            if (wd == 0ULL) continue;          // block-uniform, exact skip
            u64 f0 = bit2f2((unsigned int)wd, tq);
            u64 f1 = bit2f2((unsigned int)(wd >> 32), tq);
            const ulonglong2* wp = (const ulonglong2*)(wsm + ii * 64 + oq * 16);
            ulonglong2 w0 = wp[0], w1 = wp[1], w2 = wp[2], w3 = wp[3];
            u64 wpair[8] = {w0.x, w0.y, w1.x, w1.y, w2.x, w2.y, w3.x, w3.y};
            #pragma unroll
            for (int j = 0; j < 8; ++j) {
                ffma2(acc[j][0], wpair[j], f0);
                ffma2(acc[j][1], wpair[j], f1);
            }
        }
    }

    #pragma unroll
    for (int j = 0; j < 8; ++j)
        #pragma unroll
        for (int k = 0; k < 2; ++k) {
            float lo, hi;
            unpack2(acc[j][k], lo, hi);
            zsm[(oq * 16 + 2 * j)     * 65 + tq + 32 * k] = lo;
            zsm[(oq * 16 + 2 * j + 1) * 65 + tq + 32 * k] = hi;
        }
    __syncthreads();

    if (tid < 64) {
        int o_g = og * 64 + tid;
        float cc = 0.0f, vv = 0.0f;
        u64 m = 0;
        #pragma unroll 1
        for (int tt = 0; tt < 64; ++tt) {
            float z = zsm[tid * 65 + tt];
            cc = 0.7f * cc + z;
            vv = 0.75f * vv + cc;
            if (vv >= 1.0f) { m |= (1ULL << tt); vv = 0.0f; }
        }
        if (o_g < 2056) s4[b * 2056 + o_g] = m;
    }
}

// ---------------------------------------------------------------------------
// dense2 (2056->11) + final CUBA + float output. Grid (16 b, 11 o).
// ---------------------------------------------------------------------------
__global__ void __launch_bounds__(256)
dense2_out_kernel(const u64* __restrict__ s4, const float* __restrict__ w5,
                  float* __restrict__ out)
{
    __shared__ float part[4][64];
    __shared__ float zrow[64];
    __shared__ u64 spk;

    const int b = blockIdx.x, o = blockIdx.y;
    const int tid = threadIdx.x;
    const int t = tid & 63, q = tid >> 6;

    float s = 0.0f;
    const u64*   wp = s4 + b * 2056;
    const float* vp = w5 + (size_t)o * 2056;
    for (int i = q * 514; i < q * 514 + 514; ++i) {
        float wt = vp[i];
        if ((wp[i] >> t) & 1ULL) s += wt;
    }
    part[q][t] = s;
    __syncthreads();
    if (tid < 64)
        zrow[tid] = part[0][tid] + part[1][tid] + part[2][tid] + part[3][tid];
    __syncthreads();
    if (tid == 0) {
        float cc = 0.0f, vv = 0.0f;
        u64 m = 0;
        #pragma unroll 1
        for (int tt = 0; tt < 64; ++tt) {
            cc = 0.7f * cc + zrow[tt];
            vv = 0.75f * vv + cc;
            if (vv >= 1.0f) { m |= (1ULL << tt); vv = 0.0f; }
        }
        spk = m;
    }
    __syncthreads();
    if (tid < 64)
        out[((size_t)b * 11 + o) * 64 + tid] = (float)((spk >> tid) & 1ULL);
}

// ---------------------------------------------------------------------------
// launch
// ---------------------------------------------------------------------------
extern "C" void kernel_launch(void* const* d_in, const int* in_sizes, int n_in,
                              void* d_out, int out_size)
{
    const float* x   = (const float*)d_in[0];
    const float* c1v = (const float*)d_in[1];
    const float* c1g = (const float*)d_in[2];
    const float* c2v = (const float*)d_in[3];
    const float* c2g = (const float*)d_in[4];
    const float* c3v = (const float*)d_in[5];
    const float* c3g = (const float*)d_in[6];
    const float* d1v = (const float*)d_in[7];
    const float* d1g = (const float*)d_in[8];
    const float* d2v = (const float*)d_in[9];
    const float* d2g = (const float*)d_in[10];
    float* out = (float*)d_out;

    void* fp = nullptr; void* up = nullptr;
    cudaGetSymbolAddress(&fp, g_fbuf);
    cudaGetSymbolAddress(&up, g_ubuf);
    float* F = (float*)fp;
    u64*   U = (u64*)up;

    float* W1  = F + W1_OFF;
    float* W2  = F + W2_OFF;
    float* W3  = F + W3_OFF;
    float* W4T = F + W4T_OFF;
    float* W5  = F + W5_OFF;
    u64* XP = U + XP_OFF;  u64* S1 = U + S1_OFF;  u64* S2 = U + S2_OFF;
    u64* S3 = U + S3_OFF;  u64* S4 = U + S4_OFF;

    wnorm_all_kernel<<<2171, 256>>>(c1v, c1g, c2v, c2g, c3v, c3g,
                                    d1v, d1g, d2v, d2g);
    pack_kernel<<<2048, 256>>>(x, XP);

    conv1_kernel<<<dim3(16, 32, 2), 256>>>(XP, W1, S1);
    conv2_kernel<<<dim3(16, 8, 4), 128>>>(S1, W2, S2);
    conv3_kernel<<<dim3(16, 16), 256>>>(S2, W3, S3);

    dense1_cuba_kernel<<<dim3(16, 33), 128>>>(S3, W4T, S4);
    dense2_out_kernel<<<dim3(16, 11), 256>>>(S4, W5, out);
}

// round 7
// speedup vs baseline: 1.8038x; 1.1210x over previous
#include <cuda_runtime.h>
#include <cstdint>

typedef unsigned long long u64;

// ---------------------------------------------------------------------------
// Dimensions
// x: (16,2,128,128,64) -> conv1 (8,2,5,5) s4 p1 -> (16,8,32,32,T)
// -> conv2 (32,8,5,5) -> (16,32,8,8,T) -> conv3 (64,32,5,5) -> (16,64,2,2,T)
// -> dense1 256->2056 -> dense2 2056->11 -> out (16,11,64)
// ---------------------------------------------------------------------------

// float pool offsets
#define W1_OFF   0              // 8*50
#define W2_OFF   400            // 32*200
#define W3_OFF   6800           // 64*800
#define W4T_OFF  58000          // 256 * 2304 (transposed, padded rows)
#define W5_OFF   647824         // 11*2056
#define FBUF_TOTAL 670440

#define W4T_STRIDE 2304

// u64 pool offsets
#define XP_OFF 0                // 16*2*128*128
#define S1_OFF 524288           // 16*8*32*32
#define S2_OFF 655360           // 16*32*8*8
#define S3_OFF 688128           // 16*256
#define S4_OFF 692224           // 16*2056
#define UBUF_TOTAL 725120

__device__ float g_fbuf[FBUF_TOTAL];
__device__ u64   g_ubuf[UBUF_TOTAL];

// ---------------------------------------------------------------------------
// f32x2 packed-FMA helpers (two exact IEEE fp32 lanes -> bit-identical z)
// ---------------------------------------------------------------------------
__device__ __forceinline__ void ffma2(u64& d, u64 a, u64 b)
{
    asm("fma.rn.f32x2 %0, %1, %2, %0;" : "+l"(d) : "l"(a), "l"(b));
}
#define ONE2 0x3F8000003F800000ULL
__device__ __forceinline__ u64 bit2f2(unsigned int word, int t)
{
    return ((word >> t) & 1u) ? ONE2 : 0ULL;
}
__device__ __forceinline__ void unpack2(u64 p, float& lo, float& hi)
{
    unsigned int l_, h_;
    asm("mov.b64 {%0,%1}, %2;" : "=r"(l_), "=r"(h_) : "l"(p));
    lo = __uint_as_float(l_);
    hi = __uint_as_float(h_);
}

// ---------------------------------------------------------------------------
// Merged init kernel: blocks [0,2048) pack input spikes; blocks [2048,4219)
// run weight_norm for all 5 layers (dense1 transposed, padded rows).
// ---------------------------------------------------------------------------
__global__ void __launch_bounds__(256)
init_kernel(const float* __restrict__ x, u64* __restrict__ xp,
            const float* __restrict__ c1v, const float* __restrict__ c1g,
            const float* __restrict__ c2v, const float* __restrict__ c2g,
            const float* __restrict__ c3v, const float* __restrict__ c3g,
            const float* __restrict__ d1v, const float* __restrict__ d1g,
            const float* __restrict__ d2v, const float* __restrict__ d2g)
{
    __shared__ unsigned int nsm[256 * 17];
    const int tid = threadIdx.x;

    if (blockIdx.x < 2048) {
        // ---- pack: coalesced float4 loads -> nibble transpose -> u64 words
        const float4* xg = (const float4*)x + (size_t)blockIdx.x * 4096;
        #pragma unroll
        for (int j = 0; j < 16; ++j) {
            float4 f = xg[j * 256 + tid];
            unsigned int v = (f.x > 0.5f ? 1u : 0u) | (f.y > 0.5f ? 2u : 0u)
                           | (f.z > 0.5f ? 4u : 0u) | (f.w > 0.5f ? 8u : 0u);
            int pl  = j * 16 + (tid >> 4);
            int nib = tid & 15;
            nsm[pl * 17 + nib] = v;
        }
        __syncthreads();
        u64 m = 0;
        #pragma unroll
        for (int k = 0; k < 16; ++k)
            m |= (u64)nsm[tid * 17 + k] << (4 * k);
        xp[(size_t)blockIdx.x * 256 + tid] = m;
        return;
    }

    // ---- weight_norm
    int blk = blockIdx.x - 2048;
    const float* v; const float* g; float* w; int cols; int r; int trans = 0;
    if (blk < 8)          { v = c1v; g = c1g; w = g_fbuf + W1_OFF;  cols = 50;   r = blk; }
    else if (blk < 40)    { v = c2v; g = c2g; w = g_fbuf + W2_OFF;  cols = 200;  r = blk - 8; }
    else if (blk < 104)   { v = c3v; g = c3g; w = g_fbuf + W3_OFF;  cols = 800;  r = blk - 40; }
    else if (blk < 2160)  { v = d1v; g = d1g; w = g_fbuf + W4T_OFF; cols = 256;  r = blk - 104; trans = 1; }
    else                  { v = d2v; g = d2g; w = g_fbuf + W5_OFF;  cols = 2056; r = blk - 2160; }

    float* red = (float*)nsm;
    float s = 0.0f;
    for (int i = tid; i < cols; i += 256) {
        float a = v[(size_t)r * cols + i];
        s += a * a;
    }
    red[tid] = s;
    __syncthreads();
    for (int off = 128; off > 0; off >>= 1) {
        if (tid < off) red[tid] += red[tid + off];
        __syncthreads();
    }
    float n = sqrtf(red[0]);
    float gr = g[r];
    if (!trans) {
        for (int i = tid; i < cols; i += 256)
            w[(size_t)r * cols + i] = gr * v[(size_t)r * cols + i] / n;
    } else {
        for (int i = tid; i < cols; i += 256)
            w[(size_t)i * W4T_STRIDE + r] = gr * v[(size_t)r * cols + i] / n;
    }
}

// ---------------------------------------------------------------------------
// conv1: 2->8, in 128x128, out 32x32. Grid (16 b, 32 y, 2 xh) = 1024 blocks.
// Input halo tile staged to smem (zero-padded) -> inner loop is LDS-only.
// 256 thr = 16 tq x 16 px; thread tile 8o x 4t = 16 FFMA2 per word.
// ---------------------------------------------------------------------------
__global__ void __launch_bounds__(256, 3)
conv1_kernel(const u64* __restrict__ xp, const float* __restrict__ wn,
             u64* __restrict__ sp)
{
    __shared__ u64 tile[2][5][65];                 // 5200 B, zero-padded halo
    __shared__ __align__(16) float wsm[400];       // [50 taps][8 o]
    __shared__ float zsm[128 * 65];                // 128 neurons

    const int b = blockIdx.x, y = blockIdx.y, xh = blockIdx.z;
    const int tid = threadIdx.x;
    const int tq = tid & 15, pxl = tid >> 4;

    for (int idx = tid; idx < 400; idx += 256)
        wsm[idx] = wn[(idx & 7) * 50 + (idx >> 3)];
    for (int idx = tid; idx < 650; idx += 256) {
        int c = idx / 325, rem = idx % 325;
        int r = rem / 65, col = rem % 65;
        int gy = 4 * y - 1 + r;
        int gx = xh * 64 - 1 + col;
        u64 v = 0ULL;
        if (gy >= 0 && gx >= 0)
            v = xp[(((size_t)b * 2 + c) << 14) + ((size_t)gy << 7) + gx];
        tile[c][r][col] = v;
    }
    __syncthreads();

    u64 acc[4][4];   // [opair][k(t)]
    #pragma unroll
    for (int j = 0; j < 4; ++j)
        #pragma unroll
        for (int k = 0; k < 4; ++k) acc[j][k] = 0ULL;

    #pragma unroll
    for (int c = 0; c < 2; ++c) {
        #pragma unroll 1
        for (int ky = 0; ky < 5; ++ky) {
            #pragma unroll
            for (int kx = 0; kx < 5; ++kx) {
                u64 word = tile[c][ky][pxl * 4 + kx];
                unsigned int lo = (unsigned int)word;
                unsigned int hi = (unsigned int)(word >> 32);
                u64 fd[4];
                fd[0] = bit2f2(lo, tq);
                fd[1] = bit2f2(lo, tq + 16);
                fd[2] = bit2f2(hi, tq);
                fd[3] = bit2f2(hi, tq + 16);
                const ulonglong2* wp =
                    (const ulonglong2*)(wsm + (c * 25 + ky * 5 + kx) * 8);
                ulonglong2 wA = wp[0];
                ulonglong2 wB = wp[1];
                u64 wpair[4] = {wA.x, wA.y, wB.x, wB.y};
                #pragma unroll
                for (int k = 0; k < 4; ++k)
                    #pragma unroll
                    for (int j = 0; j < 4; ++j)
                        ffma2(acc[j][k], wpair[j], fd[k]);
            }
        }
    }

    #pragma unroll
    for (int j = 0; j < 4; ++j)
        #pragma unroll
        for (int k = 0; k < 4; ++k) {
            float lo, hi;
            unpack2(acc[j][k], lo, hi);
            zsm[((2 * j)     * 16 + pxl) * 65 + tq + 16 * k] = lo;
            zsm[((2 * j + 1) * 16 + pxl) * 65 + tq + 16 * k] = hi;
        }
    __syncthreads();

    if (tid < 128) {   // CUBA: neuron = (o, pxl)
        int o = tid >> 4, p = tid & 15;
        float cc = 0.0f, vv = 0.0f;
        u64 m = 0;
        #pragma unroll 1
        for (int tt = 0; tt < 64; ++tt) {
            float z = zsm[tid * 65 + tt];
            cc = 0.7f * cc + z;
            vv = 0.75f * vv + cc;
            if (vv >= 1.0f) { m |= (1ULL << tt); vv = 0.0f; }
        }
        sp[(((size_t)b * 8 + o) * 32 + y) * 32 + xh * 16 + p] = m;
    }
}

// ---------------------------------------------------------------------------
// conv2: 8->32, in 32x32, out 8x8. Grid (16 b, 8 yq, 8 og of 4o) = 1024
// blocks x 128 thr -> ~28 warps/SM. Input halo staged to smem.
// 128 thr = 16 tq x 8 px; thread tile 4o x 4t = 8 FFMA2 per word.
// ---------------------------------------------------------------------------
__global__ void __launch_bounds__(128, 7)
conv2_kernel(const u64* __restrict__ s1, const float* __restrict__ wn,
             u64* __restrict__ sp)
{
    __shared__ u64 tile[8][5][33];                 // 10560 B, zero-padded halo
    __shared__ __align__(16) float wsm[800];       // [200 taps][4 o]
    __shared__ float zsm[32 * 65];                 // 32 neurons

    const int b = blockIdx.x, yq = blockIdx.y, og = blockIdx.z;
    const int tid = threadIdx.x;
    const int tq = tid & 15, px = tid >> 4;        // px = output x, 0..7

    for (int idx = tid; idx < 800; idx += 128)
        wsm[idx] = wn[(og * 4 + (idx & 3)) * 200 + (idx >> 2)];
    for (int idx = tid; idx < 1320; idx += 128) {
        int c = idx / 165, rem = idx % 165;
        int r = rem / 33, col = rem % 33;
        int gy = 4 * yq - 1 + r;
        int gx = col - 1;
        u64 v = 0ULL;
        if (gy >= 0 && gx >= 0)
            v = s1[(((size_t)b * 8 + c) << 10) + ((size_t)gy << 5) + gx];
        tile[c][r][col] = v;
    }
    __syncthreads();

    u64 acc[2][4];   // [opair][k(t)]
    #pragma unroll
    for (int j = 0; j < 2; ++j)
        #pragma unroll
        for (int k = 0; k < 4; ++k) acc[j][k] = 0ULL;

    #pragma unroll 1
    for (int c = 0; c < 8; ++c) {
        #pragma unroll 1
        for (int ky = 0; ky < 5; ++ky) {
            #pragma unroll
            for (int kx = 0; kx < 5; ++kx) {
                u64 word = tile[c][ky][px * 4 + kx];
                unsigned int lo = (unsigned int)word;
                unsigned int hi = (unsigned int)(word >> 32);
                u64 fd[4];
                fd[0] = bit2f2(lo, tq);
                fd[1] = bit2f2(lo, tq + 16);
                fd[2] = bit2f2(hi, tq);
                fd[3] = bit2f2(hi, tq + 16);
                ulonglong2 wA =
                    *(const ulonglong2*)(wsm + (c * 25 + ky * 5 + kx) * 4);
                #pragma unroll
                for (int k = 0; k < 4; ++k) {
                    ffma2(acc[0][k], wA.x, fd[k]);
                    ffma2(acc[1][k], wA.y, fd[k]);
                }
            }
        }
    }

    #pragma unroll
    for (int j = 0; j < 2; ++j)
        #pragma unroll
        for (int k = 0; k < 4; ++k) {
            float lo, hi;
            unpack2(acc[j][k], lo, hi);
            zsm[((2 * j)     * 8 + px) * 65 + tq + 16 * k] = lo;
            zsm[((2 * j + 1) * 8 + px) * 65 + tq + 16 * k] = hi;
        }
    __syncthreads();

    if (tid < 32) {   // CUBA: neuron = (o_local, px)
        int o_loc = tid >> 3, p = tid & 7;
        float cc = 0.0f, vv = 0.0f;
        u64 m = 0;
        #pragma unroll 1
        for (int tt = 0; tt < 64; ++tt) {
            float z = zsm[tid * 65 + tt];
            cc = 0.7f * cc + z;
            vv = 0.75f * vv + cc;
            if (vv >= 1.0f) { m |= (1ULL << tt); vv = 0.0f; }
        }
        sp[(((size_t)b * 32 + og * 4 + o_loc) * 8 + yq) * 8 + p] = m;
    }
}

// ---------------------------------------------------------------------------
// conv3: 32->64, in 8x8, out 2x2. Grid (16 b, 16 og of 4 o) = 256 blocks
// x 512 thr: 64t x 4pos x 2 csub (c-split). Partial z reduced in smem.
// Warp-uniform zero skip in the inner loop.
// ---------------------------------------------------------------------------
__global__ void __launch_bounds__(512, 2)
conv3_kernel(const u64* __restrict__ s2, const float* __restrict__ wn,
             u64* __restrict__ sp)
{
    __shared__ u64 tile[2048];                     // 16 KB: 32c x 8 x 8
    __shared__ __align__(16) float wsm[800 * 4];   // [tap][4 o]
    __shared__ float zpart[2][16][65];             // [csub][neuron][t]

    const int b = blockIdx.x, og = blockIdx.y;
    const int tid = threadIdx.x;
    const int t = tid & 63, pq = (tid >> 6) & 3, csub = tid >> 8;
    const int y = pq >> 1, x = pq & 1;
    const int shift = t & 32, tb = t & 31;

    for (int idx = tid; idx < 3200; idx += 512)
        wsm[idx] = wn[(og * 4 + (idx & 3)) * 800 + (idx >> 2)];
    for (int idx = tid; idx < 2048; idx += 512)
        tile[idx] = s2[(size_t)b * 2048 + idx];
    __syncthreads();

    u64 acc[2] = {0ULL, 0ULL};

    #pragma unroll 1
    for (int c = csub * 16; c < csub * 16 + 16; ++c) {
        #pragma unroll 1
        for (int ky = 0; ky < 5; ++ky) {
            int iy = 4 * y - 1 + ky;
            if (iy < 0) continue;
            #pragma unroll
            for (int kx = 0; kx < 5; ++kx) {
                int ix = 4 * x - 1 + kx;
                u64 word = 0ULL;
                if (ix >= 0) word = tile[c * 64 + iy * 8 + ix];
                if (word) {
                    unsigned int half = (unsigned int)(word >> shift);
                    u64 f = bit2f2(half, tb);
                    ulonglong2 w01 =
                        *(const ulonglong2*)(wsm + (c * 25 + ky * 5 + kx) * 4);
                    ffma2(acc[0], w01.x, f);
                    ffma2(acc[1], w01.y, f);
                }
            }
        }
    }

    #pragma unroll
    for (int j = 0; j < 2; ++j) {
        float lo, hi;
        unpack2(acc[j], lo, hi);
        zpart[csub][(2 * j)     * 4 + pq][t] = lo;
        zpart[csub][(2 * j + 1) * 4 + pq][t] = hi;
    }
    __syncthreads();

    if (tid < 16) {
        int o = tid >> 2, p = tid & 3;
        float cc = 0.0f, vv = 0.0f;
        u64 m = 0;
        #pragma unroll 1
        for (int tt = 0; tt < 64; ++tt) {
            float z = zpart[0][tid][tt] + zpart[1][tid][tt];
            cc = 0.7f * cc + z;
            vv = 0.75f * vv + cc;
            if (vv >= 1.0f) { m |= (1ULL << tt); vv = 0.0f; }
        }
        sp[(size_t)b * 256 + (og * 4 + o) * 4 + p] = m;
    }
}

// ---------------------------------------------------------------------------
// dense1: 256->2056 + CUBA. Grid (16 b, 33 og of 64 o) = 528 blocks x 256
// thr: 32 tq x 8 oq; thread tile 8o (4 pairs) x 2t = 8 FFMA2 per word.
// Block-uniform zero-word skip.
// ---------------------------------------------------------------------------
__global__ void __launch_bounds__(256, 5)
dense1_cuba_kernel(const u64* __restrict__ s3,
                   const float* __restrict__ w4t,
                   u64* __restrict__ s4)
{
    __shared__ u64 words[256];                     // 2 KB
    __shared__ __align__(16) float wsm[64 * 64];   // 16 KB: [i][64 o]
    __shared__ float zsm[64 * 65];                 // 16.6 KB

    const int b = blockIdx.x, og = blockIdx.y;
    const int tid = threadIdx.x;
    const int tq = tid & 31, oq = tid >> 5;        // oq 0..7, 8 o each

    words[tid] = s3[b * 256 + tid];

    u64 acc[4][2];
    #pragma unroll
    for (int j = 0; j < 4; ++j) { acc[j][0] = 0ULL; acc[j][1] = 0ULL; }

    #pragma unroll 1
    for (int q = 0; q < 4; ++q) {
        __syncthreads();
        #pragma unroll
        for (int r = 0; r < 4; ++r) {
            int f4 = r * 256 + tid;           // 0..1023
            int ii = f4 >> 4;                 // 0..63
            int o4 = (f4 & 15) * 4;           // 0..60
            *(float4*)(wsm + ii * 64 + o4) =
                *(const float4*)(w4t + (size_t)(q * 64 + ii) * W4T_STRIDE + og * 64 + o4);
        }
        __syncthreads();

        #pragma unroll 2
        for (int ii = 0; ii < 64; ++ii) {
            u64 wd = words[q * 64 + ii];
            if (wd == 0ULL) continue;          // block-uniform, exact skip
            u64 f0 = bit2f2((unsigned int)wd, tq);
            u64 f1 = bit2f2((unsigned int)(wd >> 32), tq);
            const ulonglong2* wp = (const ulonglong2*)(wsm + ii * 64 + oq * 8);
            ulonglong2 w0 = wp[0], w1 = wp[1];
            u64 wpair[4] = {w0.x, w0.y, w1.x, w1.y};
            #pragma unroll
            for (int j = 0; j < 4; ++j) {
                ffma2(acc[j][0], wpair[j], f0);
                ffma2(acc[j][1], wpair[j], f1);
            }
        }
    }

    #pragma unroll
    for (int j = 0; j < 4; ++j)
        #pragma unroll
        for (int k = 0; k < 2; ++k) {
            float lo, hi;
            unpack2(acc[j][k], lo, hi);
            zsm[(oq * 8 + 2 * j)     * 65 + tq + 32 * k] = lo;
            zsm[(oq * 8 + 2 * j + 1) * 65 + tq + 32 * k] = hi;
        }
    __syncthreads();

    if (tid < 64) {
        int o_g = og * 64 + tid;
        float cc = 0.0f, vv = 0.0f;
        u64 m = 0;
        #pragma unroll 1
        for (int tt = 0; tt < 64; ++tt) {
            float z = zsm[tid * 65 + tt];
            cc = 0.7f * cc + z;
            vv = 0.75f * vv + cc;
            if (vv >= 1.0f) { m |= (1ULL << tt); vv = 0.0f; }
        }
        if (o_g < 2056) s4[b * 2056 + o_g] = m;
    }
}

// ---------------------------------------------------------------------------
// dense2 (2056->11) + final CUBA + float output. Grid (16 b, 11 o).
// ---------------------------------------------------------------------------
__global__ void __launch_bounds__(256)
dense2_out_kernel(const u64* __restrict__ s4, const float* __restrict__ w5,
                  float* __restrict__ out)
{
    __shared__ float part[4][64];
    __shared__ float zrow[64];
    __shared__ u64 spk;

    const int b = blockIdx.x, o = blockIdx.y;
    const int tid = threadIdx.x;
    const int t = tid & 63, q = tid >> 6;

    float s = 0.0f;
    const u64*   wp = s4 + b * 2056;
    const float* vp = w5 + (size_t)o * 2056;
    for (int i = q * 514; i < q * 514 + 514; ++i) {
        float wt = vp[i];
        if ((wp[i] >> t) & 1ULL) s += wt;
    }
    part[q][t] = s;
    __syncthreads();
    if (tid < 64)
        zrow[tid] = part[0][tid] + part[1][tid] + part[2][tid] + part[3][tid];
    __syncthreads();
    if (tid == 0) {
        float cc = 0.0f, vv = 0.0f;
        u64 m = 0;
        #pragma unroll 1
        for (int tt = 0; tt < 64; ++tt) {
            cc = 0.7f * cc + zrow[tt];
            vv = 0.75f * vv + cc;
            if (vv >= 1.0f) { m |= (1ULL << tt); vv = 0.0f; }
        }
        spk = m;
    }
    __syncthreads();
    if (tid < 64)
        out[((size_t)b * 11 + o) * 64 + tid] = (float)((spk >> tid) & 1ULL);
}

// ---------------------------------------------------------------------------
// launch
// ---------------------------------------------------------------------------
extern "C" void kernel_launch(void* const* d_in, const int* in_sizes, int n_in,
                              void* d_out, int out_size)
{
    const float* x   = (const float*)d_in[0];
    const float* c1v = (const float*)d_in[1];
    const float* c1g = (const float*)d_in[2];
    const float* c2v = (const float*)d_in[3];
    const float* c2g = (const float*)d_in[4];
    const float* c3v = (const float*)d_in[5];
    const float* c3g = (const float*)d_in[6];
    const float* d1v = (const float*)d_in[7];
    const float* d1g = (const float*)d_in[8];
    const float* d2v = (const float*)d_in[9];
    const float* d2g = (const float*)d_in[10];
    float* out = (float*)d_out;

    void* fp = nullptr; void* up = nullptr;
    cudaGetSymbolAddress(&fp, g_fbuf);
    cudaGetSymbolAddress(&up, g_ubuf);
    float* F = (float*)fp;
    u64*   U = (u64*)up;

    float* W1  = F + W1_OFF;
    float* W2  = F + W2_OFF;
    float* W3  = F + W3_OFF;
    float* W4T = F + W4T_OFF;
    float* W5  = F + W5_OFF;
    u64* XP = U + XP_OFF;  u64* S1 = U + S1_OFF;  u64* S2 = U + S2_OFF;
    u64* S3 = U + S3_OFF;  u64* S4 = U + S4_OFF;

    init_kernel<<<4219, 256>>>(x, XP, c1v, c1g, c2v, c2g, c3v, c3g,
                               d1v, d1g, d2v, d2g);

    conv1_kernel<<<dim3(16, 32, 2), 256>>>(XP, W1, S1);
    conv2_kernel<<<dim3(16, 8, 8), 128>>>(S1, W2, S2);
    conv3_kernel<<<dim3(16, 16), 512>>>(S2, W3, S3);

    dense1_cuba_kernel<<<dim3(16, 33), 256>>>(S3, W4T, S4);
    dense2_out_kernel<<<dim3(16, 11), 256>>>(S4, W5, out);
}

// round 8
// speedup vs baseline: 1.9071x; 1.0572x over previous
#include <cuda_runtime.h>
#include <cstdint>

typedef unsigned long long u64;

// ---------------------------------------------------------------------------
// Dimensions
// x: (16,2,128,128,64) -> conv1 (8,2,5,5) s4 p1 -> (16,8,32,32,T)
// -> conv2 (32,8,5,5) -> (16,32,8,8,T) -> conv3 (64,32,5,5) -> (16,64,2,2,T)
// -> dense1 256->2056 -> dense2 2056->11 -> out (16,11,64)
// ---------------------------------------------------------------------------

// float pool offsets
#define W1_OFF   0              // 8*50
#define W2_OFF   400            // 32*200
#define W3_OFF   6800           // 64*800
#define W4T_OFF  58000          // 256 * 2304 (transposed, padded rows)
#define W5_OFF   647824         // 11*2056
#define FBUF_TOTAL 670440

#define W4T_STRIDE 2304

// u64 pool offsets
#define XP_OFF 0                // 16*2*128*128
#define S1_OFF 524288           // 16*8*32*32
#define S2_OFF 655360           // 16*32*8*8
#define S3_OFF 688128           // 16*256
#define S4_OFF 692224           // 16*2056
#define UBUF_TOTAL 725120

__device__ float g_fbuf[FBUF_TOTAL];
__device__ u64   g_ubuf[UBUF_TOTAL];

// ---------------------------------------------------------------------------
// f32x2 packed-FMA helpers (two exact IEEE fp32 lanes -> bit-identical z)
// ---------------------------------------------------------------------------
__device__ __forceinline__ void ffma2(u64& d, u64 a, u64 b)
{
    asm("fma.rn.f32x2 %0, %1, %2, %0;" : "+l"(d) : "l"(a), "l"(b));
}
#define ONE2 0x3F8000003F800000ULL
__device__ __forceinline__ u64 bit2f2(unsigned int word, int t)
{
    return ((word >> t) & 1u) ? ONE2 : 0ULL;
}
__device__ __forceinline__ void unpack2(u64 p, float& lo, float& hi)
{
    unsigned int l_, h_;
    asm("mov.b64 {%0,%1}, %2;" : "=r"(l_), "=r"(h_) : "l"(p));
    lo = __uint_as_float(l_);
    hi = __uint_as_float(h_);
}

// ---------------------------------------------------------------------------
// Merged init kernel: blocks [0,2048) pack input spikes; blocks [2048,4219)
// run weight_norm for all 5 layers (dense1 transposed, padded rows).
// ---------------------------------------------------------------------------
__global__ void __launch_bounds__(256)
init_kernel(const float* __restrict__ x, u64* __restrict__ xp,
            const float* __restrict__ c1v, const float* __restrict__ c1g,
            const float* __restrict__ c2v, const float* __restrict__ c2g,
            const float* __restrict__ c3v, const float* __restrict__ c3g,
            const float* __restrict__ d1v, const float* __restrict__ d1g,
            const float* __restrict__ d2v, const float* __restrict__ d2g)
{
    __shared__ unsigned int nsm[256 * 17];
    const int tid = threadIdx.x;

    if (blockIdx.x < 2048) {
        // ---- pack: coalesced float4 loads -> nibble transpose -> u64 words
        const float4* xg = (const float4*)x + (size_t)blockIdx.x * 4096;
        #pragma unroll
        for (int j = 0; j < 16; ++j) {
            float4 f = xg[j * 256 + tid];
            unsigned int v = (f.x > 0.5f ? 1u : 0u) | (f.y > 0.5f ? 2u : 0u)
                           | (f.z > 0.5f ? 4u : 0u) | (f.w > 0.5f ? 8u : 0u);
            int pl  = j * 16 + (tid >> 4);
            int nib = tid & 15;
            nsm[pl * 17 + nib] = v;
        }
        __syncthreads();
        u64 m = 0;
        #pragma unroll
        for (int k = 0; k < 16; ++k)
            m |= (u64)nsm[tid * 17 + k] << (4 * k);
        xp[(size_t)blockIdx.x * 256 + tid] = m;
        return;
    }

    // ---- weight_norm
    int blk = blockIdx.x - 2048;
    const float* v; const float* g; float* w; int cols; int r; int trans = 0;
    if (blk < 8)          { v = c1v; g = c1g; w = g_fbuf + W1_OFF;  cols = 50;   r = blk; }
    else if (blk < 40)    { v = c2v; g = c2g; w = g_fbuf + W2_OFF;  cols = 200;  r = blk - 8; }
    else if (blk < 104)   { v = c3v; g = c3g; w = g_fbuf + W3_OFF;  cols = 800;  r = blk - 40; }
    else if (blk < 2160)  { v = d1v; g = d1g; w = g_fbuf + W4T_OFF; cols = 256;  r = blk - 104; trans = 1; }
    else                  { v = d2v; g = d2g; w = g_fbuf + W5_OFF;  cols = 2056; r = blk - 2160; }

    float* red = (float*)nsm;
    float s = 0.0f;
    for (int i = tid; i < cols; i += 256) {
        float a = v[(size_t)r * cols + i];
        s += a * a;
    }
    red[tid] = s;
    __syncthreads();
    for (int off = 128; off > 0; off >>= 1) {
        if (tid < off) red[tid] += red[tid + off];
        __syncthreads();
    }
    float n = sqrtf(red[0]);
    float gr = g[r];
    if (!trans) {
        for (int i = tid; i < cols; i += 256)
            w[(size_t)r * cols + i] = gr * v[(size_t)r * cols + i] / n;
    } else {
        for (int i = tid; i < cols; i += 256)
            w[(size_t)i * W4T_STRIDE + r] = gr * v[(size_t)r * cols + i] / n;
    }
}

// ---------------------------------------------------------------------------
// conv1: 2->8, in 128x128, out 32x32. Grid (16 b, 32 y, 2 xh) = 1024 blocks.
// Input halo tile staged to smem (zero-padded) -> inner loop is LDS-only.
// 256 thr = 16 tq x 16 px; thread tile 8o x 4t = 16 FFMA2 per word.
// ---------------------------------------------------------------------------
__global__ void __launch_bounds__(256, 3)
conv1_kernel(const u64* __restrict__ xp, const float* __restrict__ wn,
             u64* __restrict__ sp)
{
    __shared__ u64 tile[2][5][65];                 // 5200 B, zero-padded halo
    __shared__ __align__(16) float wsm[400];       // [50 taps][8 o]
    __shared__ float zsm[128 * 65];                // 128 neurons

    const int b = blockIdx.x, y = blockIdx.y, xh = blockIdx.z;
    const int tid = threadIdx.x;
    const int tq = tid & 15, pxl = tid >> 4;

    for (int idx = tid; idx < 400; idx += 256)
        wsm[idx] = wn[(idx & 7) * 50 + (idx >> 3)];
    for (int idx = tid; idx < 650; idx += 256) {
        int c = idx / 325, rem = idx % 325;
        int r = rem / 65, col = rem % 65;
        int gy = 4 * y - 1 + r;
        int gx = xh * 64 - 1 + col;
        u64 v = 0ULL;
        if (gy >= 0 && gx >= 0)
            v = xp[(((size_t)b * 2 + c) << 14) + ((size_t)gy << 7) + gx];
        tile[c][r][col] = v;
    }
    __syncthreads();

    u64 acc[4][4];   // [opair][k(t)]
    #pragma unroll
    for (int j = 0; j < 4; ++j)
        #pragma unroll
        for (int k = 0; k < 4; ++k) acc[j][k] = 0ULL;

    #pragma unroll
    for (int c = 0; c < 2; ++c) {
        #pragma unroll 1
        for (int ky = 0; ky < 5; ++ky) {
            #pragma unroll
            for (int kx = 0; kx < 5; ++kx) {
                u64 word = tile[c][ky][pxl * 4 + kx];
                unsigned int lo = (unsigned int)word;
                unsigned int hi = (unsigned int)(word >> 32);
                u64 fd[4];
                fd[0] = bit2f2(lo, tq);
                fd[1] = bit2f2(lo, tq + 16);
                fd[2] = bit2f2(hi, tq);
                fd[3] = bit2f2(hi, tq + 16);
                const ulonglong2* wp =
                    (const ulonglong2*)(wsm + (c * 25 + ky * 5 + kx) * 8);
                ulonglong2 wA = wp[0];
                ulonglong2 wB = wp[1];
                u64 wpair[4] = {wA.x, wA.y, wB.x, wB.y};
                #pragma unroll
                for (int k = 0; k < 4; ++k)
                    #pragma unroll
                    for (int j = 0; j < 4; ++j)
                        ffma2(acc[j][k], wpair[j], fd[k]);
            }
        }
    }

    #pragma unroll
    for (int j = 0; j < 4; ++j)
        #pragma unroll
        for (int k = 0; k < 4; ++k) {
            float lo, hi;
            unpack2(acc[j][k], lo, hi);
            zsm[((2 * j)     * 16 + pxl) * 65 + tq + 16 * k] = lo;
            zsm[((2 * j + 1) * 16 + pxl) * 65 + tq + 16 * k] = hi;
        }
    __syncthreads();

    if (tid < 128) {   // CUBA: neuron = (o, pxl)
        int o = tid >> 4, p = tid & 15;
        float cc = 0.0f, vv = 0.0f;
        u64 m = 0;
        #pragma unroll 1
        for (int tt = 0; tt < 64; ++tt) {
            float z = zsm[tid * 65 + tt];
            cc = 0.7f * cc + z;
            vv = 0.75f * vv + cc;
            if (vv >= 1.0f) { m |= (1ULL << tt); vv = 0.0f; }
        }
        sp[(((size_t)b * 8 + o) * 32 + y) * 32 + xh * 16 + p] = m;
    }
}

// ---------------------------------------------------------------------------
// conv2: 8->32, in 32x32, out 8x8. Grid (16 b, 8 yq, 8 og of 4o) = 1024
// blocks x 128 thr -> ~28 warps/SM. Input halo staged to smem.
// 128 thr = 16 tq x 8 px; thread tile 4o x 4t = 8 FFMA2 per word.
// ---------------------------------------------------------------------------
__global__ void __launch_bounds__(128, 7)
conv2_kernel(const u64* __restrict__ s1, const float* __restrict__ wn,
             u64* __restrict__ sp)
{
    __shared__ u64 tile[8][5][33];                 // 10560 B, zero-padded halo
    __shared__ __align__(16) float wsm[800];       // [200 taps][4 o]
    __shared__ float zsm[32 * 65];                 // 32 neurons

    const int b = blockIdx.x, yq = blockIdx.y, og = blockIdx.z;
    const int tid = threadIdx.x;
    const int tq = tid & 15, px = tid >> 4;        // px = output x, 0..7

    for (int idx = tid; idx < 800; idx += 128)
        wsm[idx] = wn[(og * 4 + (idx & 3)) * 200 + (idx >> 2)];
    for (int idx = tid; idx < 1320; idx += 128) {
        int c = idx / 165, rem = idx % 165;
        int r = rem / 33, col = rem % 33;
        int gy = 4 * yq - 1 + r;
        int gx = col - 1;
        u64 v = 0ULL;
        if (gy >= 0 && gx >= 0)
            v = s1[(((size_t)b * 8 + c) << 10) + ((size_t)gy << 5) + gx];
        tile[c][r][col] = v;
    }
    __syncthreads();

    u64 acc[2][4];   // [opair][k(t)]
    #pragma unroll
    for (int j = 0; j < 2; ++j)
        #pragma unroll
        for (int k = 0; k < 4; ++k) acc[j][k] = 0ULL;

    #pragma unroll 1
    for (int c = 0; c < 8; ++c) {
        #pragma unroll 1
        for (int ky = 0; ky < 5; ++ky) {
            #pragma unroll
            for (int kx = 0; kx < 5; ++kx) {
                u64 word = tile[c][ky][px * 4 + kx];
                unsigned int lo = (unsigned int)word;
                unsigned int hi = (unsigned int)(word >> 32);
                u64 fd[4];
                fd[0] = bit2f2(lo, tq);
                fd[1] = bit2f2(lo, tq + 16);
                fd[2] = bit2f2(hi, tq);
                fd[3] = bit2f2(hi, tq + 16);
                ulonglong2 wA =
                    *(const ulonglong2*)(wsm + (c * 25 + ky * 5 + kx) * 4);
                #pragma unroll
                for (int k = 0; k < 4; ++k) {
                    ffma2(acc[0][k], wA.x, fd[k]);
                    ffma2(acc[1][k], wA.y, fd[k]);
                }
            }
        }
    }

    #pragma unroll
    for (int j = 0; j < 2; ++j)
        #pragma unroll
        for (int k = 0; k < 4; ++k) {
            float lo, hi;
            unpack2(acc[j][k], lo, hi);
            zsm[((2 * j)     * 8 + px) * 65 + tq + 16 * k] = lo;
            zsm[((2 * j + 1) * 8 + px) * 65 + tq + 16 * k] = hi;
        }
    __syncthreads();

    if (tid < 32) {   // CUBA: neuron = (o_local, px)
        int o_loc = tid >> 3, p = tid & 7;
        float cc = 0.0f, vv = 0.0f;
        u64 m = 0;
        #pragma unroll 1
        for (int tt = 0; tt < 64; ++tt) {
            float z = zsm[tid * 65 + tt];
            cc = 0.7f * cc + z;
            vv = 0.75f * vv + cc;
            if (vv >= 1.0f) { m |= (1ULL << tt); vv = 0.0f; }
        }
        sp[(((size_t)b * 32 + og * 4 + o_loc) * 8 + yq) * 8 + p] = m;
    }
}

// ---------------------------------------------------------------------------
// conv3: 32->64, in 8x8, out 2x2. Grid (16 b, 8 og of 8 o) = 128 blocks
// x 512 thr: 64t x 4pos x 2 csub (c-split). 8 outputs per thread ->
// per word: LDS64 + shift + selp + 2xLDS128 + 4 FFMA2 (no zero-branch).
// Partial z reduced in smem before CUBA.
// ---------------------------------------------------------------------------
__global__ void __launch_bounds__(512, 2)
conv3_kernel(const u64* __restrict__ s2, const float* __restrict__ wn,
             u64* __restrict__ sp)
{
    extern __shared__ __align__(16) char sm3[];
    u64*   tile  = (u64*)sm3;                       // 2048 u64 = 16 KB
    float* wsm   = (float*)(sm3 + 16384);           // 6400 f = 25.6 KB
    float* zpart = (float*)(sm3 + 16384 + 25600);   // 2*32*65 f = 16.64 KB

    const int b = blockIdx.x, og = blockIdx.y;
    const int tid = threadIdx.x;
    const int t = tid & 63, pq = (tid >> 6) & 3, csub = tid >> 8;
    const int y = pq >> 1, x = pq & 1;
    const int shift = t & 32, tb = t & 31;

    for (int idx = tid; idx < 6400; idx += 512)
        wsm[idx] = wn[(og * 8 + (idx & 7)) * 800 + (idx >> 3)];
    for (int idx = tid; idx < 2048; idx += 512)
        tile[idx] = s2[(size_t)b * 2048 + idx];
    __syncthreads();

    u64 acc[4] = {0ULL, 0ULL, 0ULL, 0ULL};

    #pragma unroll 1
    for (int c = csub * 16; c < csub * 16 + 16; ++c) {
        #pragma unroll 1
        for (int ky = 0; ky < 5; ++ky) {
            int iy = 4 * y - 1 + ky;
            if (iy < 0) continue;
            #pragma unroll
            for (int kx = 0; kx < 5; ++kx) {
                int ix = 4 * x - 1 + kx;
                u64 word = 0ULL;
                if (ix >= 0) word = tile[c * 64 + iy * 8 + ix];
                unsigned int half = (unsigned int)(word >> shift);
                u64 f = bit2f2(half, tb);
                const ulonglong2* wp =
                    (const ulonglong2*)(wsm + (c * 25 + ky * 5 + kx) * 8);
                ulonglong2 w01 = wp[0];
                ulonglong2 w23 = wp[1];
                ffma2(acc[0], w01.x, f);
                ffma2(acc[1], w01.y, f);
                ffma2(acc[2], w23.x, f);
                ffma2(acc[3], w23.y, f);
            }
        }
    }

    #pragma unroll
    for (int j = 0; j < 4; ++j) {
        float lo, hi;
        unpack2(acc[j], lo, hi);
        zpart[(csub * 32 + (2 * j)     * 4 + pq) * 65 + t] = lo;
        zpart[(csub * 32 + (2 * j + 1) * 4 + pq) * 65 + t] = hi;
    }
    __syncthreads();

    if (tid < 32) {   // CUBA: neuron = (o_local, pos)
        int o = tid >> 2, p = tid & 3;
        float cc = 0.0f, vv = 0.0f;
        u64 m = 0;
        #pragma unroll 1
        for (int tt = 0; tt < 64; ++tt) {
            float z = zpart[tid * 65 + tt] + zpart[(32 + tid) * 65 + tt];
            cc = 0.7f * cc + z;
            vv = 0.75f * vv + cc;
            if (vv >= 1.0f) { m |= (1ULL << tt); vv = 0.0f; }
        }
        sp[(size_t)b * 256 + (og * 8 + o) * 4 + p] = m;
    }
}

// ---------------------------------------------------------------------------
// dense1: 256->2056 + CUBA. Grid (16 b, 33 og of 64 o) = 528 blocks x 256
// thr: 32 tq x 8 oq; thread tile 8o (4 pairs) x 2t = 8 FFMA2 per word.
// Block-uniform zero-word skip.
// ---------------------------------------------------------------------------
__global__ void __launch_bounds__(256, 5)
dense1_cuba_kernel(const u64* __restrict__ s3,
                   const float* __restrict__ w4t,
                   u64* __restrict__ s4)
{
    __shared__ u64 words[256];                     // 2 KB
    __shared__ __align__(16) float wsm[64 * 64];   // 16 KB: [i][64 o]
    __shared__ float zsm[64 * 65];                 // 16.6 KB

    const int b = blockIdx.x, og = blockIdx.y;
    const int tid = threadIdx.x;
    const int tq = tid & 31, oq = tid >> 5;        // oq 0..7, 8 o each

    words[tid] = s3[b * 256 + tid];

    u64 acc[4][2];
    #pragma unroll
    for (int j = 0; j < 4; ++j) { acc[j][0] = 0ULL; acc[j][1] = 0ULL; }

    #pragma unroll 1
    for (int q = 0; q < 4; ++q) {
        __syncthreads();
        #pragma unroll
        for (int r = 0; r < 4; ++r) {
            int f4 = r * 256 + tid;           // 0..1023
            int ii = f4 >> 4;                 // 0..63
            int o4 = (f4 & 15) * 4;           // 0..60
            *(float4*)(wsm + ii * 64 + o4) =
                *(const float4*)(w4t + (size_t)(q * 64 + ii) * W4T_STRIDE + og * 64 + o4);
        }
        __syncthreads();

        #pragma unroll 2
        for (int ii = 0; ii < 64; ++ii) {
            u64 wd = words[q * 64 + ii];
            if (wd == 0ULL) continue;          // block-uniform, exact skip
            u64 f0 = bit2f2((unsigned int)wd, tq);
            u64 f1 = bit2f2((unsigned int)(wd >> 32), tq);
            const ulonglong2* wp = (const ulonglong2*)(wsm + ii * 64 + oq * 8);
            ulonglong2 w0 = wp[0], w1 = wp[1];
            u64 wpair[4] = {w0.x, w0.y, w1.x, w1.y};
            #pragma unroll
            for (int j = 0; j < 4; ++j) {
                ffma2(acc[j][0], wpair[j], f0);
                ffma2(acc[j][1], wpair[j], f1);
            }
        }
    }

    #pragma unroll
    for (int j = 0; j < 4; ++j)
        #pragma unroll
        for (int k = 0; k < 2; ++k) {
            float lo, hi;
            unpack2(acc[j][k], lo, hi);
            zsm[(oq * 8 + 2 * j)     * 65 + tq + 32 * k] = lo;
            zsm[(oq * 8 + 2 * j + 1) * 65 + tq + 32 * k] = hi;
        }
    __syncthreads();

    if (tid < 64) {
        int o_g = og * 64 + tid;
        float cc = 0.0f, vv = 0.0f;
        u64 m = 0;
        #pragma unroll 1
        for (int tt = 0; tt < 64; ++tt) {
            float z = zsm[tid * 65 + tt];
            cc = 0.7f * cc + z;
            vv = 0.75f * vv + cc;
            if (vv >= 1.0f) { m |= (1ULL << tt); vv = 0.0f; }
        }
        if (o_g < 2056) s4[b * 2056 + o_g] = m;
    }
}

// ---------------------------------------------------------------------------
// dense2 (2056->11) + final CUBA + float output. Grid (16 b, 11 o).
// ---------------------------------------------------------------------------
__global__ void __launch_bounds__(256)
dense2_out_kernel(const u64* __restrict__ s4, const float* __restrict__ w5,
                  float* __restrict__ out)
{
    __shared__ float part[4][64];
    __shared__ float zrow[64];
    __shared__ u64 spk;

    const int b = blockIdx.x, o = blockIdx.y;
    const int tid = threadIdx.x;
    const int t = tid & 63, q = tid >> 6;

    float s = 0.0f;
    const u64*   wp = s4 + b * 2056;
    const float* vp = w5 + (size_t)o * 2056;
    for (int i = q * 514; i < q * 514 + 514; ++i) {
        float wt = vp[i];
        if ((wp[i] >> t) & 1ULL) s += wt;
    }
    part[q][t] = s;
    __syncthreads();
    if (tid < 64)
        zrow[tid] = part[0][tid] + part[1][tid] + part[2][tid] + part[3][tid];
    __syncthreads();
    if (tid == 0) {
        float cc = 0.0f, vv = 0.0f;
        u64 m = 0;
        #pragma unroll 1
        for (int tt = 0; tt < 64; ++tt) {
            cc = 0.7f * cc + zrow[tt];
            vv = 0.75f * vv + cc;
            if (vv >= 1.0f) { m |= (1ULL << tt); vv = 0.0f; }
        }
        spk = m;
    }
    __syncthreads();
    if (tid < 64)
        out[((size_t)b * 11 + o) * 64 + tid] = (float)((spk >> tid) & 1ULL);
}

// ---------------------------------------------------------------------------
// launch
// ---------------------------------------------------------------------------
extern "C" void kernel_launch(void* const* d_in, const int* in_sizes, int n_in,
                              void* d_out, int out_size)
{
    const float* x   = (const float*)d_in[0];
    const float* c1v = (const float*)d_in[1];
    const float* c1g = (const float*)d_in[2];
    const float* c2v = (const float*)d_in[3];
    const float* c2g = (const float*)d_in[4];
    const float* c3v = (const float*)d_in[5];
    const float* c3g = (const float*)d_in[6];
    const float* d1v = (const float*)d_in[7];
    const float* d1g = (const float*)d_in[8];
    const float* d2v = (const float*)d_in[9];
    const float* d2g = (const float*)d_in[10];
    float* out = (float*)d_out;

    void* fp = nullptr; void* up = nullptr;
    cudaGetSymbolAddress(&fp, g_fbuf);
    cudaGetSymbolAddress(&up, g_ubuf);
    float* F = (float*)fp;
    u64*   U = (u64*)up;

    float* W1  = F + W1_OFF;
    float* W2  = F + W2_OFF;
    float* W3  = F + W3_OFF;
    float* W4T = F + W4T_OFF;
    float* W5  = F + W5_OFF;
    u64* XP = U + XP_OFF;  u64* S1 = U + S1_OFF;  u64* S2 = U + S2_OFF;
    u64* S3 = U + S3_OFF;  u64* S4 = U + S4_OFF;

    const int SM3 = 16384 + 25600 + 2 * 32 * 65 * 4;   // 58624 bytes
    cudaFuncSetAttribute(conv3_kernel,
                         cudaFuncAttributeMaxDynamicSharedMemorySize, SM3);

    init_kernel<<<4219, 256>>>(x, XP, c1v, c1g, c2v, c2g, c3v, c3g,
                               d1v, d1g, d2v, d2g);

    conv1_kernel<<<dim3(16, 32, 2), 256>>>(XP, W1, S1);
    conv2_kernel<<<dim3(16, 8, 8), 128>>>(S1, W2, S2);
    conv3_kernel<<<dim3(16, 8), 512, SM3>>>(S2, W3, S3);

    dense1_cuba_kernel<<<dim3(16, 33), 256>>>(S3, W4T, S4);
    dense2_out_kernel<<<dim3(16, 11), 256>>>(S4, W5, out);
}

// round 9
// speedup vs baseline: 1.9310x; 1.0125x over previous
#include <cuda_runtime.h>
#include <cstdint>

typedef unsigned long long u64;

// ---------------------------------------------------------------------------
// Dimensions
// x: (16,2,128,128,64) -> conv1 (8,2,5,5) s4 p1 -> (16,8,32,32,T)
// -> conv2 (32,8,5,5) -> (16,32,8,8,T) -> conv3 (64,32,5,5) -> (16,64,2,2,T)
// -> dense1 256->2056 -> dense2 2056->11 -> out (16,11,64)
// ---------------------------------------------------------------------------

// float pool offsets
#define W1_OFF   0              // 8*50
#define W2_OFF   400            // 32*200
#define W3_OFF   6800           // 64*800
#define W4T_OFF  58000          // 256 * 2304 (transposed, padded rows)
#define W5_OFF   647824         // 11*2056
#define FBUF_TOTAL 670440

#define W4T_STRIDE 2304

// u64 pool offsets
#define XP_OFF 0                // 16*2*128*128
#define S1_OFF 524288           // 16*8*32*32
#define S2_OFF 655360           // 16*32*8*8
#define S3_OFF 688128           // 16*256
#define S4_OFF 692224           // 16*2056
#define UBUF_TOTAL 725120

__device__ float g_fbuf[FBUF_TOTAL];
__device__ u64   g_ubuf[UBUF_TOTAL];

// ---------------------------------------------------------------------------
// f32x2 packed-FMA helpers (two exact IEEE fp32 lanes -> bit-identical z)
// ---------------------------------------------------------------------------
__device__ __forceinline__ void ffma2(u64& d, u64 a, u64 b)
{
    asm("fma.rn.f32x2 %0, %1, %2, %0;" : "+l"(d) : "l"(a), "l"(b));
}
#define ONE2 0x3F8000003F800000ULL
__device__ __forceinline__ u64 bit2f2(unsigned int word, int t)
{
    return ((word >> t) & 1u) ? ONE2 : 0ULL;
}
__device__ __forceinline__ void unpack2(u64 p, float& lo, float& hi)
{
    unsigned int l_, h_;
    asm("mov.b64 {%0,%1}, %2;" : "=r"(l_), "=r"(h_) : "l"(p));
    lo = __uint_as_float(l_);
    hi = __uint_as_float(h_);
}

// ---------------------------------------------------------------------------
// Merged init kernel: blocks [0,2048) pack input spikes; blocks [2048,4219)
// run weight_norm for all 5 layers (dense1 transposed, padded rows).
// ---------------------------------------------------------------------------
__global__ void __launch_bounds__(256)
init_kernel(const float* __restrict__ x, u64* __restrict__ xp,
            const float* __restrict__ c1v, const float* __restrict__ c1g,
            const float* __restrict__ c2v, const float* __restrict__ c2g,
            const float* __restrict__ c3v, const float* __restrict__ c3g,
            const float* __restrict__ d1v, const float* __restrict__ d1g,
            const float* __restrict__ d2v, const float* __restrict__ d2g)
{
    __shared__ unsigned int nsm[256 * 17];
    const int tid = threadIdx.x;

    if (blockIdx.x < 2048) {
        // ---- pack: coalesced float4 loads -> nibble transpose -> u64 words
        const float4* xg = (const float4*)x + (size_t)blockIdx.x * 4096;
        #pragma unroll
        for (int j = 0; j < 16; ++j) {
            float4 f = xg[j * 256 + tid];
            unsigned int v = (f.x > 0.5f ? 1u : 0u) | (f.y > 0.5f ? 2u : 0u)
                           | (f.z > 0.5f ? 4u : 0u) | (f.w > 0.5f ? 8u : 0u);
            int pl  = j * 16 + (tid >> 4);
            int nib = tid & 15;
            nsm[pl * 17 + nib] = v;
        }
        __syncthreads();
        u64 m = 0;
        #pragma unroll
        for (int k = 0; k < 16; ++k)
            m |= (u64)nsm[tid * 17 + k] << (4 * k);
        xp[(size_t)blockIdx.x * 256 + tid] = m;
        return;
    }

    // ---- weight_norm
    int blk = blockIdx.x - 2048;
    const float* v; const float* g; float* w; int cols; int r; int trans = 0;
    if (blk < 8)          { v = c1v; g = c1g; w = g_fbuf + W1_OFF;  cols = 50;   r = blk; }
    else if (blk < 40)    { v = c2v; g = c2g; w = g_fbuf + W2_OFF;  cols = 200;  r = blk - 8; }
    else if (blk < 104)   { v = c3v; g = c3g; w = g_fbuf + W3_OFF;  cols = 800;  r = blk - 40; }
    else if (blk < 2160)  { v = d1v; g = d1g; w = g_fbuf + W4T_OFF; cols = 256;  r = blk - 104; trans = 1; }
    else                  { v = d2v; g = d2g; w = g_fbuf + W5_OFF;  cols = 2056; r = blk - 2160; }

    float* red = (float*)nsm;
    float s = 0.0f;
    for (int i = tid; i < cols; i += 256) {
        float a = v[(size_t)r * cols + i];
        s += a * a;
    }
    red[tid] = s;
    __syncthreads();
    for (int off = 128; off > 0; off >>= 1) {
        if (tid < off) red[tid] += red[tid + off];
        __syncthreads();
    }
    float n = sqrtf(red[0]);
    float gr = g[r];
    if (!trans) {
        for (int i = tid; i < cols; i += 256)
            w[(size_t)r * cols + i] = gr * v[(size_t)r * cols + i] / n;
    } else {
        for (int i = tid; i < cols; i += 256)
            w[(size_t)i * W4T_STRIDE + r] = gr * v[(size_t)r * cols + i] / n;
    }
}

// ---------------------------------------------------------------------------
// conv1: 2->8, in 128x128, out 32x32. Grid (16 b, 32 y, 2 xh) = 1024 blocks.
// Input halo tile staged to smem (zero-padded) -> inner loop is LDS-only.
// 256 thr = 16 tq x 16 px; thread tile 8o x 4t = 16 FFMA2 per word.
// ---------------------------------------------------------------------------
__global__ void __launch_bounds__(256, 3)
conv1_kernel(const u64* __restrict__ xp, const float* __restrict__ wn,
             u64* __restrict__ sp)
{
    __shared__ u64 tile[2][5][65];                 // 5200 B, zero-padded halo
    __shared__ __align__(16) float wsm[400];       // [50 taps][8 o]
    __shared__ float zsm[128 * 65];                // 128 neurons

    const int b = blockIdx.x, y = blockIdx.y, xh = blockIdx.z;
    const int tid = threadIdx.x;
    const int tq = tid & 15, pxl = tid >> 4;

    for (int idx = tid; idx < 400; idx += 256)
        wsm[idx] = wn[(idx & 7) * 50 + (idx >> 3)];
    for (int idx = tid; idx < 650; idx += 256) {
        int c = idx / 325, rem = idx % 325;
        int r = rem / 65, col = rem % 65;
        int gy = 4 * y - 1 + r;
        int gx = xh * 64 - 1 + col;
        u64 v = 0ULL;
        if (gy >= 0 && gx >= 0)
            v = xp[(((size_t)b * 2 + c) << 14) + ((size_t)gy << 7) + gx];
        tile[c][r][col] = v;
    }
    __syncthreads();

    u64 acc[4][4];   // [opair][k(t)]
    #pragma unroll
    for (int j = 0; j < 4; ++j)
        #pragma unroll
        for (int k = 0; k < 4; ++k) acc[j][k] = 0ULL;

    #pragma unroll
    for (int c = 0; c < 2; ++c) {
        #pragma unroll 1
        for (int ky = 0; ky < 5; ++ky) {
            #pragma unroll
            for (int kx = 0; kx < 5; ++kx) {
                u64 word = tile[c][ky][pxl * 4 + kx];
                unsigned int lo = (unsigned int)word;
                unsigned int hi = (unsigned int)(word >> 32);
                u64 fd[4];
                fd[0] = bit2f2(lo, tq);
                fd[1] = bit2f2(lo, tq + 16);
                fd[2] = bit2f2(hi, tq);
                fd[3] = bit2f2(hi, tq + 16);
                const ulonglong2* wp =
                    (const ulonglong2*)(wsm + (c * 25 + ky * 5 + kx) * 8);
                ulonglong2 wA = wp[0];
                ulonglong2 wB = wp[1];
                u64 wpair[4] = {wA.x, wA.y, wB.x, wB.y};
                #pragma unroll
                for (int k = 0; k < 4; ++k)
                    #pragma unroll
                    for (int j = 0; j < 4; ++j)
                        ffma2(acc[j][k], wpair[j], fd[k]);
            }
        }
    }

    #pragma unroll
    for (int j = 0; j < 4; ++j)
        #pragma unroll
        for (int k = 0; k < 4; ++k) {
            float lo, hi;
            unpack2(acc[j][k], lo, hi);
            zsm[((2 * j)     * 16 + pxl) * 65 + tq + 16 * k] = lo;
            zsm[((2 * j + 1) * 16 + pxl) * 65 + tq + 16 * k] = hi;
        }
    __syncthreads();

    if (tid < 128) {   // CUBA: neuron = (o, pxl)
        int o = tid >> 4, p = tid & 15;
        float cc = 0.0f, vv = 0.0f;
        u64 m = 0;
        #pragma unroll 1
        for (int tt = 0; tt < 64; ++tt) {
            float z = zsm[tid * 65 + tt];
            cc = 0.7f * cc + z;
            vv = 0.75f * vv + cc;
            if (vv >= 1.0f) { m |= (1ULL << tt); vv = 0.0f; }
        }
        sp[(((size_t)b * 8 + o) * 32 + y) * 32 + xh * 16 + p] = m;
    }
}

// ---------------------------------------------------------------------------
// conv2: 8->32, in 32x32, out 8x8. Grid (16 b, 8 yq, 8 og of 4o) = 1024
// blocks x 128 thr -> ~28 warps/SM. Input halo staged to smem.
// 128 thr = 16 tq x 8 px; thread tile 4o x 4t = 8 FFMA2 per word.
// ---------------------------------------------------------------------------
__global__ void __launch_bounds__(128, 7)
conv2_kernel(const u64* __restrict__ s1, const float* __restrict__ wn,
             u64* __restrict__ sp)
{
    __shared__ u64 tile[8][5][33];                 // 10560 B, zero-padded halo
    __shared__ __align__(16) float wsm[800];       // [200 taps][4 o]
    __shared__ float zsm[32 * 65];                 // 32 neurons

    const int b = blockIdx.x, yq = blockIdx.y, og = blockIdx.z;
    const int tid = threadIdx.x;
    const int tq = tid & 15, px = tid >> 4;        // px = output x, 0..7

    for (int idx = tid; idx < 800; idx += 128)
        wsm[idx] = wn[(og * 4 + (idx & 3)) * 200 + (idx >> 2)];
    for (int idx = tid; idx < 1320; idx += 128) {
        int c = idx / 165, rem = idx % 165;
        int r = rem / 33, col = rem % 33;
        int gy = 4 * yq - 1 + r;
        int gx = col - 1;
        u64 v = 0ULL;
        if (gy >= 0 && gx >= 0)
            v = s1[(((size_t)b * 8 + c) << 10) + ((size_t)gy << 5) + gx];
        tile[c][r][col] = v;
    }
    __syncthreads();

    u64 acc[2][4];   // [opair][k(t)]
    #pragma unroll
    for (int j = 0; j < 2; ++j)
        #pragma unroll
        for (int k = 0; k < 4; ++k) acc[j][k] = 0ULL;

    #pragma unroll 1
    for (int c = 0; c < 8; ++c) {
        #pragma unroll 1
        for (int ky = 0; ky < 5; ++ky) {
            #pragma unroll
            for (int kx = 0; kx < 5; ++kx) {
                u64 word = tile[c][ky][px * 4 + kx];
                unsigned int lo = (unsigned int)word;
                unsigned int hi = (unsigned int)(word >> 32);
                u64 fd[4];
                fd[0] = bit2f2(lo, tq);
                fd[1] = bit2f2(lo, tq + 16);
                fd[2] = bit2f2(hi, tq);
                fd[3] = bit2f2(hi, tq + 16);
                ulonglong2 wA =
                    *(const ulonglong2*)(wsm + (c * 25 + ky * 5 + kx) * 4);
                #pragma unroll
                for (int k = 0; k < 4; ++k) {
                    ffma2(acc[0][k], wA.x, fd[k]);
                    ffma2(acc[1][k], wA.y, fd[k]);
                }
            }
        }
    }

    #pragma unroll
    for (int j = 0; j < 2; ++j)
        #pragma unroll
        for (int k = 0; k < 4; ++k) {
            float lo, hi;
            unpack2(acc[j][k], lo, hi);
            zsm[((2 * j)     * 8 + px) * 65 + tq + 16 * k] = lo;
            zsm[((2 * j + 1) * 8 + px) * 65 + tq + 16 * k] = hi;
        }
    __syncthreads();

    if (tid < 32) {   // CUBA: neuron = (o_local, px)
        int o_loc = tid >> 3, p = tid & 7;
        float cc = 0.0f, vv = 0.0f;
        u64 m = 0;
        #pragma unroll 1
        for (int tt = 0; tt < 64; ++tt) {
            float z = zsm[tid * 65 + tt];
            cc = 0.7f * cc + z;
            vv = 0.75f * vv + cc;
            if (vv >= 1.0f) { m |= (1ULL << tt); vv = 0.0f; }
        }
        sp[(((size_t)b * 32 + og * 4 + o_loc) * 8 + yq) * 8 + p] = m;
    }
}

// ---------------------------------------------------------------------------
// conv3: 32->64, in 8x8, out 2x2. Grid (16 b, 8 og of 8 o) = 128 blocks
// x 1024 thr: 64t x 4pos x 4 csub (8 channels each) -> 32 warps/SM.
// 8 outputs per thread: per word LDS64 + shift + selp + 2xLDS128 + 4 FFMA2.
// 4 partial z tensors reduced in smem before CUBA.
// ---------------------------------------------------------------------------
__global__ void __launch_bounds__(1024, 1)
conv3_kernel(const u64* __restrict__ s2, const float* __restrict__ wn,
             u64* __restrict__ sp)
{
    extern __shared__ __align__(16) char sm3[];
    u64*   tile  = (u64*)sm3;                       // 2048 u64 = 16 KB
    float* wsm   = (float*)(sm3 + 16384);           // 6400 f = 25.6 KB
    float* zpart = (float*)(sm3 + 16384 + 25600);   // 4*32*65 f = 33.28 KB

    const int b = blockIdx.x, og = blockIdx.y;
    const int tid = threadIdx.x;
    const int t = tid & 63, pq = (tid >> 6) & 3, csub = tid >> 8;   // csub 0..3
    const int y = pq >> 1, x = pq & 1;
    const int shift = t & 32, tb = t & 31;

    for (int idx = tid; idx < 6400; idx += 1024)
        wsm[idx] = wn[(og * 8 + (idx & 7)) * 800 + (idx >> 3)];
    for (int idx = tid; idx < 2048; idx += 1024)
        tile[idx] = s2[(size_t)b * 2048 + idx];
    __syncthreads();

    u64 acc[4] = {0ULL, 0ULL, 0ULL, 0ULL};

    #pragma unroll 1
    for (int c = csub * 8; c < csub * 8 + 8; ++c) {
        #pragma unroll 1
        for (int ky = 0; ky < 5; ++ky) {
            int iy = 4 * y - 1 + ky;
            if (iy < 0) continue;
            #pragma unroll
            for (int kx = 0; kx < 5; ++kx) {
                int ix = 4 * x - 1 + kx;
                u64 word = 0ULL;
                if (ix >= 0) word = tile[c * 64 + iy * 8 + ix];
                unsigned int half = (unsigned int)(word >> shift);
                u64 f = bit2f2(half, tb);
                const ulonglong2* wp =
                    (const ulonglong2*)(wsm + (c * 25 + ky * 5 + kx) * 8);
                ulonglong2 w01 = wp[0];
                ulonglong2 w23 = wp[1];
                ffma2(acc[0], w01.x, f);
                ffma2(acc[1], w01.y, f);
                ffma2(acc[2], w23.x, f);
                ffma2(acc[3], w23.y, f);
            }
        }
    }

    #pragma unroll
    for (int j = 0; j < 4; ++j) {
        float lo, hi;
        unpack2(acc[j], lo, hi);
        zpart[(csub * 32 + (2 * j)     * 4 + pq) * 65 + t] = lo;
        zpart[(csub * 32 + (2 * j + 1) * 4 + pq) * 65 + t] = hi;
    }
    __syncthreads();

    if (tid < 32) {   // CUBA: neuron = (o_local, pos)
        int o = tid >> 2, p = tid & 3;
        float cc = 0.0f, vv = 0.0f;
        u64 m = 0;
        #pragma unroll 1
        for (int tt = 0; tt < 64; ++tt) {
            float z = ((zpart[tid * 65 + tt] + zpart[(32 + tid) * 65 + tt])
                     + zpart[(64 + tid) * 65 + tt]) + zpart[(96 + tid) * 65 + tt];
            cc = 0.7f * cc + z;
            vv = 0.75f * vv + cc;
            if (vv >= 1.0f) { m |= (1ULL << tt); vv = 0.0f; }
        }
        sp[(size_t)b * 256 + (og * 8 + o) * 4 + p] = m;
    }
}

// ---------------------------------------------------------------------------
// dense1: 256->2056 + CUBA. Grid (16 b, 33 og of 64 o) = 528 blocks x 256
// thr: 32 tq x 8 oq; thread tile 8o (4 pairs) x 2t = 8 FFMA2 per word.
// Block-uniform zero-word skip.
// ---------------------------------------------------------------------------
__global__ void __launch_bounds__(256, 5)
dense1_cuba_kernel(const u64* __restrict__ s3,
                   const float* __restrict__ w4t,
                   u64* __restrict__ s4)
{
    __shared__ u64 words[256];                     // 2 KB
    __shared__ __align__(16) float wsm[64 * 64];   // 16 KB: [i][64 o]
    __shared__ float zsm[64 * 65];                 // 16.6 KB

    const int b = blockIdx.x, og = blockIdx.y;
    const int tid = threadIdx.x;
    const int tq = tid & 31, oq = tid >> 5;        // oq 0..7, 8 o each

    words[tid] = s3[b * 256 + tid];

    u64 acc[4][2];
    #pragma unroll
    for (int j = 0; j < 4; ++j) { acc[j][0] = 0ULL; acc[j][1] = 0ULL; }

    #pragma unroll 1
    for (int q = 0; q < 4; ++q) {
        __syncthreads();
        #pragma unroll
        for (int r = 0; r < 4; ++r) {
            int f4 = r * 256 + tid;           // 0..1023
            int ii = f4 >> 4;                 // 0..63
            int o4 = (f4 & 15) * 4;           // 0..60
            *(float4*)(wsm + ii * 64 + o4) =
                *(const float4*)(w4t + (size_t)(q * 64 + ii) * W4T_STRIDE + og * 64 + o4);
        }
        __syncthreads();

        #pragma unroll 2
        for (int ii = 0; ii < 64; ++ii) {
            u64 wd = words[q * 64 + ii];
            if (wd == 0ULL) continue;          // block-uniform, exact skip
            u64 f0 = bit2f2((unsigned int)wd, tq);
            u64 f1 = bit2f2((unsigned int)(wd >> 32), tq);
            const ulonglong2* wp = (const ulonglong2*)(wsm + ii * 64 + oq * 8);
            ulonglong2 w0 = wp[0], w1 = wp[1];
            u64 wpair[4] = {w0.x, w0.y, w1.x, w1.y};
            #pragma unroll
            for (int j = 0; j < 4; ++j) {
                ffma2(acc[j][0], wpair[j], f0);
                ffma2(acc[j][1], wpair[j], f1);
            }
        }
    }

    #pragma unroll
    for (int j = 0; j < 4; ++j)
        #pragma unroll
        for (int k = 0; k < 2; ++k) {
            float lo, hi;
            unpack2(acc[j][k], lo, hi);
            zsm[(oq * 8 + 2 * j)     * 65 + tq + 32 * k] = lo;
            zsm[(oq * 8 + 2 * j + 1) * 65 + tq + 32 * k] = hi;
        }
    __syncthreads();

    if (tid < 64) {
        int o_g = og * 64 + tid;
        float cc = 0.0f, vv = 0.0f;
        u64 m = 0;
        #pragma unroll 1
        for (int tt = 0; tt < 64; ++tt) {
            float z = zsm[tid * 65 + tt];
            cc = 0.7f * cc + z;
            vv = 0.75f * vv + cc;
            if (vv >= 1.0f) { m |= (1ULL << tt); vv = 0.0f; }
        }
        if (o_g < 2056) s4[b * 2056 + o_g] = m;
    }
}

// ---------------------------------------------------------------------------
// dense2 (2056->11) + final CUBA + float output. Grid (16 b, 11 o).
// ---------------------------------------------------------------------------
__global__ void __launch_bounds__(256)
dense2_out_kernel(const u64* __restrict__ s4, const float* __restrict__ w5,
                  float* __restrict__ out)
{
    __shared__ float part[4][64];
    __shared__ float zrow[64];
    __shared__ u64 spk;

    const int b = blockIdx.x, o = blockIdx.y;
    const int tid = threadIdx.x;
    const int t = tid & 63, q = tid >> 6;

    float s = 0.0f;
    const u64*   wp = s4 + b * 2056;
    const float* vp = w5 + (size_t)o * 2056;
    for (int i = q * 514; i < q * 514 + 514; ++i) {
        float wt = vp[i];
        if ((wp[i] >> t) & 1ULL) s += wt;
    }
    part[q][t] = s;
    __syncthreads();
    if (tid < 64)
        zrow[tid] = part[0][tid] + part[1][tid] + part[2][tid] + part[3][tid];
    __syncthreads();
    if (tid == 0) {
        float cc = 0.0f, vv = 0.0f;
        u64 m = 0;
        #pragma unroll 1
        for (int tt = 0; tt < 64; ++tt) {
            cc = 0.7f * cc + zrow[tt];
            vv = 0.75f * vv + cc;
            if (vv >= 1.0f) { m |= (1ULL << tt); vv = 0.0f; }
        }
        spk = m;
    }
    __syncthreads();
    if (tid < 64)
        out[((size_t)b * 11 + o) * 64 + tid] = (float)((spk >> tid) & 1ULL);
}

// ---------------------------------------------------------------------------
// launch
// ---------------------------------------------------------------------------
extern "C" void kernel_launch(void* const* d_in, const int* in_sizes, int n_in,
                              void* d_out, int out_size)
{
    const float* x   = (const float*)d_in[0];
    const float* c1v = (const float*)d_in[1];
    const float* c1g = (const float*)d_in[2];
    const float* c2v = (const float*)d_in[3];
    const float* c2g = (const float*)d_in[4];
    const float* c3v = (const float*)d_in[5];
    const float* c3g = (const float*)d_in[6];
    const float* d1v = (const float*)d_in[7];
    const float* d1g = (const float*)d_in[8];
    const float* d2v = (const float*)d_in[9];
    const float* d2g = (const float*)d_in[10];
    float* out = (float*)d_out;

    void* fp = nullptr; void* up = nullptr;
    cudaGetSymbolAddress(&fp, g_fbuf);
    cudaGetSymbolAddress(&up, g_ubuf);
    float* F = (float*)fp;
    u64*   U = (u64*)up;

    float* W1  = F + W1_OFF;
    float* W2  = F + W2_OFF;
    float* W3  = F + W3_OFF;
    float* W4T = F + W4T_OFF;
    float* W5  = F + W5_OFF;
    u64* XP = U + XP_OFF;  u64* S1 = U + S1_OFF;  u64* S2 = U + S2_OFF;
    u64* S3 = U + S3_OFF;  u64* S4 = U + S4_OFF;

    const int SM3 = 16384 + 25600 + 4 * 32 * 65 * 4;   // 75264 bytes
    cudaFuncSetAttribute(conv3_kernel,
                         cudaFuncAttributeMaxDynamicSharedMemorySize, SM3);

    init_kernel<<<4219, 256>>>(x, XP, c1v, c1g, c2v, c2g, c3v, c3g,
                               d1v, d1g, d2v, d2g);

    conv1_kernel<<<dim3(16, 32, 2), 256>>>(XP, W1, S1);
    conv2_kernel<<<dim3(16, 8, 8), 128>>>(S1, W2, S2);
    conv3_kernel<<<dim3(16, 8), 1024, SM3>>>(S2, W3, S3);

    dense1_cuba_kernel<<<dim3(16, 33), 256>>>(S3, W4T, S4);
    dense2_out_kernel<<<dim3(16, 11), 256>>>(S4, W5, out);
}